// round 4
// baseline (speedup 1.0000x reference)
#include <cuda_runtime.h>

// Problem constants
#define BB   8
#define CC   768
#define DD   512
#define HWW  1024
#define LQQ  2048   // LEVELS*HW
#define NHEAD 8
#define NLVL  2
#define NPT   4

// ---------------- scratch (device globals; no runtime allocation) ----------------
__device__ float g_conv1  [(size_t)BB*2*DD*HWW];   // conv1 outputs, (b,lvl,d,hw)
__device__ float g_src    [(size_t)BB*LQQ*DD];
__device__ float g_query  [(size_t)BB*LQQ*DD];
__device__ float g_vproj  [(size_t)BB*LQQ*DD];
__device__ float g_off    [(size_t)BB*LQQ*128];
__device__ float g_aw     [(size_t)BB*LQQ*64];
__device__ float g_msout  [(size_t)BB*LQQ*DD];
__device__ float g_attno  [(size_t)BB*LQQ*DD];
__device__ float g_lnout  [(size_t)BB*LQQ*DD];
__device__ float g_conv2  [(size_t)BB*CC*HWW];
__device__ float g_stats1 [BB*2*32*2];
__device__ float g_stats2 [BB*32*2];

// ---------------- SGEMM NN:  C[b] = A(MxK) * B[b](KxN) + biasM ----------------
// A row-major shared over batch; B,C batched by stride. 128x128x8 tiles, 8x8/thread.
__global__ __launch_bounds__(256) void sgemm_nn(
    const float* __restrict__ A, const float* __restrict__ Bg,
    float* __restrict__ Cg, const float* __restrict__ biasM,
    int M, int N, int K, long strideB, long strideC)
{
    __shared__ float As[8][128];
    __shared__ float Bs[8][128];
    const float* Bp = Bg + (size_t)blockIdx.z * strideB;
    float* Cp       = Cg + (size_t)blockIdx.z * strideC;
    int m0 = blockIdx.y * 128, n0 = blockIdx.x * 128;
    int tid = threadIdx.x;
    int tx = tid & 15, ty = tid >> 4;
    int lm = tid >> 1, lk = (tid & 1) * 4;
    int bk = tid >> 5, bn = (tid & 31) * 4;
    float acc[8][8] = {};
    for (int k0 = 0; k0 < K; k0 += 8) {
        float4 av = *(const float4*)(A + (size_t)(m0 + lm) * K + k0 + lk);
        As[lk+0][lm] = av.x; As[lk+1][lm] = av.y; As[lk+2][lm] = av.z; As[lk+3][lm] = av.w;
        *(float4*)&Bs[bk][bn] = *(const float4*)(Bp + (size_t)(k0 + bk) * N + n0 + bn);
        __syncthreads();
        #pragma unroll
        for (int kk = 0; kk < 8; kk++) {
            float a[8], bb[8];
            *(float4*)(a)    = *(const float4*)&As[kk][ty*8];
            *(float4*)(a+4)  = *(const float4*)&As[kk][ty*8+4];
            *(float4*)(bb)   = *(const float4*)&Bs[kk][tx*8];
            *(float4*)(bb+4) = *(const float4*)&Bs[kk][tx*8+4];
            #pragma unroll
            for (int i = 0; i < 8; i++)
                #pragma unroll
                for (int j = 0; j < 8; j++) acc[i][j] = fmaf(a[i], bb[j], acc[i][j]);
        }
        __syncthreads();
    }
    #pragma unroll
    for (int i = 0; i < 8; i++) {
        int m = m0 + ty*8 + i;
        float bia = biasM[m];
        #pragma unroll
        for (int j = 0; j < 8; j += 4) {
            float4 v;
            v.x = acc[i][j+0] + bia; v.y = acc[i][j+1] + bia;
            v.z = acc[i][j+2] + bia; v.w = acc[i][j+3] + bia;
            *(float4*)(Cp + (size_t)m * N + n0 + tx*8 + j) = v;
        }
    }
}

// ---------------- SGEMM NT:  C = X(MxK) * W(NxK)^T + biasN ----------------
__global__ __launch_bounds__(256) void sgemm_nt(
    const float* __restrict__ X, const float* __restrict__ W,
    float* __restrict__ Cg, const float* __restrict__ biasN,
    int M, int N, int K)
{
    __shared__ float Xs[8][128];
    __shared__ float Ws[8][128];
    int m0 = blockIdx.y * 128, n0 = blockIdx.x * 128;
    int tid = threadIdx.x;
    int tx = tid & 15, ty = tid >> 4;
    int lm = tid >> 1, lk = (tid & 1) * 4;
    float acc[8][8] = {};
    for (int k0 = 0; k0 < K; k0 += 8) {
        float4 xv = *(const float4*)(X + (size_t)(m0 + lm) * K + k0 + lk);
        Xs[lk+0][lm] = xv.x; Xs[lk+1][lm] = xv.y; Xs[lk+2][lm] = xv.z; Xs[lk+3][lm] = xv.w;
        float4 wv4 = make_float4(0.f, 0.f, 0.f, 0.f);
        if (n0 + lm < N)
            wv4 = *(const float4*)(W + (size_t)(n0 + lm) * K + k0 + lk);
        Ws[lk+0][lm] = wv4.x; Ws[lk+1][lm] = wv4.y; Ws[lk+2][lm] = wv4.z; Ws[lk+3][lm] = wv4.w;
        __syncthreads();
        #pragma unroll
        for (int kk = 0; kk < 8; kk++) {
            float a[8], bb[8];
            *(float4*)(a)    = *(const float4*)&Xs[kk][ty*8];
            *(float4*)(a+4)  = *(const float4*)&Xs[kk][ty*8+4];
            *(float4*)(bb)   = *(const float4*)&Ws[kk][tx*8];
            *(float4*)(bb+4) = *(const float4*)&Ws[kk][tx*8+4];
            #pragma unroll
            for (int i = 0; i < 8; i++)
                #pragma unroll
                for (int j = 0; j < 8; j++) acc[i][j] = fmaf(a[i], bb[j], acc[i][j]);
        }
        __syncthreads();
    }
    #pragma unroll
    for (int i = 0; i < 8; i++) {
        int m = m0 + ty*8 + i;
        #pragma unroll
        for (int j = 0; j < 8; j += 4) {
            int n = n0 + tx*8 + j;
            if (n < N) {
                float4 v;
                v.x = acc[i][j+0] + biasN[n+0]; v.y = acc[i][j+1] + biasN[n+1];
                v.z = acc[i][j+2] + biasN[n+2]; v.w = acc[i][j+3] + biasN[n+3];
                *(float4*)(Cg + (size_t)m * N + n) = v;
            }
        }
    }
}

// ---------------- final conv GEMM: C[b,o,hw] = sum_k wc[o,k] * lnout-mapped ----------------
// lnout is (B, 2048, 512); logical B[k,hw] = lnout[b, (k>=512)*1024+hw, k&511]
__global__ __launch_bounds__(256) void sgemm_conv2(
    const float* __restrict__ A, const float* __restrict__ lnout,
    float* __restrict__ Cg, const float* __restrict__ biasM)
{
    const int M = 768, N = 1024, K = 1024;
    __shared__ float As[8][128];
    __shared__ float Bs[8][128];
    int b = blockIdx.z;
    float* Cp = Cg + (size_t)b * M * N;
    int m0 = blockIdx.y * 128, n0 = blockIdx.x * 128;
    int tid = threadIdx.x;
    int tx = tid & 15, ty = tid >> 4;
    int lm = tid >> 1, lk = (tid & 1) * 4;
    float acc[8][8] = {};
    for (int k0 = 0; k0 < K; k0 += 8) {
        float4 av = *(const float4*)(A + (size_t)(m0 + lm) * K + k0 + lk);
        As[lk+0][lm] = av.x; As[lk+1][lm] = av.y; As[lk+2][lm] = av.z; As[lk+3][lm] = av.w;
        int lvl = k0 >> 9;
        const float* bp = lnout + ((size_t)(b*2 + lvl) * 1024 + n0 + lm) * 512 + (k0 & 511) + lk;
        float4 bv = *(const float4*)bp;
        Bs[lk+0][lm] = bv.x; Bs[lk+1][lm] = bv.y; Bs[lk+2][lm] = bv.z; Bs[lk+3][lm] = bv.w;
        __syncthreads();
        #pragma unroll
        for (int kk = 0; kk < 8; kk++) {
            float a[8], bb[8];
            *(float4*)(a)    = *(const float4*)&As[kk][ty*8];
            *(float4*)(a+4)  = *(const float4*)&As[kk][ty*8+4];
            *(float4*)(bb)   = *(const float4*)&Bs[kk][tx*8];
            *(float4*)(bb+4) = *(const float4*)&Bs[kk][tx*8+4];
            #pragma unroll
            for (int i = 0; i < 8; i++)
                #pragma unroll
                for (int j = 0; j < 8; j++) acc[i][j] = fmaf(a[i], bb[j], acc[i][j]);
        }
        __syncthreads();
    }
    #pragma unroll
    for (int i = 0; i < 8; i++) {
        int m = m0 + ty*8 + i;
        float bia = biasM[m];
        #pragma unroll
        for (int j = 0; j < 8; j += 4) {
            float4 v;
            v.x = acc[i][j+0] + bia; v.y = acc[i][j+1] + bia;
            v.z = acc[i][j+2] + bia; v.w = acc[i][j+3] + bia;
            *(float4*)(Cp + (size_t)m * N + n0 + tx*8 + j) = v;
        }
    }
}

// ---------------- GroupNorm stats: contiguous groups ----------------
__global__ void gn_stats(const float* __restrict__ x, float* __restrict__ stats, int groupElems)
{
    int idx = blockIdx.y * gridDim.x + blockIdx.x;
    const float* p = x + (size_t)idx * groupElems;
    float s = 0.f, sq = 0.f;
    for (int i = threadIdx.x; i < groupElems; i += blockDim.x) {
        float v = p[i]; s += v; sq += v * v;
    }
    __shared__ float red[16];
    int t = threadIdx.x;
    for (int o = 16; o > 0; o >>= 1) {
        s  += __shfl_down_sync(0xffffffffu, s,  o);
        sq += __shfl_down_sync(0xffffffffu, sq, o);
    }
    if ((t & 31) == 0) { red[t >> 5] = s; red[8 + (t >> 5)] = sq; }
    __syncthreads();
    if (t < 32) {
        s  = (t < 8) ? red[t]     : 0.f;
        sq = (t < 8) ? red[8 + t] : 0.f;
        for (int o = 4; o > 0; o >>= 1) {
            s  += __shfl_down_sync(0xffffffffu, s,  o);
            sq += __shfl_down_sync(0xffffffffu, sq, o);
        }
        if (t == 0) {
            float inv = 1.f / (float)groupElems;
            float mean = s * inv;
            float var  = sq * inv - mean * mean;
            stats[idx*2]   = mean;
            stats[idx*2+1] = rsqrtf(var + 1e-5f);
        }
    }
}

// ---------------- GN1 normalize + transpose -> src, query ----------------
// grid (32 hw-tiles, 16 d-tiles, B*2), block (32,8)
__global__ void gn1_finish(const float* __restrict__ conv, const float* __restrict__ stats,
    const float* __restrict__ gv, const float* __restrict__ bev,
    const float* __restrict__ gi, const float* __restrict__ bei,
    const float* __restrict__ le,
    float* __restrict__ src, float* __restrict__ query)
{
    __shared__ float tile[32][33];
    int be = blockIdx.z;
    int b = be >> 1, lvl = be & 1;
    int d0 = blockIdx.y * 32, hw0 = blockIdx.x * 32;
    const float* gam = lvl ? gi : gv;
    const float* bet = lvl ? bei : bev;
    const float* ip = conv + (size_t)be * DD * HWW;
    #pragma unroll
    for (int j = 0; j < 4; j++) {
        int d = d0 + threadIdx.y + j * 8;
        float mean = stats[(be*32 + (d >> 4)) * 2];
        float rstd = stats[(be*32 + (d >> 4)) * 2 + 1];
        float v = ip[(size_t)d * HWW + hw0 + threadIdx.x];
        tile[threadIdx.y + j*8][threadIdx.x] = (v - mean) * rstd * gam[d] + bet[d];
    }
    __syncthreads();
    #pragma unroll
    for (int j = 0; j < 4; j++) {
        int hw = hw0 + threadIdx.y + j * 8;
        int d  = d0 + threadIdx.x;
        float v = tile[threadIdx.x][threadIdx.y + j*8];
        size_t o = ((size_t)b * LQQ + (size_t)lvl * HWW + hw) * DD + d;
        src[o]   = v;
        query[o] = v + le[lvl * DD + d];
    }
}

// ---------------- softmax over last-8 per (b,q,head) ----------------
__global__ void softmax8(float* __restrict__ aw, int total)
{
    int i = blockIdx.x * blockDim.x + threadIdx.x;
    if (i >= total) return;
    float* p = aw + (size_t)i * 8;
    float4 p0 = *(float4*)(p);
    float4 p1 = *(float4*)(p + 4);
    float m = fmaxf(fmaxf(fmaxf(p0.x, p0.y), fmaxf(p0.z, p0.w)),
                    fmaxf(fmaxf(p1.x, p1.y), fmaxf(p1.z, p1.w)));
    float e0 = expf(p0.x - m), e1 = expf(p0.y - m), e2 = expf(p0.z - m), e3 = expf(p0.w - m);
    float e4 = expf(p1.x - m), e5 = expf(p1.y - m), e6 = expf(p1.z - m), e7 = expf(p1.w - m);
    float inv = 1.f / (e0 + e1 + e2 + e3 + e4 + e5 + e6 + e7);
    p0.x = e0*inv; p0.y = e1*inv; p0.z = e2*inv; p0.w = e3*inv;
    p1.x = e4*inv; p1.y = e5*inv; p1.z = e6*inv; p1.w = e7*inv;
    *(float4*)(p)     = p0;
    *(float4*)(p + 4) = p1;
}

// ---------------- deformable sampling: one block per (b,q), 512 threads ----------------
__global__ __launch_bounds__(512) void msda_sample(
    const float* __restrict__ vproj, const float* __restrict__ off,
    const float* __restrict__ aw, float* __restrict__ msout)
{
    int bq = blockIdx.x;
    int b = bq >> 11;
    int q = bq & 2047;
    int hw = q & 1023;
    float refx = ((hw & 31) + 0.5f) * (1.f / 32.f);
    float refy = ((hw >> 5) + 0.5f) * (1.f / 32.f);
    __shared__ float sx[64], sy[64], sw[64];
    int t = threadIdx.x;
    if (t < 64) {
        // t = head*8 + (l*4+p); off flat layout is exactly t*2 (+c)
        const float* op = off + ((size_t)bq * 64 + t) * 2;
        float lx = refx + op[0] * (1.f / 32.f);
        float ly = refy + op[1] * (1.f / 32.f);
        sx[t] = lx * 32.f - 0.5f;
        sy[t] = ly * 32.f - 0.5f;
        sw[t] = aw[(size_t)bq * 64 + t];
    }
    __syncthreads();
    int head = t >> 6, dh = t & 63;
    const float* vb = vproj + (size_t)b * LQQ * DD + head * 64 + dh;
    float acc = 0.f;
    #pragma unroll
    for (int lp = 0; lp < 8; lp++) {
        int l = lp >> 2;
        float xs = sx[head*8 + lp], ys = sy[head*8 + lp], w = sw[head*8 + lp];
        float x0f = floorf(xs), y0f = floorf(ys);
        float fx = xs - x0f, fy = ys - y0f;
        int x0 = (int)x0f, y0 = (int)y0f;
        int x1 = x0 + 1, y1 = y0 + 1;
        const float* vl = vb + (size_t)l * HWW * DD;
        bool xa = (unsigned)x0 < 32u, xb = (unsigned)x1 < 32u;
        bool ya = (unsigned)y0 < 32u, yb = (unsigned)y1 < 32u;
        float v00 = (ya && xa) ? vl[(size_t)(y0*32 + x0) * DD] : 0.f;
        float v01 = (ya && xb) ? vl[(size_t)(y0*32 + x1) * DD] : 0.f;
        float v10 = (yb && xa) ? vl[(size_t)(y1*32 + x0) * DD] : 0.f;
        float v11 = (yb && xb) ? vl[(size_t)(y1*32 + x1) * DD] : 0.f;
        float s = v00 * (1.f-fy) * (1.f-fx) + v01 * (1.f-fy) * fx
                + v10 * fy * (1.f-fx)       + v11 * fy * fx;
        acc = fmaf(w, s, acc);
    }
    msout[(size_t)bq * DD + t] = acc;
}

// ---------------- residual + LayerNorm (one block per row) ----------------
__global__ void ln_res(const float* __restrict__ src, const float* __restrict__ att,
                       const float* __restrict__ g, const float* __restrict__ be,
                       float* __restrict__ out)
{
    int row = blockIdx.x;
    size_t base = (size_t)row * DD;
    int t = threadIdx.x; // 256
    float v0 = src[base + t]       + att[base + t];
    float v1 = src[base + t + 256] + att[base + t + 256];
    float s = v0 + v1, sq = v0*v0 + v1*v1;
    __shared__ float red[16];
    for (int o = 16; o > 0; o >>= 1) {
        s  += __shfl_down_sync(0xffffffffu, s,  o);
        sq += __shfl_down_sync(0xffffffffu, sq, o);
    }
    if ((t & 31) == 0) { red[t >> 5] = s; red[8 + (t >> 5)] = sq; }
    __syncthreads();
    if (t < 32) {
        s  = (t < 8) ? red[t]     : 0.f;
        sq = (t < 8) ? red[8 + t] : 0.f;
        for (int o = 4; o > 0; o >>= 1) {
            s  += __shfl_down_sync(0xffffffffu, s,  o);
            sq += __shfl_down_sync(0xffffffffu, sq, o);
        }
        if (t == 0) { red[0] = s; red[8] = sq; }
    }
    __syncthreads();
    float mu   = red[0] * (1.f / 512.f);
    float var  = red[8] * (1.f / 512.f) - mu * mu;
    float rstd = rsqrtf(var + 1e-5f);
    out[base + t]       = (v0 - mu) * rstd * g[t]       + be[t];
    out[base + t + 256] = (v1 - mu) * rstd * g[t + 256] + be[t + 256];
}

// ---------------- final GN normalize -> output ----------------
__global__ void gn2_finish(const float* __restrict__ x, const float* __restrict__ stats,
    const float* __restrict__ gc, const float* __restrict__ bec, float* __restrict__ out)
{
    size_t i = (size_t)blockIdx.x * blockDim.x + threadIdx.x;
    // total = B*768*1024 = 6291456, grid sized exactly
    int hwch = (int)(i >> 10);
    int ch = hwch % 768;
    int b  = hwch / 768;
    int g  = ch / 24;
    float mean = stats[(b*32 + g) * 2];
    float rstd = stats[(b*32 + g) * 2 + 1];
    out[i] = (x[i] - mean) * rstd * gc[ch] + bec[ch];
}

// ---------------- launcher ----------------
extern "C" void kernel_launch(void* const* d_in, const int* in_sizes, int n_in,
                              void* d_out, int out_size)
{
    const float* input_v = (const float*)d_in[0];
    const float* input_i = (const float*)d_in[1];
    const float* wv      = (const float*)d_in[2];
    const float* bv      = (const float*)d_in[3];
    const float* gv      = (const float*)d_in[4];
    const float* bev     = (const float*)d_in[5];
    const float* wi      = (const float*)d_in[6];
    const float* bi      = (const float*)d_in[7];
    const float* gi      = (const float*)d_in[8];
    const float* bei     = (const float*)d_in[9];
    const float* le      = (const float*)d_in[10];
    const float* w_off   = (const float*)d_in[11];
    const float* b_off   = (const float*)d_in[12];
    const float* w_attn  = (const float*)d_in[13];
    const float* b_attn  = (const float*)d_in[14];
    const float* w_val   = (const float*)d_in[15];
    const float* b_val   = (const float*)d_in[16];
    const float* w_out   = (const float*)d_in[17];
    const float* b_out   = (const float*)d_in[18];
    const float* ln_g    = (const float*)d_in[19];
    const float* ln_b    = (const float*)d_in[20];
    const float* wc      = (const float*)d_in[21];
    const float* bc      = (const float*)d_in[22];
    const float* gc      = (const float*)d_in[23];
    const float* bec     = (const float*)d_in[24];

    float *conv1, *src, *query, *vproj, *offb, *awb, *msout, *attno, *lnout, *conv2, *st1, *st2;
    cudaGetSymbolAddress((void**)&conv1, g_conv1);
    cudaGetSymbolAddress((void**)&src,   g_src);
    cudaGetSymbolAddress((void**)&query, g_query);
    cudaGetSymbolAddress((void**)&vproj, g_vproj);
    cudaGetSymbolAddress((void**)&offb,  g_off);
    cudaGetSymbolAddress((void**)&awb,   g_aw);
    cudaGetSymbolAddress((void**)&msout, g_msout);
    cudaGetSymbolAddress((void**)&attno, g_attno);
    cudaGetSymbolAddress((void**)&lnout, g_lnout);
    cudaGetSymbolAddress((void**)&conv2, g_conv2);
    cudaGetSymbolAddress((void**)&st1,   g_stats1);
    cudaGetSymbolAddress((void**)&st2,   g_stats2);

    // 1) conv1x1 for v and i  (M=512, N=1024, K=768, batched over B)
    sgemm_nn<<<dim3(8, 4, BB), 256>>>(wv, input_v, conv1,            bv, DD, HWW, CC,
                                      (long)CC*HWW, (long)2*DD*HWW);
    sgemm_nn<<<dim3(8, 4, BB), 256>>>(wi, input_i, conv1 + (size_t)DD*HWW, bi, DD, HWW, CC,
                                      (long)CC*HWW, (long)2*DD*HWW);
    // 2) GN stats + normalize/transpose -> src, query
    gn_stats<<<dim3(32, BB*2), 256>>>(conv1, st1, 16 * HWW);
    gn1_finish<<<dim3(32, 16, BB*2), dim3(32, 8)>>>(conv1, st1, gv, bev, gi, bei, le, src, query);
    // 3) projections
    sgemm_nt<<<dim3(4, 128), 256>>>(src,   w_val,  vproj, b_val,  BB*LQQ, DD,  DD);
    sgemm_nt<<<dim3(1, 128), 256>>>(query, w_off,  offb,  b_off,  BB*LQQ, 128, DD);
    sgemm_nt<<<dim3(1, 128), 256>>>(query, w_attn, awb,   b_attn, BB*LQQ, 64,  DD);
    // 4) softmax over (LEVELS*POINTS)
    softmax8<<<512, 256>>>(awb, BB*LQQ*NHEAD);
    // 5) deformable sampling + weighted sum
    msda_sample<<<BB*LQQ, 512>>>(vproj, offb, awb, msout);
    // 6) output projection
    sgemm_nt<<<dim3(4, 128), 256>>>(msout, w_out, attno, b_out, BB*LQQ, DD, DD);
    // 7) residual + LayerNorm
    ln_res<<<BB*LQQ, 256>>>(src, attno, ln_g, ln_b, lnout);
    // 8) final conv1x1 (M=768, N=1024, K=1024, batched)
    sgemm_conv2<<<dim3(8, 6, BB), 256>>>(wc, lnout, conv2, bc);
    // 9) final GN
    gn_stats<<<dim3(32, BB), 256>>>(conv2, st2, 24 * HWW);
    gn2_finish<<<24576, 256>>>(conv2, st2, gc, bec, (float*)d_out);
}

// round 6
// speedup vs baseline: 2.1287x; 2.1287x over previous
#include <cuda_runtime.h>
#include <cuda_bf16.h>
#include <cstdint>

#define BB   8
#define CC   768
#define DD   512
#define HWW  1024
#define LQQ  2048
#define MROWS (BB*LQQ)   // 16384

// ---------------- scratch (device globals) ----------------
__device__ uint4 g_xth [2][8192*768/8], g_xtl [2][8192*768/8];
__device__ uint4 g_wvh_[512*768/8],  g_wvl_[512*768/8];
__device__ uint4 g_wih_[512*768/8],  g_wil_[512*768/8];
__device__ uint4 g_wvalh[512*512/8], g_wvall[512*512/8];
__device__ uint4 g_wouth[512*512/8], g_woutl[512*512/8];
__device__ uint4 g_woah[256*512/8],  g_woal[256*512/8];
__device__ uint4 g_wch_[768*1024/8], g_wcl_[768*1024/8];
__device__ uint4 g_srch[MROWS*512/8], g_srcl[MROWS*512/8];
__device__ uint4 g_qh_[MROWS*512/8],  g_ql_[MROWS*512/8];
__device__ uint4 g_msh[MROWS*512/8],  g_msl[MROWS*512/8];
__device__ uint4 g_cath[8192*1024/8], g_catl[8192*1024/8];
__device__ float4 g_pre4  [MROWS*512/4];
__device__ float4 g_src4  [MROWS*512/4];
__device__ float4 g_vproj4[MROWS*512/4];
__device__ float4 g_oa4   [MROWS*256/4];
__device__ float4 g_attno4[MROWS*512/4];
__device__ float4 g_conv24[BB*CC*HWW/4];
__device__ float4 g_boa4  [64];
__device__ float  g_stats1[BB*2*32*2];
__device__ float  g_stats2[BB*32*2];

// ---------------- PTX helpers (sm_80-compatible ISA only) ----------------
__device__ __forceinline__ uint32_t smem_u32(const void* p) {
    uint32_t a;
    asm("{ .reg .u64 t; cvta.to.shared.u64 t, %1; cvt.u32.u64 %0, t; }" : "=r"(a) : "l"(p));
    return a;
}
#define CP16(s, g) \
    asm volatile("cp.async.cg.shared.global [%0], [%1], 16;" :: "r"(s), "l"(g))
#define CP_COMMIT() asm volatile("cp.async.commit_group;" ::: "memory")
#define LDSM4(r, a) \
    asm volatile("ldmatrix.sync.aligned.m8n8.x4.shared.b16 {%0,%1,%2,%3}, [%4];" \
        : "=r"((r)[0]), "=r"((r)[1]), "=r"((r)[2]), "=r"((r)[3]) : "r"(a))
#define MMA16(c, a, b0, b1) \
    asm volatile("mma.sync.aligned.m16n8k16.row.col.f32.bf16.bf16.f32 " \
        "{%0,%1,%2,%3}, {%4,%5,%6,%7}, {%8,%9}, {%0,%1,%2,%3};" \
        : "+f"((c)[0]), "+f"((c)[1]), "+f"((c)[2]), "+f"((c)[3]) \
        : "r"((a)[0]), "r"((a)[1]), "r"((a)[2]), "r"((a)[3]), "r"(b0), "r"(b1))

__device__ __forceinline__ void split2(float v, __nv_bfloat16& h, __nv_bfloat16& l) {
    h = __float2bfloat16(v);
    l = __float2bfloat16(v - __bfloat162float(h));
}

// ============================================================================
// Split-bf16 HMMA GEMM: D[m,n] = sum_k A[m,k]*B[n,k], 128x128 tiles, K chunk 32,
// cp.async double buffer, ldmatrix fragments, 3-product split accumulation.
// mode 0: C[((m>>10)*mMul + mOff + (m&1023))*ldC + n] + bias[n]
// mode 1: C[((n>>10)*ldC + m)*1024 + (n&1023)]        + bias[m]
// smem stage: Ah[128x32] Al Bh Bl @ 8KB each = 32KB; 2 stages = 64KB.
// ============================================================================
#define GEMM_SMEM 65536
__global__ __launch_bounds__(256) void gemm_tc(
    const __nv_bfloat16* __restrict__ Ah, const __nv_bfloat16* __restrict__ Al,
    const __nv_bfloat16* __restrict__ Bh, const __nv_bfloat16* __restrict__ Bl,
    const float* __restrict__ bias, float* __restrict__ C,
    int K, int mode, int mMul, int mOff, int ldC)
{
    extern __shared__ __align__(16) char smem[];
    const uint32_t sb = smem_u32(smem);
    const int tid = threadIdx.x;
    const int m0 = blockIdx.y * 128, n0 = blockIdx.x * 128;
    const int warp = tid >> 5, lane = tid & 31;
    const int wm = warp >> 1, wn = warp & 1;

    // per-thread cp.async geometry: kg = 16B chunk within 64B row, rows r0 and r0+64
    const int kg = tid & 3, r0 = tid >> 2;

    // A-fragment ldmatrix lane geometry
    const int arow_l = lane & 15, akg_l = lane >> 4;
    // B-fragment ldmatrix lane geometry
    const int nr = (lane & 7) + ((lane & 16) >> 1);
    const int bkg_l = (lane >> 3) & 1;

    float acc[2][8][4];
    #pragma unroll
    for (int i = 0; i < 2; ++i)
        #pragma unroll
        for (int j = 0; j < 8; ++j)
            #pragma unroll
            for (int k = 0; k < 4; ++k) acc[i][j][k] = 0.f;

    const int nC = K >> 5;

    // ---- stage loader ----
    auto load_stage = [&](int c) {
        const uint32_t stb = sb + (uint32_t)(c & 1) * 32768u;
        const int k0 = c << 5;
        #pragma unroll
        for (int h = 0; h < 2; ++h) {
            int row = r0 + h * 64;
            uint32_t so = (uint32_t)(row * 64 + ((kg ^ (row & 3)) << 4));
            size_t ga = (size_t)(m0 + row) * K + k0 + kg * 8;
            size_t gb = (size_t)(n0 + row) * K + k0 + kg * 8;
            CP16(stb +         so, Ah + ga);
            CP16(stb +  8192 + so, Al + ga);
            CP16(stb + 16384 + so, Bh + gb);
            CP16(stb + 24576 + so, Bl + gb);
        }
        CP_COMMIT();
    };

    load_stage(0);
    for (int c = 0; c < nC; ++c) {
        if (c + 1 < nC) {
            load_stage(c + 1);
            asm volatile("cp.async.wait_group 1;" ::: "memory");
        } else {
            asm volatile("cp.async.wait_group 0;" ::: "memory");
        }
        __syncthreads();
        const uint32_t stb = sb + (uint32_t)(c & 1) * 32768u;
        #pragma unroll
        for (int kk = 0; kk < 2; ++kk) {
            uint32_t ah[2][4], al[2][4];
            #pragma unroll
            for (int mf = 0; mf < 2; ++mf) {
                int arow = wm * 32 + mf * 16 + arow_l;
                uint32_t ad = stb + (uint32_t)(arow * 64 +
                              ((((kk << 1) + akg_l) ^ (arow_l & 3)) << 4));
                LDSM4(ah[mf], ad);
                LDSM4(al[mf], ad + 8192);
            }
            #pragma unroll
            for (int np = 0; np < 4; ++np) {
                int brow = wn * 64 + np * 16 + nr;
                uint32_t bd = stb + 16384u + (uint32_t)(brow * 64 +
                              ((((kk << 1) + bkg_l) ^ (nr & 3)) << 4));
                uint32_t bh[4], bl[4];
                LDSM4(bh, bd);
                LDSM4(bl, bd + 8192);
                #pragma unroll
                for (int half = 0; half < 2; ++half) {
                    uint32_t bh0 = bh[half*2], bh1 = bh[half*2+1];
                    uint32_t bl0 = bl[half*2], bl1 = bl[half*2+1];
                    int nj = np * 2 + half;
                    #pragma unroll
                    for (int mf = 0; mf < 2; ++mf) {
                        MMA16(acc[mf][nj], ah[mf], bh0, bh1);
                        MMA16(acc[mf][nj], ah[mf], bl0, bl1);
                        MMA16(acc[mf][nj], al[mf], bh0, bh1);
                    }
                }
            }
        }
        __syncthreads();
    }

    // ---- epilogue: direct float2 stores ----
    const int tq = lane >> 2, tr2 = (lane & 3) * 2;
    #pragma unroll
    for (int mf = 0; mf < 2; ++mf) {
        #pragma unroll
        for (int nj = 0; nj < 8; ++nj) {
            int mrow = m0 + wm * 32 + mf * 16 + tq;
            int col  = n0 + wn * 64 + nj * 8 + tr2;
            float* a0 = acc[mf][nj];
            if (mode == 0) {
                float b0 = bias[col], b1 = bias[col + 1];
                int rp0 = (mrow >> 10) * mMul + mOff + (mrow & 1023);
                int m2 = mrow + 8;
                int rp1 = (m2 >> 10) * mMul + mOff + (m2 & 1023);
                *(float2*)(C + (size_t)rp0 * ldC + col) = make_float2(a0[0] + b0, a0[1] + b1);
                *(float2*)(C + (size_t)rp1 * ldC + col) = make_float2(a0[2] + b0, a0[3] + b1);
            } else {
                float bm0 = bias[mrow], bm1 = bias[mrow + 8];
                size_t base = ((size_t)((col >> 10) * ldC)) * 1024 + (col & 1023);
                *(float2*)(C + base + (size_t)mrow       * 1024) = make_float2(a0[0] + bm0, a0[1] + bm0);
                *(float2*)(C + base + (size_t)(mrow + 8) * 1024) = make_float2(a0[2] + bm1, a0[3] + bm1);
            }
        }
    }
}

// ---------------- prep: transpose (b,c,hw)->(b*hw,c) + bf16 split ----------------
__global__ void prep_input(const float* __restrict__ in,
                           __nv_bfloat16* __restrict__ xh, __nv_bfloat16* __restrict__ xl)
{
    __shared__ float tl[32][33];
    int b = blockIdx.z, c0 = blockIdx.y * 32, hw0 = blockIdx.x * 32;
    const float* ip = in + ((size_t)b * CC + c0) * HWW + hw0;
    #pragma unroll
    for (int j = 0; j < 4; ++j)
        tl[threadIdx.y + j*8][threadIdx.x] = ip[(size_t)(threadIdx.y + j*8) * HWW + threadIdx.x];
    __syncthreads();
    #pragma unroll
    for (int j = 0; j < 4; ++j) {
        int hw = hw0 + threadIdx.y + j*8;
        int cc = c0 + threadIdx.x;
        __nv_bfloat16 h, l; split2(tl[threadIdx.x][threadIdx.y + j*8], h, l);
        size_t o = ((size_t)b * HWW + hw) * CC + cc;
        xh[o] = h; xl[o] = l;
    }
}

__global__ void split_w(const float* __restrict__ x,
                        __nv_bfloat16* __restrict__ h, __nv_bfloat16* __restrict__ l, int n)
{
    int i = blockIdx.x * 256 + threadIdx.x;
    if (i < n) { __nv_bfloat16 a, b; split2(x[i], a, b); h[i] = a; l[i] = b; }
}

__global__ void build_woa(const float* __restrict__ w_off, const float* __restrict__ w_attn,
                          const float* __restrict__ b_off, const float* __restrict__ b_attn,
                          __nv_bfloat16* __restrict__ h, __nv_bfloat16* __restrict__ l,
                          float* __restrict__ boa)
{
    int i = blockIdx.x * 256 + threadIdx.x;   // 131072
    int r = i >> 9, c = i & 511;
    float v = (r < 128) ? w_off[r * 512 + c] : ((r < 192) ? w_attn[(r - 128) * 512 + c] : 0.f);
    __nv_bfloat16 a, b; split2(v, a, b);
    h[i] = a; l[i] = b;
    if (i < 256) boa[i] = (i < 128) ? b_off[i] : ((i < 192) ? b_attn[i - 128] : 0.f);
}

// ---------------- GN stats over seq-major (rows=(be,hw), 512 ch); group=16 ch ----------------
__global__ void gn_stats_seq(const float* __restrict__ x, float* __restrict__ stats)
{
    int be = blockIdx.y, g = blockIdx.x;
    int t = threadIdx.x;
    const float* base = x + (size_t)be * 1024 * 512 + g * 16 + (t & 3) * 4;
    float s = 0.f, sq = 0.f;
    #pragma unroll
    for (int it = 0; it < 16; ++it) {
        float4 v = *(const float4*)(base + (size_t)((t >> 2) + it * 64) * 512);
        s  += v.x + v.y + v.z + v.w;
        sq += v.x*v.x + v.y*v.y + v.z*v.z + v.w*v.w;
    }
    __shared__ float red[16];
    for (int o = 16; o > 0; o >>= 1) {
        s  += __shfl_down_sync(0xffffffffu, s,  o);
        sq += __shfl_down_sync(0xffffffffu, sq, o);
    }
    if ((t & 31) == 0) { red[t >> 5] = s; red[8 + (t >> 5)] = sq; }
    __syncthreads();
    if (t < 32) {
        s  = (t < 8) ? red[t]     : 0.f;
        sq = (t < 8) ? red[8 + t] : 0.f;
        for (int o = 4; o > 0; o >>= 1) {
            s  += __shfl_down_sync(0xffffffffu, s,  o);
            sq += __shfl_down_sync(0xffffffffu, sq, o);
        }
        if (t == 0) {
            float mean = s * (1.f/16384.f);
            float var  = sq * (1.f/16384.f) - mean * mean;
            stats[(be*32+g)*2]   = mean;
            stats[(be*32+g)*2+1] = rsqrtf(var + 1e-5f);
        }
    }
}

// ---------------- GN1 finish: src fp32 + src/query bf16 hi/lo ----------------
__global__ void gn1_finish2(const float* __restrict__ pre, const float* __restrict__ stats,
    const float* __restrict__ gv, const float* __restrict__ bev,
    const float* __restrict__ gi, const float* __restrict__ bei,
    const float* __restrict__ le, float* __restrict__ src,
    __nv_bfloat16* __restrict__ sh, __nv_bfloat16* __restrict__ sl,
    __nv_bfloat16* __restrict__ qh, __nv_bfloat16* __restrict__ ql)
{
    size_t e = ((size_t)blockIdx.x * 256 + threadIdx.x) * 4;
    int row = (int)(e >> 9), d = (int)(e & 511);
    int be = row >> 10, lvl = be & 1;
    float mean = stats[(be * 32 + (d >> 4)) * 2];
    float rstd = stats[(be * 32 + (d >> 4)) * 2 + 1];
    const float* gam = lvl ? gi : gv;
    const float* bet = lvl ? bei : bev;
    float4 v = *(const float4*)(pre + e);
    float vv[4] = {v.x, v.y, v.z, v.w};
    float so[4];
    #pragma unroll
    for (int k = 0; k < 4; ++k) {
        float sv = (vv[k] - mean) * rstd * gam[d + k] + bet[d + k];
        so[k] = sv;
        __nv_bfloat16 h, l;
        split2(sv, h, l); sh[e + k] = h; sl[e + k] = l;
        split2(sv + le[lvl * 512 + d + k], h, l); qh[e + k] = h; ql[e + k] = l;
    }
    *(float4*)(src + e) = *(float4*)so;
}

// ---------------- softmax over 8 attn logits, in-place in oa cols 128..191 ----------------
__global__ void softmax8(float* __restrict__ oa)
{
    int i = blockIdx.x * blockDim.x + threadIdx.x;  // 131072
    float* p = oa + (size_t)(i >> 3) * 256 + 128 + (i & 7) * 8;
    float4 p0 = *(float4*)(p);
    float4 p1 = *(float4*)(p + 4);
    float m = fmaxf(fmaxf(fmaxf(p0.x, p0.y), fmaxf(p0.z, p0.w)),
                    fmaxf(fmaxf(p1.x, p1.y), fmaxf(p1.z, p1.w)));
    float e0 = expf(p0.x-m), e1 = expf(p0.y-m), e2 = expf(p0.z-m), e3 = expf(p0.w-m);
    float e4 = expf(p1.x-m), e5 = expf(p1.y-m), e6 = expf(p1.z-m), e7 = expf(p1.w-m);
    float inv = 1.f / (e0+e1+e2+e3+e4+e5+e6+e7);
    p0.x=e0*inv; p0.y=e1*inv; p0.z=e2*inv; p0.w=e3*inv;
    p1.x=e4*inv; p1.y=e5*inv; p1.z=e6*inv; p1.w=e7*inv;
    *(float4*)(p) = p0; *(float4*)(p + 4) = p1;
}

// ---------------- deformable sampling -> msout bf16 hi/lo ----------------
__global__ __launch_bounds__(512) void msda_sample(
    const float* __restrict__ vproj, const float* __restrict__ oa,
    __nv_bfloat16* __restrict__ msh, __nv_bfloat16* __restrict__ msl)
{
    int bq = blockIdx.x;
    int b = bq >> 11;
    int hw = bq & 1023;
    float refx = ((hw & 31) + 0.5f) * (1.f/32.f);
    float refy = ((hw >> 5) + 0.5f) * (1.f/32.f);
    __shared__ float sx[64], sy[64], sw[64];
    int t = threadIdx.x;
    const float* row = oa + (size_t)bq * 256;
    if (t < 64) {
        sx[t] = (refx + row[t*2]   * (1.f/32.f)) * 32.f - 0.5f;
        sy[t] = (refy + row[t*2+1] * (1.f/32.f)) * 32.f - 0.5f;
        sw[t] = row[128 + t];
    }
    __syncthreads();
    int head = t >> 6, dh = t & 63;
    const float* vb = vproj + (size_t)b * LQQ * DD + head * 64 + dh;
    float acc = 0.f;
    #pragma unroll
    for (int lp = 0; lp < 8; lp++) {
        int l = lp >> 2;
        float xs = sx[head*8+lp], ys = sy[head*8+lp], w = sw[head*8+lp];
        float x0f = floorf(xs), y0f = floorf(ys);
        float fx = xs - x0f, fy = ys - y0f;
        int x0 = (int)x0f, y0 = (int)y0f;
        const float* vl = vb + (size_t)l * HWW * DD;
        bool xa = (unsigned)x0 < 32u, xb = (unsigned)(x0+1) < 32u;
        bool ya = (unsigned)y0 < 32u, yb = (unsigned)(y0+1) < 32u;
        float v00 = (ya && xa) ? vl[(size_t)(y0*32 + x0)     * DD] : 0.f;
        float v01 = (ya && xb) ? vl[(size_t)(y0*32 + x0 + 1) * DD] : 0.f;
        float v10 = (yb && xa) ? vl[(size_t)(y0*32 + x0 + 32)* DD] : 0.f;
        float v11 = (yb && xb) ? vl[(size_t)(y0*32 + x0 + 33)* DD] : 0.f;
        float s = v00*(1.f-fy)*(1.f-fx) + v01*(1.f-fy)*fx + v10*fy*(1.f-fx) + v11*fy*fx;
        acc = fmaf(w, s, acc);
    }
    __nv_bfloat16 h, l; split2(acc, h, l);
    msh[(size_t)bq * DD + t] = h;
    msl[(size_t)bq * DD + t] = l;
}

// ---------------- residual + LayerNorm -> cat bf16 hi/lo (conv2 layout) ----------------
__global__ void ln_res(const float* __restrict__ src, const float* __restrict__ att,
                       const float* __restrict__ g, const float* __restrict__ be,
                       __nv_bfloat16* __restrict__ cath, __nv_bfloat16* __restrict__ catl)
{
    int grow = blockIdx.x;            // b*2048 + lvl*1024 + hw
    size_t base = (size_t)grow * DD;
    int t = threadIdx.x;              // 256
    float v0 = src[base + t]       + att[base + t];
    float v1 = src[base + t + 256] + att[base + t + 256];
    float s = v0 + v1, sq = v0*v0 + v1*v1;
    __shared__ float red[16];
    for (int o = 16; o > 0; o >>= 1) {
        s  += __shfl_down_sync(0xffffffffu, s,  o);
        sq += __shfl_down_sync(0xffffffffu, sq, o);
    }
    if ((t & 31) == 0) { red[t >> 5] = s; red[8 + (t >> 5)] = sq; }
    __syncthreads();
    if (t < 32) {
        s  = (t < 8) ? red[t]     : 0.f;
        sq = (t < 8) ? red[8 + t] : 0.f;
        for (int o = 4; o > 0; o >>= 1) {
            s  += __shfl_down_sync(0xffffffffu, s,  o);
            sq += __shfl_down_sync(0xffffffffu, sq, o);
        }
        if (t == 0) { red[0] = s; red[8] = sq; }
    }
    __syncthreads();
    float mu   = red[0] * (1.f/512.f);
    float var  = red[8] * (1.f/512.f) - mu * mu;
    float rstd = rsqrtf(var + 1e-5f);
    int b = grow >> 11, lvl = (grow >> 10) & 1, hw = grow & 1023;
    size_t obase = ((size_t)b * 1024 + hw) * 1024 + lvl * 512;
    __nv_bfloat16 h, l;
    split2((v0 - mu) * rstd * g[t]       + be[t],       h, l);
    cath[obase + t]       = h; catl[obase + t]       = l;
    split2((v1 - mu) * rstd * g[t + 256] + be[t + 256], h, l);
    cath[obase + t + 256] = h; catl[obase + t + 256] = l;
}

// ---------------- GN stats: contiguous groups (conv2 output) ----------------
__global__ void gn_stats(const float* __restrict__ x, float* __restrict__ stats, int groupElems)
{
    int idx = blockIdx.y * gridDim.x + blockIdx.x;
    const float* p = x + (size_t)idx * groupElems;
    float s = 0.f, sq = 0.f;
    for (int i = threadIdx.x * 4; i < groupElems; i += blockDim.x * 4) {
        float4 v = *(const float4*)(p + i);
        s  += v.x + v.y + v.z + v.w;
        sq += v.x*v.x + v.y*v.y + v.z*v.z + v.w*v.w;
    }
    __shared__ float red[16];
    int t = threadIdx.x;
    for (int o = 16; o > 0; o >>= 1) {
        s  += __shfl_down_sync(0xffffffffu, s,  o);
        sq += __shfl_down_sync(0xffffffffu, sq, o);
    }
    if ((t & 31) == 0) { red[t >> 5] = s; red[8 + (t >> 5)] = sq; }
    __syncthreads();
    if (t < 32) {
        s  = (t < 8) ? red[t]     : 0.f;
        sq = (t < 8) ? red[8 + t] : 0.f;
        for (int o = 4; o > 0; o >>= 1) {
            s  += __shfl_down_sync(0xffffffffu, s,  o);
            sq += __shfl_down_sync(0xffffffffu, sq, o);
        }
        if (t == 0) {
            float inv = 1.f / (float)groupElems;
            float mean = s * inv;
            stats[idx*2]   = mean;
            stats[idx*2+1] = rsqrtf(sq * inv - mean * mean + 1e-5f);
        }
    }
}

__global__ void gn2_finish(const float* __restrict__ x, const float* __restrict__ stats,
    const float* __restrict__ gc, const float* __restrict__ bec, float* __restrict__ out)
{
    size_t i = (size_t)blockIdx.x * blockDim.x + threadIdx.x;
    int hwch = (int)(i >> 10);
    int ch = hwch % 768;
    int b  = hwch / 768;
    int g  = ch / 24;
    float mean = stats[(b*32 + g) * 2];
    float rstd = stats[(b*32 + g) * 2 + 1];
    out[i] = (x[i] - mean) * rstd * gc[ch] + bec[ch];
}

// ---------------- launcher ----------------
#define SYM(T, v, s) T v; cudaGetSymbolAddress((void**)&v, s)
typedef __nv_bfloat16 bf;
extern "C" void kernel_launch(void* const* d_in, const int* in_sizes, int n_in,
                              void* d_out, int out_size)
{
    const float* input_v = (const float*)d_in[0];
    const float* input_i = (const float*)d_in[1];
    const float* wv      = (const float*)d_in[2];
    const float* bv      = (const float*)d_in[3];
    const float* gv      = (const float*)d_in[4];
    const float* bev     = (const float*)d_in[5];
    const float* wi      = (const float*)d_in[6];
    const float* bi      = (const float*)d_in[7];
    const float* gi      = (const float*)d_in[8];
    const float* bei     = (const float*)d_in[9];
    const float* le      = (const float*)d_in[10];
    const float* w_off   = (const float*)d_in[11];
    const float* b_off   = (const float*)d_in[12];
    const float* w_attn  = (const float*)d_in[13];
    const float* b_attn  = (const float*)d_in[14];
    const float* w_val   = (const float*)d_in[15];
    const float* b_val   = (const float*)d_in[16];
    const float* w_out   = (const float*)d_in[17];
    const float* b_out   = (const float*)d_in[18];
    const float* ln_g    = (const float*)d_in[19];
    const float* ln_b    = (const float*)d_in[20];
    const float* wc      = (const float*)d_in[21];
    const float* bc      = (const float*)d_in[22];
    const float* gc      = (const float*)d_in[23];
    const float* bec     = (const float*)d_in[24];

    SYM(bf*, xth,  g_xth);  SYM(bf*, xtl,  g_xtl);
    SYM(bf*, wvh,  g_wvh_); SYM(bf*, wvl,  g_wvl_);
    SYM(bf*, wih,  g_wih_); SYM(bf*, wil,  g_wil_);
    SYM(bf*, wvalh,g_wvalh);SYM(bf*, wvall,g_wvall);
    SYM(bf*, wouth,g_wouth);SYM(bf*, woutl,g_woutl);
    SYM(bf*, woah, g_woah); SYM(bf*, woal, g_woal);
    SYM(bf*, wch,  g_wch_); SYM(bf*, wcl,  g_wcl_);
    SYM(bf*, srch, g_srch); SYM(bf*, srcl, g_srcl);
    SYM(bf*, qh,   g_qh_);  SYM(bf*, ql,   g_ql_);
    SYM(bf*, msh,  g_msh);  SYM(bf*, msl,  g_msl);
    SYM(bf*, cath, g_cath); SYM(bf*, catl, g_catl);
    SYM(float*, pre,   g_pre4);   SYM(float*, src,   g_src4);
    SYM(float*, vproj, g_vproj4); SYM(float*, oa,    g_oa4);
    SYM(float*, attno, g_attno4); SYM(float*, conv2, g_conv24);
    SYM(float*, boa,   g_boa4);
    SYM(float*, st1,   g_stats1); SYM(float*, st2,   g_stats2);
    size_t XT = (size_t)8192*768;

    cudaFuncSetAttribute(gemm_tc, cudaFuncAttributeMaxDynamicSharedMemorySize, GEMM_SMEM);

    // weight + input prep
    split_w<<<1536, 256>>>(wv, wvh, wvl, 512*768);
    split_w<<<1536, 256>>>(wi, wih, wil, 512*768);
    split_w<<<1024, 256>>>(w_val, wvalh, wvall, 512*512);
    split_w<<<1024, 256>>>(w_out, wouth, woutl, 512*512);
    split_w<<<3072, 256>>>(wc, wch, wcl, 768*1024);
    build_woa<<<512, 256>>>(w_off, w_attn, b_off, b_attn, woah, woal, boa);
    prep_input<<<dim3(32, 24, BB), dim3(32, 8)>>>(input_v, xth, xtl);
    prep_input<<<dim3(32, 24, BB), dim3(32, 8)>>>(input_i, xth + XT, xtl + XT);

    // conv1 (v, i): D[8192,512], rows -> (b, lvl, hw)
    gemm_tc<<<dim3(4, 64), 256, GEMM_SMEM>>>(xth,      xtl,      wvh, wvl, bv, pre, 768, 0, 2048, 0,    512);
    gemm_tc<<<dim3(4, 64), 256, GEMM_SMEM>>>(xth + XT, xtl + XT, wih, wil, bi, pre, 768, 0, 2048, 1024, 512);
    // GN1
    gn_stats_seq<<<dim3(32, 16), 256>>>(pre, st1);
    gn1_finish2<<<8192, 256>>>(pre, st1, gv, bev, gi, bei, le, src, srch, srcl, qh, ql);
    // projections
    gemm_tc<<<dim3(4, 128), 256, GEMM_SMEM>>>(srch, srcl, wvalh, wvall, b_val, vproj, 512, 0, 1024, 0, 512);
    gemm_tc<<<dim3(2, 128), 256, GEMM_SMEM>>>(qh,   ql,   woah,  woal,  boa,   oa,    512, 0, 1024, 0, 256);
    // softmax + sampling
    softmax8<<<512, 256>>>(oa);
    msda_sample<<<MROWS, 512>>>(vproj, oa, msh, msl);
    // output projection
    gemm_tc<<<dim3(4, 128), 256, GEMM_SMEM>>>(msh, msl, wouth, woutl, b_out, attno, 512, 0, 1024, 0, 512);
    // residual + LN -> cat bf16
    ln_res<<<MROWS, 256>>>(src, attno, ln_g, ln_b, cath, catl);
    // conv2: D[768, 8192] -> (b, o, hw)
    gemm_tc<<<dim3(64, 6), 256, GEMM_SMEM>>>(wch, wcl, cath, catl, bc, conv2, 1024, 1, 0, 0, 768);
    // final GN
    gn_stats<<<dim3(32, BB), 256>>>(conv2, st2, 24 * HWW);
    gn2_finish<<<24576, 256>>>(conv2, st2, gc, bec, (float*)d_out);
}

// round 7
// speedup vs baseline: 2.8480x; 1.3379x over previous
#include <cuda_runtime.h>
#include <cuda_fp16.h>
#include <cstdint>

#define BB   8
#define CC   768
#define DD   512
#define HWW  1024
#define LQQ  2048
#define MROWS (BB*LQQ)   // 16384

// ---------------- scratch (device globals) ----------------
__device__ uint4 g_xth [2][8192*768/8], g_xtl [2][8192*768/8];
__device__ uint4 g_wvh_[512*768/8];
__device__ uint4 g_wih_[512*768/8];
__device__ uint4 g_wvalh[512*512/8];
__device__ uint4 g_wouth[512*512/8];
__device__ uint4 g_woah[256*512/8];
__device__ uint4 g_wch_[768*1024/8], g_wcl_[768*1024/8];
__device__ uint4 g_srch[MROWS*512/8], g_srcl[MROWS*512/8];
__device__ uint4 g_qh_[MROWS*512/8],  g_ql_[MROWS*512/8];
__device__ uint4 g_msh[MROWS*512/8],  g_msl[MROWS*512/8];
__device__ uint4 g_cath[8192*1024/8];
__device__ float4 g_pre4  [MROWS*512/4];
__device__ float4 g_src4  [MROWS*512/4];
__device__ float4 g_vproj4[MROWS*512/4];
__device__ float4 g_oa4   [MROWS*256/4];
__device__ float4 g_attno4[MROWS*512/4];
__device__ float4 g_conv24[BB*CC*HWW/4];
__device__ float4 g_boa4  [64];
__device__ float  g_stats1[BB*2*32*2];
__device__ float  g_stats2[BB*32*2];

// ---------------- PTX helpers (sm_80-compatible ISA only) ----------------
__device__ __forceinline__ uint32_t smem_u32(const void* p) {
    uint32_t a;
    asm("{ .reg .u64 t; cvta.to.shared.u64 t, %1; cvt.u32.u64 %0, t; }" : "=r"(a) : "l"(p));
    return a;
}
#define CP16(s, g) \
    asm volatile("cp.async.cg.shared.global [%0], [%1], 16;" :: "r"(s), "l"(g))
#define CP_COMMIT() asm volatile("cp.async.commit_group;" ::: "memory")
#define LDSM4(r, a) \
    asm volatile("ldmatrix.sync.aligned.m8n8.x4.shared.b16 {%0,%1,%2,%3}, [%4];" \
        : "=r"((r)[0]), "=r"((r)[1]), "=r"((r)[2]), "=r"((r)[3]) : "r"(a))
#define MMA16(c, a, b0, b1) \
    asm volatile("mma.sync.aligned.m16n8k16.row.col.f32.f16.f16.f32 " \
        "{%0,%1,%2,%3}, {%4,%5,%6,%7}, {%8,%9}, {%0,%1,%2,%3};" \
        : "+f"((c)[0]), "+f"((c)[1]), "+f"((c)[2]), "+f"((c)[3]) \
        : "r"((a)[0]), "r"((a)[1]), "r"((a)[2]), "r"((a)[3]), "r"(b0), "r"(b1))

__device__ __forceinline__ void splitH(float v, __half& h, __half& l) {
    h = __float2half_rn(v);
    l = __float2half_rn(v - __half2float(h));
}

// ============================================================================
// Split-fp16 HMMA GEMM: D[m,n] = sum_k A[m,k]*B[n,k].  A = Ah + Al (fp16 split),
// B single fp16.  2 products: Ah*B + Al*B, fp32 accum.
// 128x128 tiles, K chunk 32, cp.async double buffer.
// mode 0: C[((m>>10)*mMul + mOff + (m&1023))*ldC + n] + bias[n]
// mode 1: C[((n>>10)*ldC + m)*1024 + (n&1023)]        + bias[m]
// smem stage: Ah | Al | B @ 8KB each = 24KB; 2 stages = 48KB.
// ============================================================================
#define GEMM_SMEM 49152
__global__ __launch_bounds__(256) void gemm_tc(
    const __half* __restrict__ Ah, const __half* __restrict__ Al,
    const __half* __restrict__ B,
    const float* __restrict__ bias, float* __restrict__ C,
    int K, int mode, int mMul, int mOff, int ldC)
{
    extern __shared__ __align__(16) char smem[];
    const uint32_t sb = smem_u32(smem);
    const int tid = threadIdx.x;
    const int m0 = blockIdx.y * 128, n0 = blockIdx.x * 128;
    const int warp = tid >> 5, lane = tid & 31;
    const int wm = warp >> 1, wn = warp & 1;

    const int kg = tid & 3, r0 = tid >> 2;
    const int arow_l = lane & 15, akg_l = lane >> 4;
    const int nr = (lane & 7) + ((lane & 16) >> 1);
    const int bkg_l = (lane >> 3) & 1;

    float acc[2][8][4];
    #pragma unroll
    for (int i = 0; i < 2; ++i)
        #pragma unroll
        for (int j = 0; j < 8; ++j)
            #pragma unroll
            for (int k = 0; k < 4; ++k) acc[i][j][k] = 0.f;

    const int nC = K >> 5;

    auto load_stage = [&](int c) {
        const uint32_t stb = sb + (uint32_t)(c & 1) * 24576u;
        const int k0 = c << 5;
        #pragma unroll
        for (int h = 0; h < 2; ++h) {
            int row = r0 + h * 64;
            uint32_t so = (uint32_t)(row * 64 + ((kg ^ (row & 3)) << 4));
            size_t ga = (size_t)(m0 + row) * K + k0 + kg * 8;
            size_t gb = (size_t)(n0 + row) * K + k0 + kg * 8;
            CP16(stb +         so, Ah + ga);
            CP16(stb +  8192 + so, Al + ga);
            CP16(stb + 16384 + so, B  + gb);
        }
        CP_COMMIT();
    };

    load_stage(0);
    for (int c = 0; c < nC; ++c) {
        if (c + 1 < nC) {
            load_stage(c + 1);
            asm volatile("cp.async.wait_group 1;" ::: "memory");
        } else {
            asm volatile("cp.async.wait_group 0;" ::: "memory");
        }
        __syncthreads();
        const uint32_t stb = sb + (uint32_t)(c & 1) * 24576u;
        #pragma unroll
        for (int kk = 0; kk < 2; ++kk) {
            uint32_t ah[2][4], al[2][4];
            #pragma unroll
            for (int mf = 0; mf < 2; ++mf) {
                int arow = wm * 32 + mf * 16 + arow_l;
                uint32_t ad = stb + (uint32_t)(arow * 64 +
                              ((((kk << 1) + akg_l) ^ (arow_l & 3)) << 4));
                LDSM4(ah[mf], ad);
                LDSM4(al[mf], ad + 8192);
            }
            #pragma unroll
            for (int np = 0; np < 4; ++np) {
                int brow = wn * 64 + np * 16 + nr;
                uint32_t bd = stb + 16384u + (uint32_t)(brow * 64 +
                              ((((kk << 1) + bkg_l) ^ (nr & 3)) << 4));
                uint32_t bh[4];
                LDSM4(bh, bd);
                #pragma unroll
                for (int half = 0; half < 2; ++half) {
                    uint32_t b0 = bh[half*2], b1 = bh[half*2+1];
                    int nj = np * 2 + half;
                    #pragma unroll
                    for (int mf = 0; mf < 2; ++mf) {
                        MMA16(acc[mf][nj], ah[mf], b0, b1);
                        MMA16(acc[mf][nj], al[mf], b0, b1);
                    }
                }
            }
        }
        __syncthreads();
    }

    // ---- epilogue: direct float2 stores ----
    const int tq = lane >> 2, tr2 = (lane & 3) * 2;
    #pragma unroll
    for (int mf = 0; mf < 2; ++mf) {
        #pragma unroll
        for (int nj = 0; nj < 8; ++nj) {
            int mrow = m0 + wm * 32 + mf * 16 + tq;
            int col  = n0 + wn * 64 + nj * 8 + tr2;
            float* a0 = acc[mf][nj];
            if (mode == 0) {
                float b0 = bias[col], b1 = bias[col + 1];
                int rp0 = (mrow >> 10) * mMul + mOff + (mrow & 1023);
                int m2 = mrow + 8;
                int rp1 = (m2 >> 10) * mMul + mOff + (m2 & 1023);
                *(float2*)(C + (size_t)rp0 * ldC + col) = make_float2(a0[0] + b0, a0[1] + b1);
                *(float2*)(C + (size_t)rp1 * ldC + col) = make_float2(a0[2] + b0, a0[3] + b1);
            } else {
                float bm0 = bias[mrow], bm1 = bias[mrow + 8];
                size_t base = ((size_t)((col >> 10) * ldC)) * 1024 + (col & 1023);
                *(float2*)(C + base + (size_t)mrow       * 1024) = make_float2(a0[0] + bm0, a0[1] + bm0);
                *(float2*)(C + base + (size_t)(mrow + 8) * 1024) = make_float2(a0[2] + bm1, a0[3] + bm1);
            }
        }
    }
}

// ---------------- prep: transpose (b,c,hw)->(b*hw,c) + fp16 split ----------------
__global__ void prep_input(const float* __restrict__ in,
                           __half* __restrict__ xh, __half* __restrict__ xl)
{
    __shared__ float tl[32][33];
    int b = blockIdx.z, c0 = blockIdx.y * 32, hw0 = blockIdx.x * 32;
    const float* ip = in + ((size_t)b * CC + c0) * HWW + hw0;
    #pragma unroll
    for (int j = 0; j < 4; ++j)
        tl[threadIdx.y + j*8][threadIdx.x] = ip[(size_t)(threadIdx.y + j*8) * HWW + threadIdx.x];
    __syncthreads();
    #pragma unroll
    for (int j = 0; j < 4; ++j) {
        int hw = hw0 + threadIdx.y + j*8;
        int cc = c0 + threadIdx.x;
        __half h, l; splitH(tl[threadIdx.x][threadIdx.y + j*8], h, l);
        size_t o = ((size_t)b * HWW + hw) * CC + cc;
        xh[o] = h; xl[o] = l;
    }
}

// ---------------- one-shot weight prep (all weights, one launch) ----------------
// ranges: [0,393216) wv | [+,786432) wi | [+,1048576) w_val | [+,1310720) w_out
//         [+,1441792) woa-build | [+,2228224) wc split
__global__ void prep_weights(
    const float* __restrict__ wv,    const float* __restrict__ wi,
    const float* __restrict__ w_val, const float* __restrict__ w_out,
    const float* __restrict__ w_off, const float* __restrict__ w_attn,
    const float* __restrict__ b_off, const float* __restrict__ b_attn,
    const float* __restrict__ wc,
    __half* __restrict__ wvh,  __half* __restrict__ wih,
    __half* __restrict__ wvalh,__half* __restrict__ wouth,
    __half* __restrict__ woah, float* __restrict__ boa,
    __half* __restrict__ wch,  __half* __restrict__ wcl)
{
    int i = blockIdx.x * 256 + threadIdx.x;
    if (i < 393216) {
        wvh[i] = __float2half_rn(wv[i]);
    } else if (i < 786432) {
        int j = i - 393216;
        wih[j] = __float2half_rn(wi[j]);
    } else if (i < 1048576) {
        int j = i - 786432;
        wvalh[j] = __float2half_rn(w_val[j]);
    } else if (i < 1310720) {
        int j = i - 1048576;
        wouth[j] = __float2half_rn(w_out[j]);
    } else if (i < 1441792) {
        int j = i - 1310720;               // 0..131071
        int r = j >> 9, c = j & 511;
        float v = (r < 128) ? w_off[r * 512 + c] : ((r < 192) ? w_attn[(r - 128) * 512 + c] : 0.f);
        woah[j] = __float2half_rn(v);
        if (j < 256) boa[j] = (j < 128) ? b_off[j] : ((j < 192) ? b_attn[j - 128] : 0.f);
    } else if (i < 2228224) {
        int j = i - 1441792;               // 0..786431
        __half h, l; splitH(wc[j], h, l);
        wch[j] = h; wcl[j] = l;
    }
}

// ---------------- GN stats over seq-major (rows=(be,hw), 512 ch); group=16 ch ----------------
__global__ void gn_stats_seq(const float* __restrict__ x, float* __restrict__ stats)
{
    int be = blockIdx.y, g = blockIdx.x;
    int t = threadIdx.x;
    const float* base = x + (size_t)be * 1024 * 512 + g * 16 + (t & 3) * 4;
    float s = 0.f, sq = 0.f;
    #pragma unroll
    for (int it = 0; it < 16; ++it) {
        float4 v = *(const float4*)(base + (size_t)((t >> 2) + it * 64) * 512);
        s  += v.x + v.y + v.z + v.w;
        sq += v.x*v.x + v.y*v.y + v.z*v.z + v.w*v.w;
    }
    __shared__ float red[16];
    for (int o = 16; o > 0; o >>= 1) {
        s  += __shfl_down_sync(0xffffffffu, s,  o);
        sq += __shfl_down_sync(0xffffffffu, sq, o);
    }
    if ((t & 31) == 0) { red[t >> 5] = s; red[8 + (t >> 5)] = sq; }
    __syncthreads();
    if (t < 32) {
        s  = (t < 8) ? red[t]     : 0.f;
        sq = (t < 8) ? red[8 + t] : 0.f;
        for (int o = 4; o > 0; o >>= 1) {
            s  += __shfl_down_sync(0xffffffffu, s,  o);
            sq += __shfl_down_sync(0xffffffffu, sq, o);
        }
        if (t == 0) {
            float mean = s * (1.f/16384.f);
            float var  = sq * (1.f/16384.f) - mean * mean;
            stats[(be*32+g)*2]   = mean;
            stats[(be*32+g)*2+1] = rsqrtf(var + 1e-5f);
        }
    }
}

// ---------------- GN1 finish: src fp32 + src/query fp16 hi/lo ----------------
__global__ void gn1_finish2(const float* __restrict__ pre, const float* __restrict__ stats,
    const float* __restrict__ gv, const float* __restrict__ bev,
    const float* __restrict__ gi, const float* __restrict__ bei,
    const float* __restrict__ le, float* __restrict__ src,
    __half* __restrict__ sh, __half* __restrict__ sl,
    __half* __restrict__ qh, __half* __restrict__ ql)
{
    size_t e = ((size_t)blockIdx.x * 256 + threadIdx.x) * 4;
    int row = (int)(e >> 9), d = (int)(e & 511);
    int be = row >> 10, lvl = be & 1;
    float mean = stats[(be * 32 + (d >> 4)) * 2];
    float rstd = stats[(be * 32 + (d >> 4)) * 2 + 1];
    const float* gam = lvl ? gi : gv;
    const float* bet = lvl ? bei : bev;
    float4 v = *(const float4*)(pre + e);
    float vv[4] = {v.x, v.y, v.z, v.w};
    float so[4];
    #pragma unroll
    for (int k = 0; k < 4; ++k) {
        float sv = (vv[k] - mean) * rstd * gam[d + k] + bet[d + k];
        so[k] = sv;
        __half h, l;
        splitH(sv, h, l); sh[e + k] = h; sl[e + k] = l;
        splitH(sv + le[lvl * 512 + d + k], h, l); qh[e + k] = h; ql[e + k] = l;
    }
    *(float4*)(src + e) = *(float4*)so;
}

// ---------------- softmax over 8 attn logits, in-place in oa cols 128..191 ----------------
__global__ void softmax8(float* __restrict__ oa)
{
    int i = blockIdx.x * blockDim.x + threadIdx.x;  // 131072
    float* p = oa + (size_t)(i >> 3) * 256 + 128 + (i & 7) * 8;
    float4 p0 = *(float4*)(p);
    float4 p1 = *(float4*)(p + 4);
    float m = fmaxf(fmaxf(fmaxf(p0.x, p0.y), fmaxf(p0.z, p0.w)),
                    fmaxf(fmaxf(p1.x, p1.y), fmaxf(p1.z, p1.w)));
    float e0 = expf(p0.x-m), e1 = expf(p0.y-m), e2 = expf(p0.z-m), e3 = expf(p0.w-m);
    float e4 = expf(p1.x-m), e5 = expf(p1.y-m), e6 = expf(p1.z-m), e7 = expf(p1.w-m);
    float inv = 1.f / (e0+e1+e2+e3+e4+e5+e6+e7);
    p0.x=e0*inv; p0.y=e1*inv; p0.z=e2*inv; p0.w=e3*inv;
    p1.x=e4*inv; p1.y=e5*inv; p1.z=e6*inv; p1.w=e7*inv;
    *(float4*)(p) = p0; *(float4*)(p + 4) = p1;
}

// ---------------- deformable sampling -> msout fp16 hi/lo ----------------
__global__ __launch_bounds__(512) void msda_sample(
    const float* __restrict__ vproj, const float* __restrict__ oa,
    __half* __restrict__ msh, __half* __restrict__ msl)
{
    int bq = blockIdx.x;
    int b = bq >> 11;
    int hw = bq & 1023;
    float refx = ((hw & 31) + 0.5f) * (1.f/32.f);
    float refy = ((hw >> 5) + 0.5f) * (1.f/32.f);
    __shared__ float sx[64], sy[64], sw[64];
    int t = threadIdx.x;
    const float* row = oa + (size_t)bq * 256;
    if (t < 64) {
        sx[t] = (refx + row[t*2]   * (1.f/32.f)) * 32.f - 0.5f;
        sy[t] = (refy + row[t*2+1] * (1.f/32.f)) * 32.f - 0.5f;
        sw[t] = row[128 + t];
    }
    __syncthreads();
    int head = t >> 6, dh = t & 63;
    const float* vb = vproj + (size_t)b * LQQ * DD + head * 64 + dh;
    float acc = 0.f;
    #pragma unroll
    for (int lp = 0; lp < 8; lp++) {
        int l = lp >> 2;
        float xs = sx[head*8+lp], ys = sy[head*8+lp], w = sw[head*8+lp];
        float x0f = floorf(xs), y0f = floorf(ys);
        float fx = xs - x0f, fy = ys - y0f;
        int x0 = (int)x0f, y0 = (int)y0f;
        const float* vl = vb + (size_t)l * HWW * DD;
        bool xa = (unsigned)x0 < 32u, xb = (unsigned)(x0+1) < 32u;
        bool ya = (unsigned)y0 < 32u, yb = (unsigned)(y0+1) < 32u;
        float v00 = (ya && xa) ? vl[(size_t)(y0*32 + x0)     * DD] : 0.f;
        float v01 = (ya && xb) ? vl[(size_t)(y0*32 + x0 + 1) * DD] : 0.f;
        float v10 = (yb && xa) ? vl[(size_t)(y0*32 + x0 + 32)* DD] : 0.f;
        float v11 = (yb && xb) ? vl[(size_t)(y0*32 + x0 + 33)* DD] : 0.f;
        float s = v00*(1.f-fy)*(1.f-fx) + v01*(1.f-fy)*fx + v10*fy*(1.f-fx) + v11*fy*fx;
        acc = fmaf(w, s, acc);
    }
    __half h, l; splitH(acc, h, l);
    msh[(size_t)bq * DD + t] = h;
    msl[(size_t)bq * DD + t] = l;
}

// ---------------- residual + LayerNorm -> cat fp16 (conv2 B layout) ----------------
__global__ void ln_res(const float* __restrict__ src, const float* __restrict__ att,
                       const float* __restrict__ g, const float* __restrict__ be,
                       __half* __restrict__ cath)
{
    int grow = blockIdx.x;            // b*2048 + lvl*1024 + hw
    size_t base = (size_t)grow * DD;
    int t = threadIdx.x;              // 256
    float v0 = src[base + t]       + att[base + t];
    float v1 = src[base + t + 256] + att[base + t + 256];
    float s = v0 + v1, sq = v0*v0 + v1*v1;
    __shared__ float red[16];
    for (int o = 16; o > 0; o >>= 1) {
        s  += __shfl_down_sync(0xffffffffu, s,  o);
        sq += __shfl_down_sync(0xffffffffu, sq, o);
    }
    if ((t & 31) == 0) { red[t >> 5] = s; red[8 + (t >> 5)] = sq; }
    __syncthreads();
    if (t < 32) {
        s  = (t < 8) ? red[t]     : 0.f;
        sq = (t < 8) ? red[8 + t] : 0.f;
        for (int o = 4; o > 0; o >>= 1) {
            s  += __shfl_down_sync(0xffffffffu, s,  o);
            sq += __shfl_down_sync(0xffffffffu, sq, o);
        }
        if (t == 0) { red[0] = s; red[8] = sq; }
    }
    __syncthreads();
    float mu   = red[0] * (1.f/512.f);
    float var  = red[8] * (1.f/512.f) - mu * mu;
    float rstd = rsqrtf(var + 1e-5f);
    int b = grow >> 11, lvl = (grow >> 10) & 1, hw = grow & 1023;
    size_t obase = ((size_t)b * 1024 + hw) * 1024 + lvl * 512;
    cath[obase + t]       = __float2half_rn((v0 - mu) * rstd * g[t]       + be[t]);
    cath[obase + t + 256] = __float2half_rn((v1 - mu) * rstd * g[t + 256] + be[t + 256]);
}

// ---------------- GN stats: contiguous groups (conv2 output) ----------------
__global__ void gn_stats(const float* __restrict__ x, float* __restrict__ stats, int groupElems)
{
    int idx = blockIdx.y * gridDim.x + blockIdx.x;
    const float* p = x + (size_t)idx * groupElems;
    float s = 0.f, sq = 0.f;
    for (int i = threadIdx.x * 4; i < groupElems; i += blockDim.x * 4) {
        float4 v = *(const float4*)(p + i);
        s  += v.x + v.y + v.z + v.w;
        sq += v.x*v.x + v.y*v.y + v.z*v.z + v.w*v.w;
    }
    __shared__ float red[16];
    int t = threadIdx.x;
    for (int o = 16; o > 0; o >>= 1) {
        s  += __shfl_down_sync(0xffffffffu, s,  o);
        sq += __shfl_down_sync(0xffffffffu, sq, o);
    }
    if ((t & 31) == 0) { red[t >> 5] = s; red[8 + (t >> 5)] = sq; }
    __syncthreads();
    if (t < 32) {
        s  = (t < 8) ? red[t]     : 0.f;
        sq = (t < 8) ? red[8 + t] : 0.f;
        for (int o = 4; o > 0; o >>= 1) {
            s  += __shfl_down_sync(0xffffffffu, s,  o);
            sq += __shfl_down_sync(0xffffffffu, sq, o);
        }
        if (t == 0) {
            float inv = 1.f / (float)groupElems;
            float mean = s * inv;
            stats[idx*2]   = mean;
            stats[idx*2+1] = rsqrtf(sq * inv - mean * mean + 1e-5f);
        }
    }
}

__global__ void gn2_finish(const float* __restrict__ x, const float* __restrict__ stats,
    const float* __restrict__ gc, const float* __restrict__ bec, float* __restrict__ out)
{
    size_t i = (size_t)blockIdx.x * blockDim.x + threadIdx.x;
    int hwch = (int)(i >> 10);
    int ch = hwch % 768;
    int b  = hwch / 768;
    int g  = ch / 24;
    float mean = stats[(b*32 + g) * 2];
    float rstd = stats[(b*32 + g) * 2 + 1];
    out[i] = (x[i] - mean) * rstd * gc[ch] + bec[ch];
}

// ---------------- launcher ----------------
#define SYM(T, v, s) T v; cudaGetSymbolAddress((void**)&v, s)
extern "C" void kernel_launch(void* const* d_in, const int* in_sizes, int n_in,
                              void* d_out, int out_size)
{
    const float* input_v = (const float*)d_in[0];
    const float* input_i = (const float*)d_in[1];
    const float* wv      = (const float*)d_in[2];
    const float* bv      = (const float*)d_in[3];
    const float* gv      = (const float*)d_in[4];
    const float* bev     = (const float*)d_in[5];
    const float* wi      = (const float*)d_in[6];
    const float* bi      = (const float*)d_in[7];
    const float* gi      = (const float*)d_in[8];
    const float* bei     = (const float*)d_in[9];
    const float* le      = (const float*)d_in[10];
    const float* w_off   = (const float*)d_in[11];
    const float* b_off   = (const float*)d_in[12];
    const float* w_attn  = (const float*)d_in[13];
    const float* b_attn  = (const float*)d_in[14];
    const float* w_val   = (const float*)d_in[15];
    const float* b_val   = (const float*)d_in[16];
    const float* w_out   = (const float*)d_in[17];
    const float* b_out   = (const float*)d_in[18];
    const float* ln_g    = (const float*)d_in[19];
    const float* ln_b    = (const float*)d_in[20];
    const float* wc      = (const float*)d_in[21];
    const float* bc      = (const float*)d_in[22];
    const float* gc      = (const float*)d_in[23];
    const float* bec     = (const float*)d_in[24];

    SYM(__half*, xth,  g_xth);  SYM(__half*, xtl,  g_xtl);
    SYM(__half*, wvh,  g_wvh_);
    SYM(__half*, wih,  g_wih_);
    SYM(__half*, wvalh,g_wvalh);
    SYM(__half*, wouth,g_wouth);
    SYM(__half*, woah, g_woah);
    SYM(__half*, wch,  g_wch_); SYM(__half*, wcl,  g_wcl_);
    SYM(__half*, srch, g_srch); SYM(__half*, srcl, g_srcl);
    SYM(__half*, qh,   g_qh_);  SYM(__half*, ql,   g_ql_);
    SYM(__half*, msh,  g_msh);  SYM(__half*, msl,  g_msl);
    SYM(__half*, cath, g_cath);
    SYM(float*, pre,   g_pre4);   SYM(float*, src,   g_src4);
    SYM(float*, vproj, g_vproj4); SYM(float*, oa,    g_oa4);
    SYM(float*, attno, g_attno4); SYM(float*, conv2, g_conv24);
    SYM(float*, boa,   g_boa4);
    SYM(float*, st1,   g_stats1); SYM(float*, st2,   g_stats2);
    size_t XT = (size_t)8192*768;

    cudaFuncSetAttribute(gemm_tc, cudaFuncAttributeMaxDynamicSharedMemorySize, GEMM_SMEM);

    // prep (one weight launch + two input transposes)
    prep_weights<<<8704, 256>>>(wv, wi, w_val, w_out, w_off, w_attn, b_off, b_attn, wc,
                                wvh, wih, wvalh, wouth, woah, boa, wch, wcl);
    prep_input<<<dim3(32, 24, BB), dim3(32, 8)>>>(input_v, xth, xtl);
    prep_input<<<dim3(32, 24, BB), dim3(32, 8)>>>(input_i, xth + XT, xtl + XT);

    // conv1 (v, i): D[8192,512], rows -> (b, lvl, hw)
    gemm_tc<<<dim3(4, 64), 256, GEMM_SMEM>>>(xth,      xtl,      wvh, bv, pre, 768, 0, 2048, 0,    512);
    gemm_tc<<<dim3(4, 64), 256, GEMM_SMEM>>>(xth + XT, xtl + XT, wih, bi, pre, 768, 0, 2048, 1024, 512);
    // GN1
    gn_stats_seq<<<dim3(32, 16), 256>>>(pre, st1);
    gn1_finish2<<<8192, 256>>>(pre, st1, gv, bev, gi, bei, le, src, srch, srcl, qh, ql);
    // projections
    gemm_tc<<<dim3(4, 128), 256, GEMM_SMEM>>>(srch, srcl, wvalh, b_val, vproj, 512, 0, 1024, 0, 512);
    gemm_tc<<<dim3(2, 128), 256, GEMM_SMEM>>>(qh,   ql,   woah,  boa,   oa,    512, 0, 1024, 0, 256);
    // softmax + sampling
    softmax8<<<512, 256>>>(oa);
    msda_sample<<<MROWS, 512>>>(vproj, oa, msh, msl);
    // output projection
    gemm_tc<<<dim3(4, 128), 256, GEMM_SMEM>>>(msh, msl, wouth, b_out, attno, 512, 0, 1024, 0, 512);
    // residual + LN -> cat fp16
    ln_res<<<MROWS, 256>>>(src, attno, ln_g, ln_b, cath);
    // conv2: D[768, 8192] -> (b, o, hw)
    gemm_tc<<<dim3(64, 6), 256, GEMM_SMEM>>>(wch, wcl, cath, bc, conv2, 1024, 1, 0, 0, 768);
    // final GN
    gn_stats<<<dim3(32, BB), 256>>>(conv2, st2, 24 * HWW);
    gn2_finish<<<24576, 256>>>(conv2, st2, gc, bec, (float*)d_out);
}

// round 8
// speedup vs baseline: 2.8528x; 1.0017x over previous
#include <cuda_runtime.h>
#include <cuda_fp16.h>
#include <cstdint>

#define BB   8
#define CC   768
#define DD   512
#define HWW  1024
#define LQQ  2048
#define MROWS (BB*LQQ)   // 16384

// ---------------- scratch (device globals) ----------------
__device__ uint4 g_xth [2][8192*768/8], g_xtl [2][8192*768/8];
__device__ uint4 g_w1h [2*512*768/8];                 // conv1 weights v|i
__device__ uint4 g_wvalh[512*512/8];
__device__ uint4 g_wouth[512*512/8];
__device__ uint4 g_woah[256*512/8];
__device__ uint4 g_wch_[768*1024/8], g_wcl_[768*1024/8];
__device__ uint4 g_srch[MROWS*512/8], g_srcl[MROWS*512/8];
__device__ uint4 g_qh_[MROWS*512/8],  g_ql_[MROWS*512/8];
__device__ uint4 g_msh[MROWS*512/8],  g_msl[MROWS*512/8];
__device__ uint4 g_cath[8192*1024/8];
__device__ uint4 g_vph [MROWS*512/8];                 // vproj fp16
__device__ float4 g_pre4  [MROWS*512/4];
__device__ float4 g_src4  [MROWS*512/4];
__device__ float4 g_oa4   [MROWS*256/4];
__device__ float4 g_attno4[MROWS*512/4];
__device__ float4 g_conv24[BB*CC*HWW/4];
__device__ float4 g_boa4  [64];
__device__ float  g_b1   [1024];                      // conv1 bias v|i
__device__ float  g_stats1[BB*2*32*2];
__device__ float  g_stats2[BB*32*2];

// ---------------- PTX helpers (sm_80-compatible ISA only) ----------------
__device__ __forceinline__ uint32_t smem_u32(const void* p) {
    uint32_t a;
    asm("{ .reg .u64 t; cvta.to.shared.u64 t, %1; cvt.u32.u64 %0, t; }" : "=r"(a) : "l"(p));
    return a;
}
#define CP16(s, g) \
    asm volatile("cp.async.cg.shared.global [%0], [%1], 16;" :: "r"(s), "l"(g))
#define CP_COMMIT() asm volatile("cp.async.commit_group;" ::: "memory")
#define LDSM4(r, a) \
    asm volatile("ldmatrix.sync.aligned.m8n8.x4.shared.b16 {%0,%1,%2,%3}, [%4];" \
        : "=r"((r)[0]), "=r"((r)[1]), "=r"((r)[2]), "=r"((r)[3]) : "r"(a))
#define MMA16(c, a, b0, b1) \
    asm volatile("mma.sync.aligned.m16n8k16.row.col.f32.f16.f16.f32 " \
        "{%0,%1,%2,%3}, {%4,%5,%6,%7}, {%8,%9}, {%0,%1,%2,%3};" \
        : "+f"((c)[0]), "+f"((c)[1]), "+f"((c)[2]), "+f"((c)[3]) \
        : "r"((a)[0]), "r"((a)[1]), "r"((a)[2]), "r"((a)[3]), "r"(b0), "r"(b1))

__device__ __forceinline__ void splitH(float v, __half& h, __half& l) {
    h = __float2half_rn(v);
    l = __float2half_rn(v - __half2float(h));
}

// ============================================================================
// Split-fp16 HMMA GEMM: D[m,n] = sum_k A[m,k]*B[n,k].  A = Ah + Al, B fp16.
// 128x128 tiles, K chunk 32, 3-stage cp.async pipeline (24KB/stage).
// mode 0: fp32 C[((m>>10)*mMul + mOff + m&1023)*ldC + n] + bias[n]
// mode 1: fp32 C[((n>>10)*ldC + m)*1024 + (n&1023)]      + bias[m]
// mode 2: fp16 C, same row mapping as mode 0
// blockIdx.z planes: A += z*zA, B += z*zB, bias += z*zBias, mOff += z*zOffMul
// ============================================================================
#define GEMM_SMEM 73728
__global__ __launch_bounds__(256) void gemm_tc(
    const __half* __restrict__ Ah, const __half* __restrict__ Al,
    const __half* __restrict__ B,
    const float* __restrict__ bias, void* __restrict__ Cv,
    int K, int mode, int mMul, int mOff, int ldC,
    long zA, long zB, int zBias, int zOffMul)
{
    extern __shared__ __align__(16) char smem[];
    const uint32_t sb = smem_u32(smem);
    const int tid = threadIdx.x;
    const int z = blockIdx.z;
    Ah += (size_t)z * zA; Al += (size_t)z * zA; B += (size_t)z * zB;
    bias += z * zBias;
    const int mOffE = mOff + z * zOffMul;
    const int m0 = blockIdx.y * 128, n0 = blockIdx.x * 128;
    const int warp = tid >> 5, lane = tid & 31;
    const int wm = warp >> 1, wn = warp & 1;

    const int kg = tid & 3, r0 = tid >> 2;
    const int arow_l = lane & 15, akg_l = lane >> 4;
    const int nr = (lane & 7) + ((lane & 16) >> 1);
    const int bkg_l = (lane >> 3) & 1;

    float acc[2][8][4];
    #pragma unroll
    for (int i = 0; i < 2; ++i)
        #pragma unroll
        for (int j = 0; j < 8; ++j)
            #pragma unroll
            for (int k = 0; k < 4; ++k) acc[i][j][k] = 0.f;

    const int nC = K >> 5;

    auto load_stage = [&](int c, int st) {
        const uint32_t stb = sb + (uint32_t)st * 24576u;
        const int k0 = c << 5;
        #pragma unroll
        for (int h = 0; h < 2; ++h) {
            int row = r0 + h * 64;
            uint32_t so = (uint32_t)(row * 64 + ((kg ^ (row & 3)) << 4));
            size_t ga = (size_t)(m0 + row) * K + k0 + kg * 8;
            size_t gb = (size_t)(n0 + row) * K + k0 + kg * 8;
            CP16(stb +         so, Ah + ga);
            CP16(stb +  8192 + so, Al + ga);
            CP16(stb + 16384 + so, B  + gb);
        }
        CP_COMMIT();
    };

    load_stage(0, 0);
    if (nC > 1) load_stage(1, 1);
    int stc = 0, stn = 2;
    for (int c = 0; c < nC; ++c) {
        if (c + 2 < nC) {
            load_stage(c + 2, stn);
            asm volatile("cp.async.wait_group 2;" ::: "memory");
        } else if (c + 1 < nC) {
            asm volatile("cp.async.wait_group 1;" ::: "memory");
        } else {
            asm volatile("cp.async.wait_group 0;" ::: "memory");
        }
        __syncthreads();
        const uint32_t stb = sb + (uint32_t)stc * 24576u;
        #pragma unroll
        for (int kk = 0; kk < 2; ++kk) {
            uint32_t ah[2][4], al[2][4];
            #pragma unroll
            for (int mf = 0; mf < 2; ++mf) {
                int arow = wm * 32 + mf * 16 + arow_l;
                uint32_t ad = stb + (uint32_t)(arow * 64 +
                              ((((kk << 1) + akg_l) ^ (arow_l & 3)) << 4));
                LDSM4(ah[mf], ad);
                LDSM4(al[mf], ad + 8192);
            }
            #pragma unroll
            for (int np = 0; np < 4; ++np) {
                int brow = wn * 64 + np * 16 + nr;
                uint32_t bd = stb + 16384u + (uint32_t)(brow * 64 +
                              ((((kk << 1) + bkg_l) ^ (nr & 3)) << 4));
                uint32_t bh[4];
                LDSM4(bh, bd);
                #pragma unroll
                for (int half = 0; half < 2; ++half) {
                    uint32_t b0 = bh[half*2], b1 = bh[half*2+1];
                    int nj = np * 2 + half;
                    #pragma unroll
                    for (int mf = 0; mf < 2; ++mf) {
                        MMA16(acc[mf][nj], ah[mf], b0, b1);
                        MMA16(acc[mf][nj], al[mf], b0, b1);
                    }
                }
            }
        }
        __syncthreads();
        stc = (stc == 2) ? 0 : stc + 1;
        stn = (stn == 2) ? 0 : stn + 1;
    }

    // ---- epilogue ----
    const int tq = lane >> 2, tr2 = (lane & 3) * 2;
    #pragma unroll
    for (int mf = 0; mf < 2; ++mf) {
        #pragma unroll
        for (int nj = 0; nj < 8; ++nj) {
            int mrow = m0 + wm * 32 + mf * 16 + tq;
            int col  = n0 + wn * 64 + nj * 8 + tr2;
            float* a0 = acc[mf][nj];
            if (mode == 1) {
                float* C = (float*)Cv;
                float bm0 = bias[mrow], bm1 = bias[mrow + 8];
                size_t base = ((size_t)((col >> 10) * ldC)) * 1024 + (col & 1023);
                *(float2*)(C + base + (size_t)mrow       * 1024) = make_float2(a0[0] + bm0, a0[1] + bm0);
                *(float2*)(C + base + (size_t)(mrow + 8) * 1024) = make_float2(a0[2] + bm1, a0[3] + bm1);
            } else {
                float b0 = bias[col], b1 = bias[col + 1];
                int rp0 = (mrow >> 10) * mMul + mOffE + (mrow & 1023);
                int m2 = mrow + 8;
                int rp1 = (m2 >> 10) * mMul + mOffE + (m2 & 1023);
                if (mode == 0) {
                    float* C = (float*)Cv;
                    *(float2*)(C + (size_t)rp0 * ldC + col) = make_float2(a0[0] + b0, a0[1] + b1);
                    *(float2*)(C + (size_t)rp1 * ldC + col) = make_float2(a0[2] + b0, a0[3] + b1);
                } else {
                    __half* C = (__half*)Cv;
                    *(__half2*)(C + (size_t)rp0 * ldC + col) =
                        __floats2half2_rn(a0[0] + b0, a0[1] + b1);
                    *(__half2*)(C + (size_t)rp1 * ldC + col) =
                        __floats2half2_rn(a0[2] + b0, a0[3] + b1);
                }
            }
        }
    }
}

// ---------------- prep: transpose (b,c,hw)->(b*hw,c) + fp16 split ----------------
__global__ void prep_input(const float* __restrict__ in,
                           __half* __restrict__ xh, __half* __restrict__ xl)
{
    __shared__ float tl[32][33];
    int b = blockIdx.z, c0 = blockIdx.y * 32, hw0 = blockIdx.x * 32;
    const float* ip = in + ((size_t)b * CC + c0) * HWW + hw0;
    #pragma unroll
    for (int j = 0; j < 4; ++j)
        tl[threadIdx.y + j*8][threadIdx.x] = ip[(size_t)(threadIdx.y + j*8) * HWW + threadIdx.x];
    __syncthreads();
    #pragma unroll
    for (int j = 0; j < 4; ++j) {
        int hw = hw0 + threadIdx.y + j*8;
        int cc = c0 + threadIdx.x;
        __half h, l; splitH(tl[threadIdx.x][threadIdx.y + j*8], h, l);
        size_t o = ((size_t)b * HWW + hw) * CC + cc;
        xh[o] = h; xl[o] = l;
    }
}

// ---------------- one-shot weight prep ----------------
__global__ void prep_weights(
    const float* __restrict__ wv,    const float* __restrict__ wi,
    const float* __restrict__ w_val, const float* __restrict__ w_out,
    const float* __restrict__ w_off, const float* __restrict__ w_attn,
    const float* __restrict__ b_off, const float* __restrict__ b_attn,
    const float* __restrict__ wc,
    const float* __restrict__ bv,    const float* __restrict__ bi,
    __half* __restrict__ w1h,
    __half* __restrict__ wvalh,__half* __restrict__ wouth,
    __half* __restrict__ woah, float* __restrict__ boa,
    __half* __restrict__ wch,  __half* __restrict__ wcl,
    float* __restrict__ b1)
{
    int i = blockIdx.x * 256 + threadIdx.x;
    if (i < 786432) {
        w1h[i] = __float2half_rn(i < 393216 ? wv[i] : wi[i - 393216]);
    } else if (i < 1048576) {
        int j = i - 786432;
        wvalh[j] = __float2half_rn(w_val[j]);
    } else if (i < 1310720) {
        int j = i - 1048576;
        wouth[j] = __float2half_rn(w_out[j]);
    } else if (i < 1441792) {
        int j = i - 1310720;               // 0..131071
        int r = j >> 9, c = j & 511;
        float v = (r < 128) ? w_off[r * 512 + c] : ((r < 192) ? w_attn[(r - 128) * 512 + c] : 0.f);
        woah[j] = __float2half_rn(v);
        if (j < 256) boa[j] = (j < 128) ? b_off[j] : ((j < 192) ? b_attn[j - 128] : 0.f);
    } else if (i < 2228224) {
        int j = i - 1441792;               // 0..786431
        __half h, l; splitH(wc[j], h, l);
        wch[j] = h; wcl[j] = l;
    } else if (i < 2229248) {
        int j = i - 2228224;               // 0..1023
        b1[j] = (j < 512) ? bv[j] : bi[j - 512];
    }
}

// ---------------- GN stats over seq-major (rows=(be,hw), 512 ch); group=16 ch ----------------
__global__ void gn_stats_seq(const float* __restrict__ x, float* __restrict__ stats)
{
    int be = blockIdx.y, g = blockIdx.x;
    int t = threadIdx.x;
    const float* base = x + (size_t)be * 1024 * 512 + g * 16 + (t & 3) * 4;
    float s = 0.f, sq = 0.f;
    #pragma unroll
    for (int it = 0; it < 16; ++it) {
        float4 v = *(const float4*)(base + (size_t)((t >> 2) + it * 64) * 512);
        s  += v.x + v.y + v.z + v.w;
        sq += v.x*v.x + v.y*v.y + v.z*v.z + v.w*v.w;
    }
    __shared__ float red[16];
    for (int o = 16; o > 0; o >>= 1) {
        s  += __shfl_down_sync(0xffffffffu, s,  o);
        sq += __shfl_down_sync(0xffffffffu, sq, o);
    }
    if ((t & 31) == 0) { red[t >> 5] = s; red[8 + (t >> 5)] = sq; }
    __syncthreads();
    if (t < 32) {
        s  = (t < 8) ? red[t]     : 0.f;
        sq = (t < 8) ? red[8 + t] : 0.f;
        for (int o = 4; o > 0; o >>= 1) {
            s  += __shfl_down_sync(0xffffffffu, s,  o);
            sq += __shfl_down_sync(0xffffffffu, sq, o);
        }
        if (t == 0) {
            float mean = s * (1.f/16384.f);
            float var  = sq * (1.f/16384.f) - mean * mean;
            stats[(be*32+g)*2]   = mean;
            stats[(be*32+g)*2+1] = rsqrtf(var + 1e-5f);
        }
    }
}

// ---------------- GN1 finish: src fp32 + src/query fp16 hi/lo ----------------
__global__ void gn1_finish2(const float* __restrict__ pre, const float* __restrict__ stats,
    const float* __restrict__ gv, const float* __restrict__ bev,
    const float* __restrict__ gi, const float* __restrict__ bei,
    const float* __restrict__ le, float* __restrict__ src,
    __half* __restrict__ sh, __half* __restrict__ sl,
    __half* __restrict__ qh, __half* __restrict__ ql)
{
    size_t e = ((size_t)blockIdx.x * 256 + threadIdx.x) * 4;
    int row = (int)(e >> 9), d = (int)(e & 511);
    int be = row >> 10, lvl = be & 1;
    float mean = stats[(be * 32 + (d >> 4)) * 2];
    float rstd = stats[(be * 32 + (d >> 4)) * 2 + 1];
    const float* gam = lvl ? gi : gv;
    const float* bet = lvl ? bei : bev;
    float4 v = *(const float4*)(pre + e);
    float vv[4] = {v.x, v.y, v.z, v.w};
    float so[4];
    #pragma unroll
    for (int k = 0; k < 4; ++k) {
        float sv = (vv[k] - mean) * rstd * gam[d + k] + bet[d + k];
        so[k] = sv;
        __half h, l;
        splitH(sv, h, l); sh[e + k] = h; sl[e + k] = l;
        splitH(sv + le[lvl * 512 + d + k], h, l); qh[e + k] = h; ql[e + k] = l;
    }
    *(float4*)(src + e) = *(float4*)so;
}

// ---------------- deformable sampling (fused softmax) -> msout fp16 hi/lo ----------------
__global__ __launch_bounds__(512) void msda_sample(
    const __half* __restrict__ vproj, const float* __restrict__ oa,
    __half* __restrict__ msh, __half* __restrict__ msl)
{
    int bq = blockIdx.x;
    int b = bq >> 11;
    int hw = bq & 1023;
    float refx = ((hw & 31) + 0.5f) * (1.f/32.f);
    float refy = ((hw >> 5) + 0.5f) * (1.f/32.f);
    __shared__ float sx[64], sy[64], sw[64];
    int t = threadIdx.x;
    const float* row = oa + (size_t)bq * 256;
    if (t < 64) {
        sx[t] = (refx + row[t*2]   * (1.f/32.f)) * 32.f - 0.5f;
        sy[t] = (refy + row[t*2+1] * (1.f/32.f)) * 32.f - 0.5f;
        // fused softmax over the 8 logits of this head (8-lane shuffle groups)
        float lg = row[128 + t];
        float m = lg;
        #pragma unroll
        for (int o = 1; o < 8; o <<= 1) m = fmaxf(m, __shfl_xor_sync(0xffffffffu, m, o));
        float ex = expf(lg - m);
        float s = ex;
        #pragma unroll
        for (int o = 1; o < 8; o <<= 1) s += __shfl_xor_sync(0xffffffffu, s, o);
        sw[t] = ex / s;
    }
    __syncthreads();
    int head = t >> 6, dh = t & 63;
    const __half* vb = vproj + (size_t)b * LQQ * DD + head * 64 + dh;
    float acc = 0.f;
    #pragma unroll
    for (int lp = 0; lp < 8; lp++) {
        int l = lp >> 2;
        float xs = sx[head*8+lp], ys = sy[head*8+lp], w = sw[head*8+lp];
        float x0f = floorf(xs), y0f = floorf(ys);
        float fx = xs - x0f, fy = ys - y0f;
        int x0 = (int)x0f, y0 = (int)y0f;
        const __half* vl = vb + (size_t)l * HWW * DD;
        bool xa = (unsigned)x0 < 32u, xb = (unsigned)(x0+1) < 32u;
        bool ya = (unsigned)y0 < 32u, yb = (unsigned)(y0+1) < 32u;
        float v00 = (ya && xa) ? __half2float(vl[(size_t)(y0*32 + x0)     * DD]) : 0.f;
        float v01 = (ya && xb) ? __half2float(vl[(size_t)(y0*32 + x0 + 1) * DD]) : 0.f;
        float v10 = (yb && xa) ? __half2float(vl[(size_t)(y0*32 + x0 + 32)* DD]) : 0.f;
        float v11 = (yb && xb) ? __half2float(vl[(size_t)(y0*32 + x0 + 33)* DD]) : 0.f;
        float s = v00*(1.f-fy)*(1.f-fx) + v01*(1.f-fy)*fx + v10*fy*(1.f-fx) + v11*fy*fx;
        acc = fmaf(w, s, acc);
    }
    __half h, l; splitH(acc, h, l);
    msh[(size_t)bq * DD + t] = h;
    msl[(size_t)bq * DD + t] = l;
}

// ---------------- residual + LayerNorm -> cat fp16 (conv2 B layout) ----------------
__global__ void ln_res(const float* __restrict__ src, const float* __restrict__ att,
                       const float* __restrict__ g, const float* __restrict__ be,
                       __half* __restrict__ cath)
{
    int grow = blockIdx.x;            // b*2048 + lvl*1024 + hw
    size_t base = (size_t)grow * DD;
    int t = threadIdx.x;              // 256
    float v0 = src[base + t]       + att[base + t];
    float v1 = src[base + t + 256] + att[base + t + 256];
    float s = v0 + v1, sq = v0*v0 + v1*v1;
    __shared__ float red[16];
    for (int o = 16; o > 0; o >>= 1) {
        s  += __shfl_down_sync(0xffffffffu, s,  o);
        sq += __shfl_down_sync(0xffffffffu, sq, o);
    }
    if ((t & 31) == 0) { red[t >> 5] = s; red[8 + (t >> 5)] = sq; }
    __syncthreads();
    if (t < 32) {
        s  = (t < 8) ? red[t]     : 0.f;
        sq = (t < 8) ? red[8 + t] : 0.f;
        for (int o = 4; o > 0; o >>= 1) {
            s  += __shfl_down_sync(0xffffffffu, s,  o);
            sq += __shfl_down_sync(0xffffffffu, sq, o);
        }
        if (t == 0) { red[0] = s; red[8] = sq; }
    }
    __syncthreads();
    float mu   = red[0] * (1.f/512.f);
    float var  = red[8] * (1.f/512.f) - mu * mu;
    float rstd = rsqrtf(var + 1e-5f);
    int b = grow >> 11, lvl = (grow >> 10) & 1, hw = grow & 1023;
    size_t obase = ((size_t)b * 1024 + hw) * 1024 + lvl * 512;
    cath[obase + t]       = __float2half_rn((v0 - mu) * rstd * g[t]       + be[t]);
    cath[obase + t + 256] = __float2half_rn((v1 - mu) * rstd * g[t + 256] + be[t + 256]);
}

// ---------------- GN stats: contiguous groups (conv2 output) ----------------
__global__ void gn_stats(const float* __restrict__ x, float* __restrict__ stats, int groupElems)
{
    int idx = blockIdx.y * gridDim.x + blockIdx.x;
    const float* p = x + (size_t)idx * groupElems;
    float s = 0.f, sq = 0.f;
    for (int i = threadIdx.x * 4; i < groupElems; i += blockDim.x * 4) {
        float4 v = *(const float4*)(p + i);
        s  += v.x + v.y + v.z + v.w;
        sq += v.x*v.x + v.y*v.y + v.z*v.z + v.w*v.w;
    }
    __shared__ float red[16];
    int t = threadIdx.x;
    for (int o = 16; o > 0; o >>= 1) {
        s  += __shfl_down_sync(0xffffffffu, s,  o);
        sq += __shfl_down_sync(0xffffffffu, sq, o);
    }
    if ((t & 31) == 0) { red[t >> 5] = s; red[8 + (t >> 5)] = sq; }
    __syncthreads();
    if (t < 32) {
        s  = (t < 8) ? red[t]     : 0.f;
        sq = (t < 8) ? red[8 + t] : 0.f;
        for (int o = 4; o > 0; o >>= 1) {
            s  += __shfl_down_sync(0xffffffffu, s,  o);
            sq += __shfl_down_sync(0xffffffffu, sq, o);
        }
        if (t == 0) {
            float inv = 1.f / (float)groupElems;
            float mean = s * inv;
            stats[idx*2]   = mean;
            stats[idx*2+1] = rsqrtf(sq * inv - mean * mean + 1e-5f);
        }
    }
}

__global__ void gn2_finish(const float* __restrict__ x, const float* __restrict__ stats,
    const float* __restrict__ gc, const float* __restrict__ bec, float* __restrict__ out)
{
    size_t i = (size_t)blockIdx.x * blockDim.x + threadIdx.x;
    int hwch = (int)(i >> 10);
    int ch = hwch % 768;
    int b  = hwch / 768;
    int g  = ch / 24;
    float mean = stats[(b*32 + g) * 2];
    float rstd = stats[(b*32 + g) * 2 + 1];
    out[i] = (x[i] - mean) * rstd * gc[ch] + bec[ch];
}

// ---------------- launcher ----------------
#define SYM(T, v, s) T v; cudaGetSymbolAddress((void**)&v, s)
extern "C" void kernel_launch(void* const* d_in, const int* in_sizes, int n_in,
                              void* d_out, int out_size)
{
    const float* input_v = (const float*)d_in[0];
    const float* input_i = (const float*)d_in[1];
    const float* wv      = (const float*)d_in[2];
    const float* bv      = (const float*)d_in[3];
    const float* gv      = (const float*)d_in[4];
    const float* bev     = (const float*)d_in[5];
    const float* wi      = (const float*)d_in[6];
    const float* bi      = (const float*)d_in[7];
    const float* gi      = (const float*)d_in[8];
    const float* bei     = (const float*)d_in[9];
    const float* le      = (const float*)d_in[10];
    const float* w_off   = (const float*)d_in[11];
    const float* b_off   = (const float*)d_in[12];
    const float* w_attn  = (const float*)d_in[13];
    const float* b_attn  = (const float*)d_in[14];
    const float* w_val   = (const float*)d_in[15];
    const float* b_val   = (const float*)d_in[16];
    const float* w_out   = (const float*)d_in[17];
    const float* b_out   = (const float*)d_in[18];
    const float* ln_g    = (const float*)d_in[19];
    const float* ln_b    = (const float*)d_in[20];
    const float* wc      = (const float*)d_in[21];
    const float* bc      = (const float*)d_in[22];
    const float* gc      = (const float*)d_in[23];
    const float* bec     = (const float*)d_in[24];

    SYM(__half*, xth,  g_xth);  SYM(__half*, xtl,  g_xtl);
    SYM(__half*, w1h,  g_w1h);
    SYM(__half*, wvalh,g_wvalh);
    SYM(__half*, wouth,g_wouth);
    SYM(__half*, woah, g_woah);
    SYM(__half*, wch,  g_wch_); SYM(__half*, wcl,  g_wcl_);
    SYM(__half*, srch, g_srch); SYM(__half*, srcl, g_srcl);
    SYM(__half*, qh,   g_qh_);  SYM(__half*, ql,   g_ql_);
    SYM(__half*, msh,  g_msh);  SYM(__half*, msl,  g_msl);
    SYM(__half*, cath, g_cath); SYM(__half*, vph,  g_vph);
    SYM(float*, pre,   g_pre4);   SYM(float*, src,   g_src4);
    SYM(float*, oa,    g_oa4);
    SYM(float*, attno, g_attno4); SYM(float*, conv2, g_conv24);
    SYM(float*, boa,   g_boa4);   SYM(float*, b1,    g_b1);
    SYM(float*, st1,   g_stats1); SYM(float*, st2,   g_stats2);
    size_t XT = (size_t)8192*768;

    cudaFuncSetAttribute(gemm_tc, cudaFuncAttributeMaxDynamicSharedMemorySize, GEMM_SMEM);

    // prep
    prep_weights<<<8708, 256>>>(wv, wi, w_val, w_out, w_off, w_attn, b_off, b_attn, wc,
                                bv, bi, w1h, wvalh, wouth, woah, boa, wch, wcl, b1);
    prep_input<<<dim3(32, 24, BB), dim3(32, 8)>>>(input_v, xth, xtl);
    prep_input<<<dim3(32, 24, BB), dim3(32, 8)>>>(input_i, xth + XT, xtl + XT);

    // conv1 (v+i in one launch, z selects plane): D[8192,512] -> rows (b, lvl, hw)
    gemm_tc<<<dim3(4, 64, 2), 256, GEMM_SMEM>>>(xth, xtl, w1h, b1, pre,
        768, 0, 2048, 0, 512, (long)XT, 393216L, 512, 1024);
    // GN1
    gn_stats_seq<<<dim3(32, 16), 256>>>(pre, st1);
    gn1_finish2<<<8192, 256>>>(pre, st1, gv, bev, gi, bei, le, src, srch, srcl, qh, ql);
    // projections (vproj writes fp16)
    gemm_tc<<<dim3(4, 128), 256, GEMM_SMEM>>>(srch, srcl, wvalh, b_val, vph,
        512, 2, 1024, 0, 512, 0L, 0L, 0, 0);
    gemm_tc<<<dim3(2, 128), 256, GEMM_SMEM>>>(qh, ql, woah, boa, oa,
        512, 0, 1024, 0, 256, 0L, 0L, 0, 0);
    // sampling (softmax fused)
    msda_sample<<<MROWS, 512>>>(vph, oa, msh, msl);
    // output projection
    gemm_tc<<<dim3(4, 128), 256, GEMM_SMEM>>>(msh, msl, wouth, b_out, attno,
        512, 0, 1024, 0, 512, 0L, 0L, 0, 0);
    // residual + LN -> cat fp16
    ln_res<<<MROWS, 256>>>(src, attno, ln_g, ln_b, cath);
    // conv2: D[768, 8192] -> (b, o, hw)
    gemm_tc<<<dim3(64, 6), 256, GEMM_SMEM>>>(wch, wcl, cath, bc, conv2,
        1024, 1, 0, 0, 768, 0L, 0L, 0, 0);
    // final GN
    gn_stats<<<dim3(32, BB), 256>>>(conv2, st2, 24 * HWW);
    gn2_finish<<<24576, 256>>>(conv2, st2, gc, bec, (float*)d_out);
}

// round 9
// speedup vs baseline: 3.0002x; 1.0517x over previous
#include <cuda_runtime.h>
#include <cuda_fp16.h>
#include <cstdint>

#define BB   8
#define CC   768
#define DD   512
#define HWW  1024
#define LQQ  2048
#define MROWS (BB*LQQ)   // 16384

// ---------------- scratch (device globals) ----------------
__device__ uint4 g_xth [2][8192*768/8], g_xtl [2][8192*768/8];
__device__ uint4 g_w1h [2*512*768/8];                 // conv1 weights v|i
__device__ uint4 g_wvalh[512*512/8];
__device__ uint4 g_wouth[512*512/8];
__device__ uint4 g_woah[256*512/8];
__device__ uint4 g_wch_[768*1024/8], g_wcl_[768*1024/8];
__device__ uint4 g_srch[MROWS*512/8], g_srcl[MROWS*512/8];
__device__ uint4 g_msh[MROWS*512/8],  g_msl[MROWS*512/8];
__device__ uint4 g_cath[8192*1024/8];
__device__ uint4 g_vph [MROWS*512/8];                 // vproj fp16
__device__ float4 g_pre4  [MROWS*512/4];
__device__ float4 g_oa4   [MROWS*256/4];
__device__ float4 g_attno4[MROWS*512/4];
__device__ float4 g_conv24[BB*CC*HWW/4];
__device__ float  g_lep  [512];                       // le@Woa^T + boa, [lvl][256]
__device__ float  g_b1   [1024];                      // conv1 bias v|i
__device__ float  g_stats1[BB*2*32*2];
__device__ float  g_stats2[BB*32*2];

// ---------------- PTX helpers (sm_80-compatible ISA only) ----------------
__device__ __forceinline__ uint32_t smem_u32(const void* p) {
    uint32_t a;
    asm("{ .reg .u64 t; cvta.to.shared.u64 t, %1; cvt.u32.u64 %0, t; }" : "=r"(a) : "l"(p));
    return a;
}
#define CP16(s, g) \
    asm volatile("cp.async.cg.shared.global [%0], [%1], 16;" :: "r"(s), "l"(g))
#define CP_COMMIT() asm volatile("cp.async.commit_group;" ::: "memory")
#define LDSM4(r, a) \
    asm volatile("ldmatrix.sync.aligned.m8n8.x4.shared.b16 {%0,%1,%2,%3}, [%4];" \
        : "=r"((r)[0]), "=r"((r)[1]), "=r"((r)[2]), "=r"((r)[3]) : "r"(a))
#define MMA16(c, a, b0, b1) \
    asm volatile("mma.sync.aligned.m16n8k16.row.col.f32.f16.f16.f32 " \
        "{%0,%1,%2,%3}, {%4,%5,%6,%7}, {%8,%9}, {%0,%1,%2,%3};" \
        : "+f"((c)[0]), "+f"((c)[1]), "+f"((c)[2]), "+f"((c)[3]) \
        : "r"((a)[0]), "r"((a)[1]), "r"((a)[2]), "r"((a)[3]), "r"(b0), "r"(b1))

__device__ __forceinline__ void splitH(float v, __half& h, __half& l) {
    h = __float2half_rn(v);
    l = __float2half_rn(v - __half2float(h));
}

// ============================================================================
// Split-fp16 HMMA GEMM: D[m,n] = sum_k A[m,k]*B[n,k].  A = Ah + Al, B fp16.
// 128x128 tiles, K chunk 32, 4-stage cp.async pipeline, ONE syncthreads/chunk.
// mode 0: fp32 C[((m>>10)*mMul + mOff + m&1023)*ldC + n] + bias[n]
// mode 1: fp32 C[((n>>10)*ldC + m)*1024 + (n&1023)]      + bias[m]
// mode 2: fp16 C, same row mapping as mode 0
// bias += z*zBias + ((m0>>10)&1)*biasLvl  (per-level bias for the oa GEMM)
// ============================================================================
#define GEMM_SMEM 98304
__global__ __launch_bounds__(256) void gemm_tc(
    const __half* __restrict__ Ah, const __half* __restrict__ Al,
    const __half* __restrict__ B,
    const float* __restrict__ bias, void* __restrict__ Cv,
    int K, int mode, int mMul, int mOff, int ldC,
    long zA, long zB, int zBias, int zOffMul, int biasLvl)
{
    extern __shared__ __align__(16) char smem[];
    const uint32_t sb = smem_u32(smem);
    const int tid = threadIdx.x;
    const int z = blockIdx.z;
    Ah += (size_t)z * zA; Al += (size_t)z * zA; B += (size_t)z * zB;
    const int m0 = blockIdx.y * 128, n0 = blockIdx.x * 128;
    bias += z * zBias + ((m0 >> 10) & 1) * biasLvl;
    const int mOffE = mOff + z * zOffMul;
    const int warp = tid >> 5, lane = tid & 31;
    const int wm = warp >> 1, wn = warp & 1;

    const int kg = tid & 3, r0 = tid >> 2;
    const int arow_l = lane & 15, akg_l = lane >> 4;
    const int nr = (lane & 7) + ((lane & 16) >> 1);
    const int bkg_l = (lane >> 3) & 1;

    float acc[2][8][4];
    #pragma unroll
    for (int i = 0; i < 2; ++i)
        #pragma unroll
        for (int j = 0; j < 8; ++j)
            #pragma unroll
            for (int k = 0; k < 4; ++k) acc[i][j][k] = 0.f;

    const int nC = K >> 5;

    auto load_stage = [&](int c) {
        const uint32_t stb = sb + (uint32_t)(c & 3) * 24576u;
        const int k0 = c << 5;
        #pragma unroll
        for (int h = 0; h < 2; ++h) {
            int row = r0 + h * 64;
            uint32_t so = (uint32_t)(row * 64 + ((kg ^ (row & 3)) << 4));
            size_t ga = (size_t)(m0 + row) * K + k0 + kg * 8;
            size_t gb = (size_t)(n0 + row) * K + k0 + kg * 8;
            CP16(stb +         so, Ah + ga);
            CP16(stb +  8192 + so, Al + ga);
            CP16(stb + 16384 + so, B  + gb);
        }
        CP_COMMIT();
    };

    // prologue: 3 stages in flight
    load_stage(0); load_stage(1); load_stage(2);
    for (int c = 0; c < nC; ++c) {
        // wait for stage c (oldest) to complete
        int rem = nC - c;
        if (rem >= 3)      asm volatile("cp.async.wait_group 2;" ::: "memory");
        else if (rem == 2) asm volatile("cp.async.wait_group 1;" ::: "memory");
        else               asm volatile("cp.async.wait_group 0;" ::: "memory");
        __syncthreads();
        // only now is stage (c+3)&3 free (all warps finished compute c-1)
        if (c + 3 < nC) load_stage(c + 3);
        const uint32_t stb = sb + (uint32_t)(c & 3) * 24576u;
        #pragma unroll
        for (int kk = 0; kk < 2; ++kk) {
            uint32_t ah[2][4], al[2][4];
            #pragma unroll
            for (int mf = 0; mf < 2; ++mf) {
                int arow = wm * 32 + mf * 16 + arow_l;
                uint32_t ad = stb + (uint32_t)(arow * 64 +
                              ((((kk << 1) + akg_l) ^ (arow_l & 3)) << 4));
                LDSM4(ah[mf], ad);
                LDSM4(al[mf], ad + 8192);
            }
            #pragma unroll
            for (int np = 0; np < 4; ++np) {
                int brow = wn * 64 + np * 16 + nr;
                uint32_t bd = stb + 16384u + (uint32_t)(brow * 64 +
                              ((((kk << 1) + bkg_l) ^ (nr & 3)) << 4));
                uint32_t bh[4];
                LDSM4(bh, bd);
                #pragma unroll
                for (int half = 0; half < 2; ++half) {
                    uint32_t b0 = bh[half*2], b1 = bh[half*2+1];
                    int nj = np * 2 + half;
                    #pragma unroll
                    for (int mf = 0; mf < 2; ++mf) {
                        MMA16(acc[mf][nj], ah[mf], b0, b1);
                        MMA16(acc[mf][nj], al[mf], b0, b1);
                    }
                }
            }
        }
    }

    // ---- epilogue ----
    const int tq = lane >> 2, tr2 = (lane & 3) * 2;
    #pragma unroll
    for (int mf = 0; mf < 2; ++mf) {
        #pragma unroll
        for (int nj = 0; nj < 8; ++nj) {
            int mrow = m0 + wm * 32 + mf * 16 + tq;
            int col  = n0 + wn * 64 + nj * 8 + tr2;
            float* a0 = acc[mf][nj];
            if (mode == 1) {
                float* C = (float*)Cv;
                float bm0 = bias[mrow], bm1 = bias[mrow + 8];
                size_t base = ((size_t)((col >> 10) * ldC)) * 1024 + (col & 1023);
                *(float2*)(C + base + (size_t)mrow       * 1024) = make_float2(a0[0] + bm0, a0[1] + bm0);
                *(float2*)(C + base + (size_t)(mrow + 8) * 1024) = make_float2(a0[2] + bm1, a0[3] + bm1);
            } else {
                float b0 = bias[col], b1 = bias[col + 1];
                int rp0 = (mrow >> 10) * mMul + mOffE + (mrow & 1023);
                int m2 = mrow + 8;
                int rp1 = (m2 >> 10) * mMul + mOffE + (m2 & 1023);
                if (mode == 0) {
                    float* C = (float*)Cv;
                    *(float2*)(C + (size_t)rp0 * ldC + col) = make_float2(a0[0] + b0, a0[1] + b1);
                    *(float2*)(C + (size_t)rp1 * ldC + col) = make_float2(a0[2] + b0, a0[3] + b1);
                } else {
                    __half* C = (__half*)Cv;
                    *(__half2*)(C + (size_t)rp0 * ldC + col) =
                        __floats2half2_rn(a0[0] + b0, a0[1] + b1);
                    *(__half2*)(C + (size_t)rp1 * ldC + col) =
                        __floats2half2_rn(a0[2] + b0, a0[3] + b1);
                }
            }
        }
    }
}

// ---------------- prep: transpose (b,c,hw)->(b*hw,c) + fp16 split ----------------
__global__ void prep_input(const float* __restrict__ in,
                           __half* __restrict__ xh, __half* __restrict__ xl)
{
    __shared__ float tl[32][33];
    int b = blockIdx.z, c0 = blockIdx.y * 32, hw0 = blockIdx.x * 32;
    const float* ip = in + ((size_t)b * CC + c0) * HWW + hw0;
    #pragma unroll
    for (int j = 0; j < 4; ++j)
        tl[threadIdx.y + j*8][threadIdx.x] = ip[(size_t)(threadIdx.y + j*8) * HWW + threadIdx.x];
    __syncthreads();
    #pragma unroll
    for (int j = 0; j < 4; ++j) {
        int hw = hw0 + threadIdx.y + j*8;
        int cc = c0 + threadIdx.x;
        __half h, l; splitH(tl[threadIdx.x][threadIdx.y + j*8], h, l);
        size_t o = ((size_t)b * HWW + hw) * CC + cc;
        xh[o] = h; xl[o] = l;
    }
}

// ---------------- one-shot weight prep ----------------
__global__ void prep_weights(
    const float* __restrict__ wv,    const float* __restrict__ wi,
    const float* __restrict__ w_val, const float* __restrict__ w_out,
    const float* __restrict__ w_off, const float* __restrict__ w_attn,
    const float* __restrict__ wc,
    const float* __restrict__ bv,    const float* __restrict__ bi,
    __half* __restrict__ w1h,
    __half* __restrict__ wvalh,__half* __restrict__ wouth,
    __half* __restrict__ woah,
    __half* __restrict__ wch,  __half* __restrict__ wcl,
    float* __restrict__ b1)
{
    int i = blockIdx.x * 256 + threadIdx.x;
    if (i < 786432) {
        w1h[i] = __float2half_rn(i < 393216 ? wv[i] : wi[i - 393216]);
    } else if (i < 1048576) {
        int j = i - 786432;
        wvalh[j] = __float2half_rn(w_val[j]);
    } else if (i < 1310720) {
        int j = i - 1048576;
        wouth[j] = __float2half_rn(w_out[j]);
    } else if (i < 1441792) {
        int j = i - 1310720;               // 0..131071
        int r = j >> 9, c = j & 511;
        float v = (r < 128) ? w_off[r * 512 + c] : ((r < 192) ? w_attn[(r - 128) * 512 + c] : 0.f);
        woah[j] = __float2half_rn(v);
    } else if (i < 2228224) {
        int j = i - 1441792;               // 0..786431
        __half h, l; splitH(wc[j], h, l);
        wch[j] = h; wcl[j] = l;
    } else if (i < 2229248) {
        int j = i - 2228224;               // 0..1023
        b1[j] = (j < 512) ? bv[j] : bi[j - 512];
    }
}

// ---------------- lep[lvl][n] = le[lvl] . Woa[n] + boa[n]  (fp32, exact) -------
__global__ void leproj_k(const float* __restrict__ le,
                         const float* __restrict__ w_off, const float* __restrict__ w_attn,
                         const float* __restrict__ b_off, const float* __restrict__ b_attn,
                         float* __restrict__ lep)
{
    int lvl = blockIdx.x, n = threadIdx.x;   // 2 x 256
    const float* l = le + lvl * 512;
    float s = 0.f;
    if (n < 128) {
        s = b_off[n];
        const float* w = w_off + n * 512;
        for (int d = 0; d < 512; ++d) s = fmaf(l[d], w[d], s);
    } else if (n < 192) {
        s = b_attn[n - 128];
        const float* w = w_attn + (n - 128) * 512;
        for (int d = 0; d < 512; ++d) s = fmaf(l[d], w[d], s);
    }
    lep[lvl * 256 + n] = s;
}

// ---------------- GN stats over seq-major (rows=(be,hw), 512 ch); group=16 ch ----------------
__global__ void gn_stats_seq(const float* __restrict__ x, float* __restrict__ stats)
{
    int be = blockIdx.y, g = blockIdx.x;
    int t = threadIdx.x;
    const float* base = x + (size_t)be * 1024 * 512 + g * 16 + (t & 3) * 4;
    float s = 0.f, sq = 0.f;
    #pragma unroll
    for (int it = 0; it < 16; ++it) {
        float4 v = *(const float4*)(base + (size_t)((t >> 2) + it * 64) * 512);
        s  += v.x + v.y + v.z + v.w;
        sq += v.x*v.x + v.y*v.y + v.z*v.z + v.w*v.w;
    }
    __shared__ float red[16];
    for (int o = 16; o > 0; o >>= 1) {
        s  += __shfl_down_sync(0xffffffffu, s,  o);
        sq += __shfl_down_sync(0xffffffffu, sq, o);
    }
    if ((t & 31) == 0) { red[t >> 5] = s; red[8 + (t >> 5)] = sq; }
    __syncthreads();
    if (t < 32) {
        s  = (t < 8) ? red[t]     : 0.f;
        sq = (t < 8) ? red[8 + t] : 0.f;
        for (int o = 4; o > 0; o >>= 1) {
            s  += __shfl_down_sync(0xffffffffu, s,  o);
            sq += __shfl_down_sync(0xffffffffu, sq, o);
        }
        if (t == 0) {
            float mean = s * (1.f/16384.f);
            float var  = sq * (1.f/16384.f) - mean * mean;
            stats[(be*32+g)*2]   = mean;
            stats[(be*32+g)*2+1] = rsqrtf(var + 1e-5f);
        }
    }
}

// ---------------- GN1 finish: src fp16 hi/lo only ----------------
__global__ void gn1_finish2(const float* __restrict__ pre, const float* __restrict__ stats,
    const float* __restrict__ gv, const float* __restrict__ bev,
    const float* __restrict__ gi, const float* __restrict__ bei,
    __half* __restrict__ sh, __half* __restrict__ sl)
{
    size_t e = ((size_t)blockIdx.x * 256 + threadIdx.x) * 4;
    int row = (int)(e >> 9), d = (int)(e & 511);
    int be = row >> 10, lvl = be & 1;
    float mean = stats[(be * 32 + (d >> 4)) * 2];
    float rstd = stats[(be * 32 + (d >> 4)) * 2 + 1];
    const float* gam = lvl ? gi : gv;
    const float* bet = lvl ? bei : bev;
    float4 v = *(const float4*)(pre + e);
    float vv[4] = {v.x, v.y, v.z, v.w};
    __half hh[4], ll[4];
    #pragma unroll
    for (int k = 0; k < 4; ++k) {
        float sv = (vv[k] - mean) * rstd * gam[d + k] + bet[d + k];
        splitH(sv, hh[k], ll[k]);
    }
    *(uint2*)(sh + e) = *(uint2*)hh;
    *(uint2*)(sl + e) = *(uint2*)ll;
}

// ---------------- deformable sampling (fused softmax), half2 loads ----------------
__global__ __launch_bounds__(256) void msda_sample(
    const __half* __restrict__ vproj, const float* __restrict__ oa,
    __half* __restrict__ msh, __half* __restrict__ msl)
{
    int bq = blockIdx.x;
    int b = bq >> 11;
    int hw = bq & 1023;
    float refx = ((hw & 31) + 0.5f) * (1.f/32.f);
    float refy = ((hw >> 5) + 0.5f) * (1.f/32.f);
    __shared__ float sx[64], sy[64], sw[64];
    int t = threadIdx.x;   // 256
    const float* row = oa + (size_t)bq * 256;
    if (t < 64) {
        sx[t] = (refx + row[t*2]   * (1.f/32.f)) * 32.f - 0.5f;
        sy[t] = (refy + row[t*2+1] * (1.f/32.f)) * 32.f - 0.5f;
        float lg = row[128 + t];
        float m = lg;
        #pragma unroll
        for (int o = 1; o < 8; o <<= 1) m = fmaxf(m, __shfl_xor_sync(0xffffffffu, m, o));
        float ex = expf(lg - m);
        float s = ex;
        #pragma unroll
        for (int o = 1; o < 8; o <<= 1) s += __shfl_xor_sync(0xffffffffu, s, o);
        sw[t] = ex / s;
    }
    __syncthreads();
    int head = t >> 5, c2 = t & 31;       // 8 heads x 32 half2-channels
    const __half2* vb = (const __half2*)(vproj + (size_t)b * LQQ * DD) + head * 32 + c2;
    float accx = 0.f, accy = 0.f;
    #pragma unroll
    for (int lp = 0; lp < 8; lp++) {
        int l = lp >> 2;
        float xs = sx[head*8+lp], ys = sy[head*8+lp], w = sw[head*8+lp];
        float x0f = floorf(xs), y0f = floorf(ys);
        float fx = xs - x0f, fy = ys - y0f;
        int x0 = (int)x0f, y0 = (int)y0f;
        const __half2* vl = vb + (size_t)l * HWW * 256;
        bool xa = (unsigned)x0 < 32u, xb = (unsigned)(x0+1) < 32u;
        bool ya = (unsigned)y0 < 32u, yb = (unsigned)(y0+1) < 32u;
        float2 z2 = make_float2(0.f, 0.f);
        float2 v00 = (ya && xa) ? __half22float2(vl[(size_t)(y0*32 + x0)      * 256]) : z2;
        float2 v01 = (ya && xb) ? __half22float2(vl[(size_t)(y0*32 + x0 + 1)  * 256]) : z2;
        float2 v10 = (yb && xa) ? __half22float2(vl[(size_t)(y0*32 + x0 + 32) * 256]) : z2;
        float2 v11 = (yb && xb) ? __half22float2(vl[(size_t)(y0*32 + x0 + 33) * 256]) : z2;
        float w00 = (1.f-fy)*(1.f-fx), w01 = (1.f-fy)*fx, w10 = fy*(1.f-fx), w11 = fy*fx;
        accx = fmaf(w, v00.x*w00 + v01.x*w01 + v10.x*w10 + v11.x*w11, accx);
        accy = fmaf(w, v00.y*w00 + v01.y*w01 + v10.y*w10 + v11.y*w11, accy);
    }
    __half hx, lx, hy, ly;
    splitH(accx, hx, lx); splitH(accy, hy, ly);
    ((__half2*)msh)[(size_t)bq * 256 + head * 32 + c2] = __halves2half2(hx, hy);
    ((__half2*)msl)[(size_t)bq * 256 + head * 32 + c2] = __halves2half2(lx, ly);
}

// ---------------- residual + LayerNorm -> cat fp16 (conv2 B layout) ----------------
__global__ void ln_res(const __half* __restrict__ srch, const __half* __restrict__ srcl,
                       const float* __restrict__ att,
                       const float* __restrict__ g, const float* __restrict__ be,
                       __half* __restrict__ cath)
{
    int grow = blockIdx.x;            // b*2048 + lvl*1024 + hw
    size_t base = (size_t)grow * DD;
    int t = threadIdx.x;              // 256
    float s0 = __half2float(srch[base + t])       + __half2float(srcl[base + t]);
    float s1 = __half2float(srch[base + t + 256]) + __half2float(srcl[base + t + 256]);
    float v0 = s0 + att[base + t];
    float v1 = s1 + att[base + t + 256];
    float s = v0 + v1, sq = v0*v0 + v1*v1;
    __shared__ float red[16];
    for (int o = 16; o > 0; o >>= 1) {
        s  += __shfl_down_sync(0xffffffffu, s,  o);
        sq += __shfl_down_sync(0xffffffffu, sq, o);
    }
    if ((t & 31) == 0) { red[t >> 5] = s; red[8 + (t >> 5)] = sq; }
    __syncthreads();
    if (t < 32) {
        s  = (t < 8) ? red[t]     : 0.f;
        sq = (t < 8) ? red[8 + t] : 0.f;
        for (int o = 4; o > 0; o >>= 1) {
            s  += __shfl_down_sync(0xffffffffu, s,  o);
            sq += __shfl_down_sync(0xffffffffu, sq, o);
        }
        if (t == 0) { red[0] = s; red[8] = sq; }
    }
    __syncthreads();
    float mu   = red[0] * (1.f/512.f);
    float var  = red[8] * (1.f/512.f) - mu * mu;
    float rstd = rsqrtf(var + 1e-5f);
    int b = grow >> 11, lvl = (grow >> 10) & 1, hw = grow & 1023;
    size_t obase = ((size_t)b * 1024 + hw) * 1024 + lvl * 512;
    cath[obase + t]       = __float2half_rn((v0 - mu) * rstd * g[t]       + be[t]);
    cath[obase + t + 256] = __float2half_rn((v1 - mu) * rstd * g[t + 256] + be[t + 256]);
}

// ---------------- GN stats: contiguous groups (conv2 output) ----------------
__global__ void gn_stats(const float* __restrict__ x, float* __restrict__ stats, int groupElems)
{
    int idx = blockIdx.y * gridDim.x + blockIdx.x;
    const float* p = x + (size_t)idx * groupElems;
    float s = 0.f, sq = 0.f;
    for (int i = threadIdx.x * 4; i < groupElems; i += blockDim.x * 4) {
        float4 v = *(const float4*)(p + i);
        s  += v.x + v.y + v.z + v.w;
        sq += v.x*v.x + v.y*v.y + v.z*v.z + v.w*v.w;
    }
    __shared__ float red[16];
    int t = threadIdx.x;
    for (int o = 16; o > 0; o >>= 1) {
        s  += __shfl_down_sync(0xffffffffu, s,  o);
        sq += __shfl_down_sync(0xffffffffu, sq, o);
    }
    if ((t & 31) == 0) { red[t >> 5] = s; red[8 + (t >> 5)] = sq; }
    __syncthreads();
    if (t < 32) {
        s  = (t < 8) ? red[t]     : 0.f;
        sq = (t < 8) ? red[8 + t] : 0.f;
        for (int o = 4; o > 0; o >>= 1) {
            s  += __shfl_down_sync(0xffffffffu, s,  o);
            sq += __shfl_down_sync(0xffffffffu, sq, o);
        }
        if (t == 0) {
            float inv = 1.f / (float)groupElems;
            float mean = s * inv;
            stats[idx*2]   = mean;
            stats[idx*2+1] = rsqrtf(sq * inv - mean * mean + 1e-5f);
        }
    }
}

__global__ void gn2_finish(const float* __restrict__ x, const float* __restrict__ stats,
    const float* __restrict__ gc, const float* __restrict__ bec, float* __restrict__ out)
{
    size_t i = (size_t)blockIdx.x * blockDim.x + threadIdx.x;
    int hwch = (int)(i >> 10);
    int ch = hwch % 768;
    int b  = hwch / 768;
    int g  = ch / 24;
    float mean = stats[(b*32 + g) * 2];
    float rstd = stats[(b*32 + g) * 2 + 1];
    out[i] = (x[i] - mean) * rstd * gc[ch] + bec[ch];
}

// ---------------- launcher ----------------
#define SYM(T, v, s) T v; cudaGetSymbolAddress((void**)&v, s)
extern "C" void kernel_launch(void* const* d_in, const int* in_sizes, int n_in,
                              void* d_out, int out_size)
{
    const float* input_v = (const float*)d_in[0];
    const float* input_i = (const float*)d_in[1];
    const float* wv      = (const float*)d_in[2];
    const float* bv      = (const float*)d_in[3];
    const float* gv      = (const float*)d_in[4];
    const float* bev     = (const float*)d_in[5];
    const float* wi      = (const float*)d_in[6];
    const float* bi      = (const float*)d_in[7];
    const float* gi      = (const float*)d_in[8];
    const float* bei     = (const float*)d_in[9];
    const float* le      = (const float*)d_in[10];
    const float* w_off   = (const float*)d_in[11];
    const float* b_off   = (const float*)d_in[12];
    const float* w_attn  = (const float*)d_in[13];
    const float* b_attn  = (const float*)d_in[14];
    const float* w_val   = (const float*)d_in[15];
    const float* b_val   = (const float*)d_in[16];
    const float* w_out   = (const float*)d_in[17];
    const float* b_out   = (const float*)d_in[18];
    const float* ln_g    = (const float*)d_in[19];
    const float* ln_b    = (const float*)d_in[20];
    const float* wc      = (const float*)d_in[21];
    const float* bc      = (const float*)d_in[22];
    const float* gc      = (const float*)d_in[23];
    const float* bec     = (const float*)d_in[24];

    SYM(__half*, xth,  g_xth);  SYM(__half*, xtl,  g_xtl);
    SYM(__half*, w1h,  g_w1h);
    SYM(__half*, wvalh,g_wvalh);
    SYM(__half*, wouth,g_wouth);
    SYM(__half*, woah, g_woah);
    SYM(__half*, wch,  g_wch_); SYM(__half*, wcl,  g_wcl_);
    SYM(__half*, srch, g_srch); SYM(__half*, srcl, g_srcl);
    SYM(__half*, msh,  g_msh);  SYM(__half*, msl,  g_msl);
    SYM(__half*, cath, g_cath); SYM(__half*, vph,  g_vph);
    SYM(float*, pre,   g_pre4);
    SYM(float*, oa,    g_oa4);
    SYM(float*, attno, g_attno4); SYM(float*, conv2, g_conv24);
    SYM(float*, lep,   g_lep);    SYM(float*, b1,    g_b1);
    SYM(float*, st1,   g_stats1); SYM(float*, st2,   g_stats2);
    size_t XT = (size_t)8192*768;

    cudaFuncSetAttribute(gemm_tc, cudaFuncAttributeMaxDynamicSharedMemorySize, GEMM_SMEM);

    // prep
    prep_weights<<<8708, 256>>>(wv, wi, w_val, w_out, w_off, w_attn, wc,
                                bv, bi, w1h, wvalh, wouth, woah, wch, wcl, b1);
    leproj_k<<<2, 256>>>(le, w_off, w_attn, b_off, b_attn, lep);
    prep_input<<<dim3(32, 24, BB), dim3(32, 8)>>>(input_v, xth, xtl);
    prep_input<<<dim3(32, 24, BB), dim3(32, 8)>>>(input_i, xth + XT, xtl + XT);

    // conv1 (v+i in one launch, z selects plane): D[8192,512] -> rows (b, lvl, hw)
    gemm_tc<<<dim3(4, 64, 2), 256, GEMM_SMEM>>>(xth, xtl, w1h, b1, pre,
        768, 0, 2048, 0, 512, (long)XT, 393216L, 512, 1024, 0);
    // GN1
    gn_stats_seq<<<dim3(32, 16), 256>>>(pre, st1);
    gn1_finish2<<<8192, 256>>>(pre, st1, gv, bev, gi, bei, srch, srcl);
    // projections (vproj fp16; oa with per-level lep bias — the level-embed trick)
    gemm_tc<<<dim3(4, 128), 256, GEMM_SMEM>>>(srch, srcl, wvalh, b_val, vph,
        512, 2, 1024, 0, 512, 0L, 0L, 0, 0, 0);
    gemm_tc<<<dim3(2, 128), 256, GEMM_SMEM>>>(srch, srcl, woah, lep, oa,
        512, 0, 1024, 0, 256, 0L, 0L, 0, 0, 256);
    // sampling (softmax fused)
    msda_sample<<<MROWS, 256>>>(vph, oa, msh, msl);
    // output projection
    gemm_tc<<<dim3(4, 128), 256, GEMM_SMEM>>>(msh, msl, wouth, b_out, attno,
        512, 0, 1024, 0, 512, 0L, 0L, 0, 0, 0);
    // residual + LN -> cat fp16
    ln_res<<<MROWS, 256>>>(srch, srcl, attno, ln_g, ln_b, cath);
    // conv2: D[768, 8192] -> (b, o, hw)
    gemm_tc<<<dim3(64, 6), 256, GEMM_SMEM>>>(wch, wcl, cath, bc, conv2,
        1024, 1, 0, 0, 768, 0L, 0L, 0, 0, 0);
    // final GN
    gn_stats<<<dim3(32, BB), 256>>>(conv2, st2, 24 * HWW);
    gn2_finish<<<24576, 256>>>(conv2, st2, gc, bec, (float*)d_out);
}

// round 10
// speedup vs baseline: 3.1217x; 1.0405x over previous
#include <cuda_runtime.h>
#include <cuda_fp16.h>
#include <cstdint>

#define BB   8
#define CC   768
#define DD   512
#define HWW  1024
#define LQQ  2048
#define MROWS (BB*LQQ)   // 16384

// ---------------- scratch (device globals) ----------------
__device__ uint4 g_xth [2][8192*768/8], g_xtl [2][8192*768/8];
__device__ uint4 g_w1h [2*512*768/8];                 // conv1 weights v|i
__device__ uint4 g_wvoa[768*512/8];                   // [w_val(512) ; w_oa(256)]
__device__ uint4 g_wouth[512*512/8];
__device__ uint4 g_wch_[768*1024/8], g_wcl_[768*1024/8];
__device__ uint4 g_srch[MROWS*512/8], g_srcl[MROWS*512/8];
__device__ uint4 g_msh[MROWS*512/8];
__device__ uint4 g_cath[8192*1024/8];
__device__ uint4 g_vph [MROWS*512/8];                 // vproj fp16
__device__ float4 g_pre4  [MROWS*512/4];
__device__ float4 g_oa4   [MROWS*256/4];
__device__ float4 g_attno4[MROWS*512/4];
__device__ float4 g_conv24[BB*CC*HWW/4];
__device__ float  g_lep  [512];                       // le@Woa^T + boa, [lvl][256]
__device__ float  g_b1   [1024];                      // conv1 bias v|i
__device__ float  g_stats1[BB*2*32*2];
__device__ float  g_stats2[BB*32*2];

// ---------------- PTX helpers (sm_80-compatible ISA only) ----------------
__device__ __forceinline__ uint32_t smem_u32(const void* p) {
    uint32_t a;
    asm("{ .reg .u64 t; cvta.to.shared.u64 t, %1; cvt.u32.u64 %0, t; }" : "=r"(a) : "l"(p));
    return a;
}
#define CP16(s, g) \
    asm volatile("cp.async.cg.shared.global [%0], [%1], 16;" :: "r"(s), "l"(g))
#define CP_COMMIT() asm volatile("cp.async.commit_group;" ::: "memory")
#define LDSM4(r, a) \
    asm volatile("ldmatrix.sync.aligned.m8n8.x4.shared.b16 {%0,%1,%2,%3}, [%4];" \
        : "=r"((r)[0]), "=r"((r)[1]), "=r"((r)[2]), "=r"((r)[3]) : "r"(a))
#define MMA16(c, a, b0, b1) \
    asm volatile("mma.sync.aligned.m16n8k16.row.col.f32.f16.f16.f32 " \
        "{%0,%1,%2,%3}, {%4,%5,%6,%7}, {%8,%9}, {%0,%1,%2,%3};" \
        : "+f"((c)[0]), "+f"((c)[1]), "+f"((c)[2]), "+f"((c)[3]) \
        : "r"((a)[0]), "r"((a)[1]), "r"((a)[2]), "r"((a)[3]), "r"(b0), "r"(b1))

__device__ __forceinline__ void splitH(float v, __half& h, __half& l) {
    h = __float2half_rn(v);
    l = __float2half_rn(v - __half2float(h));
}

// ============================================================================
// Split-fp16 HMMA GEMM (template NSPLIT = 1 or 2 A-planes).
// D[m,n] = sum_k A[m,k]*B[n,k]; 128x128 tiles, K chunk 32, 4-stage pipeline,
// one __syncthreads per chunk.
// mode 0: fp32 C[((m>>10)*mMul + mOff + m&1023)*ldC + n] + bias[n]
// mode 1: fp32 C[((n>>10)*ldC + m)*1024 + (n&1023)]      + bias[m]
// mode 2: fp16 C, row mapping of mode 0
// mode 3: dual: col<512 -> fp16 Cv (ld 512, bias[n]); col>=512 -> fp32 Cv2
//         (ld 256, bias2[lvl*256 + n-512]),  lvl = (m0>>10)&1
// ============================================================================
#define GEMM_SMEM 98304
template<int NSPLIT>
__global__ __launch_bounds__(256) void gemm_tc(
    const __half* __restrict__ Ah, const __half* __restrict__ Al,
    const __half* __restrict__ B,
    const float* __restrict__ bias, void* __restrict__ Cv,
    int K, int mode, int mMul, int mOff, int ldC,
    long zA, long zB, int zBias, int zOffMul, int biasLvl,
    void* __restrict__ Cv2, const float* __restrict__ bias2)
{
    extern __shared__ __align__(16) char smem[];
    const uint32_t sb = smem_u32(smem);
    const int tid = threadIdx.x;
    const int z = blockIdx.z;
    Ah += (size_t)z * zA; Al += (size_t)z * zA; B += (size_t)z * zB;
    const int m0 = blockIdx.y * 128, n0 = blockIdx.x * 128;
    bias += z * zBias + ((m0 >> 10) & 1) * biasLvl;
    const int mOffE = mOff + z * zOffMul;
    const int warp = tid >> 5, lane = tid & 31;
    const int wm = warp >> 1, wn = warp & 1;

    const int kg = tid & 3, r0 = tid >> 2;
    const int arow_l = lane & 15, akg_l = lane >> 4;
    const int nr = (lane & 7) + ((lane & 16) >> 1);
    const int bkg_l = (lane >> 3) & 1;

    float acc[2][8][4];
    #pragma unroll
    for (int i = 0; i < 2; ++i)
        #pragma unroll
        for (int j = 0; j < 8; ++j)
            #pragma unroll
            for (int k = 0; k < 4; ++k) acc[i][j][k] = 0.f;

    const int nC = K >> 5;

    auto load_stage = [&](int c) {
        const uint32_t stb = sb + (uint32_t)(c & 3) * 24576u;
        const int k0 = c << 5;
        #pragma unroll
        for (int h = 0; h < 2; ++h) {
            int row = r0 + h * 64;
            uint32_t so = (uint32_t)(row * 64 + ((kg ^ (row & 3)) << 4));
            size_t ga = (size_t)(m0 + row) * K + k0 + kg * 8;
            size_t gb = (size_t)(n0 + row) * K + k0 + kg * 8;
            CP16(stb +         so, Ah + ga);
            if (NSPLIT == 2) CP16(stb + 8192 + so, Al + ga);
            CP16(stb + 16384 + so, B  + gb);
        }
        CP_COMMIT();
    };

    load_stage(0); load_stage(1); load_stage(2);
    for (int c = 0; c < nC; ++c) {
        int rem = nC - c;
        if (rem >= 3)      asm volatile("cp.async.wait_group 2;" ::: "memory");
        else if (rem == 2) asm volatile("cp.async.wait_group 1;" ::: "memory");
        else               asm volatile("cp.async.wait_group 0;" ::: "memory");
        __syncthreads();
        if (c + 3 < nC) load_stage(c + 3);
        const uint32_t stb = sb + (uint32_t)(c & 3) * 24576u;
        #pragma unroll
        for (int kk = 0; kk < 2; ++kk) {
            uint32_t ah[2][4], al[2][4];
            #pragma unroll
            for (int mf = 0; mf < 2; ++mf) {
                int arow = wm * 32 + mf * 16 + arow_l;
                uint32_t ad = stb + (uint32_t)(arow * 64 +
                              ((((kk << 1) + akg_l) ^ (arow_l & 3)) << 4));
                LDSM4(ah[mf], ad);
                if (NSPLIT == 2) LDSM4(al[mf], ad + 8192);
            }
            #pragma unroll
            for (int np = 0; np < 4; ++np) {
                int brow = wn * 64 + np * 16 + nr;
                uint32_t bd = stb + 16384u + (uint32_t)(brow * 64 +
                              ((((kk << 1) + bkg_l) ^ (nr & 3)) << 4));
                uint32_t bh[4];
                LDSM4(bh, bd);
                #pragma unroll
                for (int half = 0; half < 2; ++half) {
                    uint32_t b0 = bh[half*2], b1 = bh[half*2+1];
                    int nj = np * 2 + half;
                    #pragma unroll
                    for (int mf = 0; mf < 2; ++mf) {
                        MMA16(acc[mf][nj], ah[mf], b0, b1);
                        if (NSPLIT == 2) MMA16(acc[mf][nj], al[mf], b0, b1);
                    }
                }
            }
        }
    }

    // ---- epilogue ----
    const int tq = lane >> 2, tr2 = (lane & 3) * 2;
    const int lvlB = ((m0 >> 10) & 1) * 256;
    #pragma unroll
    for (int mf = 0; mf < 2; ++mf) {
        #pragma unroll
        for (int nj = 0; nj < 8; ++nj) {
            int mrow = m0 + wm * 32 + mf * 16 + tq;
            int col  = n0 + wn * 64 + nj * 8 + tr2;
            float* a0 = acc[mf][nj];
            if (mode == 1) {
                float* C = (float*)Cv;
                float bm0 = bias[mrow], bm1 = bias[mrow + 8];
                size_t base = ((size_t)((col >> 10) * ldC)) * 1024 + (col & 1023);
                *(float2*)(C + base + (size_t)mrow       * 1024) = make_float2(a0[0] + bm0, a0[1] + bm0);
                *(float2*)(C + base + (size_t)(mrow + 8) * 1024) = make_float2(a0[2] + bm1, a0[3] + bm1);
            } else if (mode == 3) {
                int rp0 = mrow, rp1 = mrow + 8;
                if (col < 512) {
                    __half* C = (__half*)Cv;
                    float b0 = bias[col], b1 = bias[col + 1];
                    *(__half2*)(C + (size_t)rp0 * 512 + col) =
                        __floats2half2_rn(a0[0] + b0, a0[1] + b1);
                    *(__half2*)(C + (size_t)rp1 * 512 + col) =
                        __floats2half2_rn(a0[2] + b0, a0[3] + b1);
                } else {
                    float* C = (float*)Cv2;
                    int cc = col - 512;
                    float b0 = bias2[lvlB + cc], b1 = bias2[lvlB + cc + 1];
                    *(float2*)(C + (size_t)rp0 * 256 + cc) = make_float2(a0[0] + b0, a0[1] + b1);
                    *(float2*)(C + (size_t)rp1 * 256 + cc) = make_float2(a0[2] + b0, a0[3] + b1);
                }
            } else {
                float b0 = bias[col], b1 = bias[col + 1];
                int rp0 = (mrow >> 10) * mMul + mOffE + (mrow & 1023);
                int m2 = mrow + 8;
                int rp1 = (m2 >> 10) * mMul + mOffE + (m2 & 1023);
                if (mode == 0) {
                    float* C = (float*)Cv;
                    *(float2*)(C + (size_t)rp0 * ldC + col) = make_float2(a0[0] + b0, a0[1] + b1);
                    *(float2*)(C + (size_t)rp1 * ldC + col) = make_float2(a0[2] + b0, a0[3] + b1);
                } else {
                    __half* C = (__half*)Cv;
                    *(__half2*)(C + (size_t)rp0 * ldC + col) =
                        __floats2half2_rn(a0[0] + b0, a0[1] + b1);
                    *(__half2*)(C + (size_t)rp1 * ldC + col) =
                        __floats2half2_rn(a0[2] + b0, a0[3] + b1);
                }
            }
        }
    }
}

// ---------------- prep: transpose (b,c,hw)->(b*hw,c) + fp16 split ----------------
__global__ void prep_input(const float* __restrict__ in,
                           __half* __restrict__ xh, __half* __restrict__ xl)
{
    __shared__ float tl[32][33];
    int b = blockIdx.z, c0 = blockIdx.y * 32, hw0 = blockIdx.x * 32;
    const float* ip = in + ((size_t)b * CC + c0) * HWW + hw0;
    #pragma unroll
    for (int j = 0; j < 4; ++j)
        tl[threadIdx.y + j*8][threadIdx.x] = ip[(size_t)(threadIdx.y + j*8) * HWW + threadIdx.x];
    __syncthreads();
    #pragma unroll
    for (int j = 0; j < 4; ++j) {
        int hw = hw0 + threadIdx.y + j*8;
        int cc = c0 + threadIdx.x;
        __half h, l; splitH(tl[threadIdx.x][threadIdx.y + j*8], h, l);
        size_t o = ((size_t)b * HWW + hw) * CC + cc;
        xh[o] = h; xl[o] = l;
    }
}

// ---------------- one-shot weight prep ----------------
__global__ void prep_weights(
    const float* __restrict__ wv,    const float* __restrict__ wi,
    const float* __restrict__ w_val, const float* __restrict__ w_out,
    const float* __restrict__ w_off, const float* __restrict__ w_attn,
    const float* __restrict__ wc,
    const float* __restrict__ bv,    const float* __restrict__ bi,
    __half* __restrict__ w1h,  __half* __restrict__ wvoa,
    __half* __restrict__ wouth,
    __half* __restrict__ wch,  __half* __restrict__ wcl,
    float* __restrict__ b1)
{
    int i = blockIdx.x * 256 + threadIdx.x;
    if (i < 786432) {
        w1h[i] = __float2half_rn(i < 393216 ? wv[i] : wi[i - 393216]);
    } else if (i < 1179648) {
        int j = i - 786432;                // 0..393215, combined [w_val ; w_oa]
        int r = j >> 9, c = j & 511;
        float v;
        if (r < 512) v = w_val[r * 512 + c];
        else {
            int rr = r - 512;
            v = (rr < 128) ? w_off[rr * 512 + c] : ((rr < 192) ? w_attn[(rr - 128) * 512 + c] : 0.f);
        }
        wvoa[j] = __float2half_rn(v);
    } else if (i < 1441792) {
        int j = i - 1179648;
        wouth[j] = __float2half_rn(w_out[j]);
    } else if (i < 2228224) {
        int j = i - 1441792;               // 0..786431
        __half h, l; splitH(wc[j], h, l);
        wch[j] = h; wcl[j] = l;
    } else if (i < 2229248) {
        int j = i - 2228224;
        b1[j] = (j < 512) ? bv[j] : bi[j - 512];
    }
}

// ---------------- lep[lvl][n] = le[lvl] . Woa[n] + boa[n]  (fp32, exact) -------
__global__ void leproj_k(const float* __restrict__ le,
                         const float* __restrict__ w_off, const float* __restrict__ w_attn,
                         const float* __restrict__ b_off, const float* __restrict__ b_attn,
                         float* __restrict__ lep)
{
    int lvl = blockIdx.x, n = threadIdx.x;   // 2 x 256
    const float* l = le + lvl * 512;
    float s = 0.f;
    if (n < 128) {
        s = b_off[n];
        const float* w = w_off + n * 512;
        for (int d = 0; d < 512; ++d) s = fmaf(l[d], w[d], s);
    } else if (n < 192) {
        s = b_attn[n - 128];
        const float* w = w_attn + (n - 128) * 512;
        for (int d = 0; d < 512; ++d) s = fmaf(l[d], w[d], s);
    }
    lep[lvl * 256 + n] = s;
}

// ---------------- GN stats over seq-major (rows=(be,hw), 512 ch); group=16 ch ----------------
__global__ void gn_stats_seq(const float* __restrict__ x, float* __restrict__ stats)
{
    int be = blockIdx.y, g = blockIdx.x;
    int t = threadIdx.x;
    const float* base = x + (size_t)be * 1024 * 512 + g * 16 + (t & 3) * 4;
    float s = 0.f, sq = 0.f;
    #pragma unroll
    for (int it = 0; it < 16; ++it) {
        float4 v = *(const float4*)(base + (size_t)((t >> 2) + it * 64) * 512);
        s  += v.x + v.y + v.z + v.w;
        sq += v.x*v.x + v.y*v.y + v.z*v.z + v.w*v.w;
    }
    __shared__ float red[16];
    for (int o = 16; o > 0; o >>= 1) {
        s  += __shfl_down_sync(0xffffffffu, s,  o);
        sq += __shfl_down_sync(0xffffffffu, sq, o);
    }
    if ((t & 31) == 0) { red[t >> 5] = s; red[8 + (t >> 5)] = sq; }
    __syncthreads();
    if (t < 32) {
        s  = (t < 8) ? red[t]     : 0.f;
        sq = (t < 8) ? red[8 + t] : 0.f;
        for (int o = 4; o > 0; o >>= 1) {
            s  += __shfl_down_sync(0xffffffffu, s,  o);
            sq += __shfl_down_sync(0xffffffffu, sq, o);
        }
        if (t == 0) {
            float mean = s * (1.f/16384.f);
            float var  = sq * (1.f/16384.f) - mean * mean;
            stats[(be*32+g)*2]   = mean;
            stats[(be*32+g)*2+1] = rsqrtf(var + 1e-5f);
        }
    }
}

// ---------------- GN1 finish: src fp16 hi/lo ----------------
__global__ void gn1_finish2(const float* __restrict__ pre, const float* __restrict__ stats,
    const float* __restrict__ gv, const float* __restrict__ bev,
    const float* __restrict__ gi, const float* __restrict__ bei,
    __half* __restrict__ sh, __half* __restrict__ sl)
{
    size_t e = ((size_t)blockIdx.x * 256 + threadIdx.x) * 4;
    int row = (int)(e >> 9), d = (int)(e & 511);
    int be = row >> 10, lvl = be & 1;
    float mean = stats[(be * 32 + (d >> 4)) * 2];
    float rstd = stats[(be * 32 + (d >> 4)) * 2 + 1];
    const float* gam = lvl ? gi : gv;
    const float* bet = lvl ? bei : bev;
    float4 v = *(const float4*)(pre + e);
    float vv[4] = {v.x, v.y, v.z, v.w};
    __half hh[4], ll[4];
    #pragma unroll
    for (int k = 0; k < 4; ++k) {
        float sv = (vv[k] - mean) * rstd * gam[d + k] + bet[d + k];
        splitH(sv, hh[k], ll[k]);
    }
    *(uint2*)(sh + e) = *(uint2*)hh;
    *(uint2*)(sl + e) = *(uint2*)ll;
}

// ---------------- deformable sampling (fused softmax), half2 loads, single out ----
__global__ __launch_bounds__(256) void msda_sample(
    const __half* __restrict__ vproj, const float* __restrict__ oa,
    __half* __restrict__ msh)
{
    int bq = blockIdx.x;
    int b = bq >> 11;
    int hw = bq & 1023;
    float refx = ((hw & 31) + 0.5f) * (1.f/32.f);
    float refy = ((hw >> 5) + 0.5f) * (1.f/32.f);
    __shared__ float sx[64], sy[64], sw[64];
    int t = threadIdx.x;   // 256
    const float* row = oa + (size_t)bq * 256;
    if (t < 64) {
        sx[t] = (refx + row[t*2]   * (1.f/32.f)) * 32.f - 0.5f;
        sy[t] = (refy + row[t*2+1] * (1.f/32.f)) * 32.f - 0.5f;
        float lg = row[128 + t];
        float m = lg;
        #pragma unroll
        for (int o = 1; o < 8; o <<= 1) m = fmaxf(m, __shfl_xor_sync(0xffffffffu, m, o));
        float ex = expf(lg - m);
        float s = ex;
        #pragma unroll
        for (int o = 1; o < 8; o <<= 1) s += __shfl_xor_sync(0xffffffffu, s, o);
        sw[t] = ex / s;
    }
    __syncthreads();
    int head = t >> 5, c2 = t & 31;       // 8 heads x 32 half2-channels
    const __half2* vb = (const __half2*)(vproj + (size_t)b * LQQ * DD) + head * 32 + c2;
    float accx = 0.f, accy = 0.f;
    #pragma unroll
    for (int lp = 0; lp < 8; lp++) {
        int l = lp >> 2;
        float xs = sx[head*8+lp], ys = sy[head*8+lp], w = sw[head*8+lp];
        float x0f = floorf(xs), y0f = floorf(ys);
        float fx = xs - x0f, fy = ys - y0f;
        int x0 = (int)x0f, y0 = (int)y0f;
        const __half2* vl = vb + (size_t)l * HWW * 256;
        bool xa = (unsigned)x0 < 32u, xb = (unsigned)(x0+1) < 32u;
        bool ya = (unsigned)y0 < 32u, yb = (unsigned)(y0+1) < 32u;
        float2 z2 = make_float2(0.f, 0.f);
        float2 v00 = (ya && xa) ? __half22float2(vl[(size_t)(y0*32 + x0)      * 256]) : z2;
        float2 v01 = (ya && xb) ? __half22float2(vl[(size_t)(y0*32 + x0 + 1)  * 256]) : z2;
        float2 v10 = (yb && xa) ? __half22float2(vl[(size_t)(y0*32 + x0 + 32) * 256]) : z2;
        float2 v11 = (yb && xb) ? __half22float2(vl[(size_t)(y0*32 + x0 + 33) * 256]) : z2;
        float w00 = (1.f-fy)*(1.f-fx), w01 = (1.f-fy)*fx, w10 = fy*(1.f-fx), w11 = fy*fx;
        accx = fmaf(w, v00.x*w00 + v01.x*w01 + v10.x*w10 + v11.x*w11, accx);
        accy = fmaf(w, v00.y*w00 + v01.y*w01 + v10.y*w10 + v11.y*w11, accy);
    }
    ((__half2*)msh)[(size_t)bq * 256 + head * 32 + c2] = __floats2half2_rn(accx, accy);
}

// ---------------- residual + LayerNorm -> cat fp16 (conv2 B layout) ----------------
__global__ void ln_res(const __half* __restrict__ srch, const __half* __restrict__ srcl,
                       const float* __restrict__ att,
                       const float* __restrict__ g, const float* __restrict__ be,
                       __half* __restrict__ cath)
{
    int grow = blockIdx.x;            // b*2048 + lvl*1024 + hw
    size_t base = (size_t)grow * DD;
    int t = threadIdx.x;              // 256
    float s0 = __half2float(srch[base + t])       + __half2float(srcl[base + t]);
    float s1 = __half2float(srch[base + t + 256]) + __half2float(srcl[base + t + 256]);
    float v0 = s0 + att[base + t];
    float v1 = s1 + att[base + t + 256];
    float s = v0 + v1, sq = v0*v0 + v1*v1;
    __shared__ float red[16];
    for (int o = 16; o > 0; o >>= 1) {
        s  += __shfl_down_sync(0xffffffffu, s,  o);
        sq += __shfl_down_sync(0xffffffffu, sq, o);
    }
    if ((t & 31) == 0) { red[t >> 5] = s; red[8 + (t >> 5)] = sq; }
    __syncthreads();
    if (t < 32) {
        s  = (t < 8) ? red[t]     : 0.f;
        sq = (t < 8) ? red[8 + t] : 0.f;
        for (int o = 4; o > 0; o >>= 1) {
            s  += __shfl_down_sync(0xffffffffu, s,  o);
            sq += __shfl_down_sync(0xffffffffu, sq, o);
        }
        if (t == 0) { red[0] = s; red[8] = sq; }
    }
    __syncthreads();
    float mu   = red[0] * (1.f/512.f);
    float var  = red[8] * (1.f/512.f) - mu * mu;
    float rstd = rsqrtf(var + 1e-5f);
    int b = grow >> 11, lvl = (grow >> 10) & 1, hw = grow & 1023;
    size_t obase = ((size_t)b * 1024 + hw) * 1024 + lvl * 512;
    cath[obase + t]       = __float2half_rn((v0 - mu) * rstd * g[t]       + be[t]);
    cath[obase + t + 256] = __float2half_rn((v1 - mu) * rstd * g[t + 256] + be[t + 256]);
}

// ---------------- GN stats: contiguous groups (conv2 output) ----------------
__global__ void gn_stats(const float* __restrict__ x, float* __restrict__ stats, int groupElems)
{
    int idx = blockIdx.y * gridDim.x + blockIdx.x;
    const float* p = x + (size_t)idx * groupElems;
    float s = 0.f, sq = 0.f;
    for (int i = threadIdx.x * 4; i < groupElems; i += blockDim.x * 4) {
        float4 v = *(const float4*)(p + i);
        s  += v.x + v.y + v.z + v.w;
        sq += v.x*v.x + v.y*v.y + v.z*v.z + v.w*v.w;
    }
    __shared__ float red[16];
    int t = threadIdx.x;
    for (int o = 16; o > 0; o >>= 1) {
        s  += __shfl_down_sync(0xffffffffu, s,  o);
        sq += __shfl_down_sync(0xffffffffu, sq, o);
    }
    if ((t & 31) == 0) { red[t >> 5] = s; red[8 + (t >> 5)] = sq; }
    __syncthreads();
    if (t < 32) {
        s  = (t < 8) ? red[t]     : 0.f;
        sq = (t < 8) ? red[8 + t] : 0.f;
        for (int o = 4; o > 0; o >>= 1) {
            s  += __shfl_down_sync(0xffffffffu, s,  o);
            sq += __shfl_down_sync(0xffffffffu, sq, o);
        }
        if (t == 0) {
            float inv = 1.f / (float)groupElems;
            float mean = s * inv;
            stats[idx*2]   = mean;
            stats[idx*2+1] = rsqrtf(sq * inv - mean * mean + 1e-5f);
        }
    }
}

__global__ void gn2_finish(const float* __restrict__ x, const float* __restrict__ stats,
    const float* __restrict__ gc, const float* __restrict__ bec, float* __restrict__ out)
{
    size_t i = (size_t)blockIdx.x * blockDim.x + threadIdx.x;
    int hwch = (int)(i >> 10);
    int ch = hwch % 768;
    int b  = hwch / 768;
    int g  = ch / 24;
    float mean = stats[(b*32 + g) * 2];
    float rstd = stats[(b*32 + g) * 2 + 1];
    out[i] = (x[i] - mean) * rstd * gc[ch] + bec[ch];
}

// ---------------- launcher ----------------
#define SYM(T, v, s) T v; cudaGetSymbolAddress((void**)&v, s)
extern "C" void kernel_launch(void* const* d_in, const int* in_sizes, int n_in,
                              void* d_out, int out_size)
{
    const float* input_v = (const float*)d_in[0];
    const float* input_i = (const float*)d_in[1];
    const float* wv      = (const float*)d_in[2];
    const float* bv      = (const float*)d_in[3];
    const float* gv      = (const float*)d_in[4];
    const float* bev     = (const float*)d_in[5];
    const float* wi      = (const float*)d_in[6];
    const float* bi      = (const float*)d_in[7];
    const float* gi      = (const float*)d_in[8];
    const float* bei     = (const float*)d_in[9];
    const float* le      = (const float*)d_in[10];
    const float* w_off   = (const float*)d_in[11];
    const float* b_off   = (const float*)d_in[12];
    const float* w_attn  = (const float*)d_in[13];
    const float* b_attn  = (const float*)d_in[14];
    const float* w_val   = (const float*)d_in[15];
    const float* b_val   = (const float*)d_in[16];
    const float* w_out   = (const float*)d_in[17];
    const float* b_out   = (const float*)d_in[18];
    const float* ln_g    = (const float*)d_in[19];
    const float* ln_b    = (const float*)d_in[20];
    const float* wc      = (const float*)d_in[21];
    const float* bc      = (const float*)d_in[22];
    const float* gc      = (const float*)d_in[23];
    const float* bec     = (const float*)d_in[24];

    SYM(__half*, xth,  g_xth);  SYM(__half*, xtl,  g_xtl);
    SYM(__half*, w1h,  g_w1h);  SYM(__half*, wvoa, g_wvoa);
    SYM(__half*, wouth,g_wouth);
    SYM(__half*, wch,  g_wch_); SYM(__half*, wcl,  g_wcl_);
    SYM(__half*, srch, g_srch); SYM(__half*, srcl, g_srcl);
    SYM(__half*, msh,  g_msh);
    SYM(__half*, cath, g_cath); SYM(__half*, vph,  g_vph);
    SYM(float*, pre,   g_pre4);
    SYM(float*, oa,    g_oa4);
    SYM(float*, attno, g_attno4); SYM(float*, conv2, g_conv24);
    SYM(float*, lep,   g_lep);    SYM(float*, b1,    g_b1);
    SYM(float*, st1,   g_stats1); SYM(float*, st2,   g_stats2);
    size_t XT = (size_t)8192*768;

    cudaFuncSetAttribute(gemm_tc<1>, cudaFuncAttributeMaxDynamicSharedMemorySize, GEMM_SMEM);
    cudaFuncSetAttribute(gemm_tc<2>, cudaFuncAttributeMaxDynamicSharedMemorySize, GEMM_SMEM);

    // prep
    prep_weights<<<8708, 256>>>(wv, wi, w_val, w_out, w_off, w_attn, wc,
                                bv, bi, w1h, wvoa, wouth, wch, wcl, b1);
    leproj_k<<<2, 256>>>(le, w_off, w_attn, b_off, b_attn, lep);
    prep_input<<<dim3(32, 24, BB), dim3(32, 8)>>>(input_v, xth, xtl);
    prep_input<<<dim3(32, 24, BB), dim3(32, 8)>>>(input_i, xth + XT, xtl + XT);

    // conv1 (v+i, z planes): D[8192,512] -> rows (b, lvl, hw)  [2-split]
    gemm_tc<2><<<dim3(4, 64, 2), 256, GEMM_SMEM>>>(xth, xtl, w1h, b1, pre,
        768, 0, 2048, 0, 512, (long)XT, 393216L, 512, 1024, 0, nullptr, nullptr);
    // GN1
    gn_stats_seq<<<dim3(32, 16), 256>>>(pre, st1);
    gn1_finish2<<<8192, 256>>>(pre, st1, gv, bev, gi, bei, srch, srcl);
    // fused vproj+oa projection [1-split, dual output]
    gemm_tc<1><<<dim3(6, 128), 256, GEMM_SMEM>>>(srch, srch, wvoa, b_val, vph,
        512, 3, 1024, 0, 512, 0L, 0L, 0, 0, 0, oa, lep);
    // sampling (softmax fused)
    msda_sample<<<MROWS, 256>>>(vph, oa, msh);
    // output projection [1-split]
    gemm_tc<1><<<dim3(4, 128), 256, GEMM_SMEM>>>(msh, msh, wouth, b_out, attno,
        512, 0, 1024, 0, 512, 0L, 0L, 0, 0, 0, nullptr, nullptr);
    // residual + LN -> cat fp16
    ln_res<<<MROWS, 256>>>(srch, srcl, attno, ln_g, ln_b, cath);
    // conv2: D[768, 8192] -> (b, o, hw)  [2-split]
    gemm_tc<2><<<dim3(64, 6), 256, GEMM_SMEM>>>(wch, wcl, cath, bc, conv2,
        1024, 1, 0, 0, 768, 0L, 0L, 0, 0, 0, nullptr, nullptr);
    // final GN
    gn_stats<<<dim3(32, BB), 256>>>(conv2, st2, 24 * HWW);
    gn2_finish<<<24576, 256>>>(conv2, st2, gc, bec, (float*)d_out);
}

// round 11
// speedup vs baseline: 3.7137x; 1.1896x over previous
#include <cuda_runtime.h>
#include <cuda_fp16.h>
#include <cstdint>

#define BB   8
#define CC   768
#define DD   512
#define HWW  1024
#define LQQ  2048
#define MROWS (BB*LQQ)   // 16384

// ---------------- scratch (device globals) ----------------
__device__ uint4 g_xth [2][8192*768/8];
__device__ uint4 g_w1h [2*512*768/8];                 // conv1 weights v|i
__device__ uint4 g_wvoa[768*512/8];                   // [w_val(512) ; w_oa(256)]
__device__ uint4 g_wouth[512*512/8];
__device__ uint4 g_wch_[768*1024/8];
__device__ uint4 g_srch[MROWS*512/8], g_srcl[MROWS*512/8];
__device__ uint4 g_msh[MROWS*512/8];
__device__ uint4 g_cath[8192*1024/8];
__device__ uint4 g_vph [MROWS*512/8];                 // vproj fp16
__device__ uint4 g_attnoh[MROWS*512/8];               // attn out fp16
__device__ float4 g_pre4  [MROWS*512/4];
__device__ float4 g_oa4   [MROWS*256/4];
__device__ float4 g_conv24[BB*CC*HWW/4];
__device__ float  g_lep  [512];                       // le@Woa^T + boa, [lvl][256]
__device__ float  g_b1   [1024];                      // conv1 bias v|i
__device__ float  g_stats1[BB*2*32*2];
__device__ float  g_stats2[BB*32*2];

// ---------------- PTX helpers (sm_80-compatible ISA only) ----------------
__device__ __forceinline__ uint32_t smem_u32(const void* p) {
    uint32_t a;
    asm("{ .reg .u64 t; cvta.to.shared.u64 t, %1; cvt.u32.u64 %0, t; }" : "=r"(a) : "l"(p));
    return a;
}
#define CP16(s, g) \
    asm volatile("cp.async.cg.shared.global [%0], [%1], 16;" :: "r"(s), "l"(g))
#define CP_COMMIT() asm volatile("cp.async.commit_group;" ::: "memory")
#define LDSM4(r, a) \
    asm volatile("ldmatrix.sync.aligned.m8n8.x4.shared.b16 {%0,%1,%2,%3}, [%4];" \
        : "=r"((r)[0]), "=r"((r)[1]), "=r"((r)[2]), "=r"((r)[3]) : "r"(a))
#define MMA16(c, a, b0, b1) \
    asm volatile("mma.sync.aligned.m16n8k16.row.col.f32.f16.f16.f32 " \
        "{%0,%1,%2,%3}, {%4,%5,%6,%7}, {%8,%9}, {%0,%1,%2,%3};" \
        : "+f"((c)[0]), "+f"((c)[1]), "+f"((c)[2]), "+f"((c)[3]) \
        : "r"((a)[0]), "r"((a)[1]), "r"((a)[2]), "r"((a)[3]), "r"(b0), "r"(b1))

__device__ __forceinline__ void splitH(float v, __half& h, __half& l) {
    h = __float2half_rn(v);
    l = __float2half_rn(v - __half2float(h));
}

// ============================================================================
// Split-fp16 HMMA GEMM (template NSPLIT = 1 or 2 A-planes).
// D[m,n] = sum_k A[m,k]*B[n,k]; 128x128 tiles, K chunk 32, 4-stage pipeline,
// one __syncthreads per chunk.
// mode 0: fp32 C[((m>>10)*mMul + mOff + m&1023)*ldC + n] + bias[n]
// mode 1: fp32 C[((n>>10)*ldC + m)*1024 + (n&1023)]      + bias[m]
// mode 2: fp16 C, row mapping of mode 0
// mode 3: dual: col<512 -> fp16 Cv (ld 512, bias[n]); col>=512 -> fp32 Cv2
//         (ld 256, bias2[lvl*256 + n-512]),  lvl = (m0>>10)&1
// ============================================================================
#define GEMM_SMEM 98304
template<int NSPLIT>
__global__ __launch_bounds__(256) void gemm_tc(
    const __half* __restrict__ Ah, const __half* __restrict__ Al,
    const __half* __restrict__ B,
    const float* __restrict__ bias, void* __restrict__ Cv,
    int K, int mode, int mMul, int mOff, int ldC,
    long zA, long zB, int zBias, int zOffMul, int biasLvl,
    void* __restrict__ Cv2, const float* __restrict__ bias2)
{
    extern __shared__ __align__(16) char smem[];
    const uint32_t sb = smem_u32(smem);
    const int tid = threadIdx.x;
    const int z = blockIdx.z;
    Ah += (size_t)z * zA; Al += (size_t)z * zA; B += (size_t)z * zB;
    const int m0 = blockIdx.y * 128, n0 = blockIdx.x * 128;
    bias += z * zBias + ((m0 >> 10) & 1) * biasLvl;
    const int mOffE = mOff + z * zOffMul;
    const int warp = tid >> 5, lane = tid & 31;
    const int wm = warp >> 1, wn = warp & 1;

    const int kg = tid & 3, r0 = tid >> 2;
    const int arow_l = lane & 15, akg_l = lane >> 4;
    const int nr = (lane & 7) + ((lane & 16) >> 1);
    const int bkg_l = (lane >> 3) & 1;

    float acc[2][8][4];
    #pragma unroll
    for (int i = 0; i < 2; ++i)
        #pragma unroll
        for (int j = 0; j < 8; ++j)
            #pragma unroll
            for (int k = 0; k < 4; ++k) acc[i][j][k] = 0.f;

    const int nC = K >> 5;

    auto load_stage = [&](int c) {
        const uint32_t stb = sb + (uint32_t)(c & 3) * 24576u;
        const int k0 = c << 5;
        #pragma unroll
        for (int h = 0; h < 2; ++h) {
            int row = r0 + h * 64;
            uint32_t so = (uint32_t)(row * 64 + ((kg ^ (row & 3)) << 4));
            size_t ga = (size_t)(m0 + row) * K + k0 + kg * 8;
            size_t gb = (size_t)(n0 + row) * K + k0 + kg * 8;
            CP16(stb +         so, Ah + ga);
            if (NSPLIT == 2) CP16(stb + 8192 + so, Al + ga);
            CP16(stb + 16384 + so, B  + gb);
        }
        CP_COMMIT();
    };

    load_stage(0); load_stage(1); load_stage(2);
    for (int c = 0; c < nC; ++c) {
        int rem = nC - c;
        if (rem >= 3)      asm volatile("cp.async.wait_group 2;" ::: "memory");
        else if (rem == 2) asm volatile("cp.async.wait_group 1;" ::: "memory");
        else               asm volatile("cp.async.wait_group 0;" ::: "memory");
        __syncthreads();
        if (c + 3 < nC) load_stage(c + 3);
        const uint32_t stb = sb + (uint32_t)(c & 3) * 24576u;
        #pragma unroll
        for (int kk = 0; kk < 2; ++kk) {
            uint32_t ah[2][4], al[2][4];
            #pragma unroll
            for (int mf = 0; mf < 2; ++mf) {
                int arow = wm * 32 + mf * 16 + arow_l;
                uint32_t ad = stb + (uint32_t)(arow * 64 +
                              ((((kk << 1) + akg_l) ^ (arow_l & 3)) << 4));
                LDSM4(ah[mf], ad);
                if (NSPLIT == 2) LDSM4(al[mf], ad + 8192);
            }
            #pragma unroll
            for (int np = 0; np < 4; ++np) {
                int brow = wn * 64 + np * 16 + nr;
                uint32_t bd = stb + 16384u + (uint32_t)(brow * 64 +
                              ((((kk << 1) + bkg_l) ^ (nr & 3)) << 4));
                uint32_t bh[4];
                LDSM4(bh, bd);
                #pragma unroll
                for (int half = 0; half < 2; ++half) {
                    uint32_t b0 = bh[half*2], b1 = bh[half*2+1];
                    int nj = np * 2 + half;
                    #pragma unroll
                    for (int mf = 0; mf < 2; ++mf) {
                        MMA16(acc[mf][nj], ah[mf], b0, b1);
                        if (NSPLIT == 2) MMA16(acc[mf][nj], al[mf], b0, b1);
                    }
                }
            }
        }
    }

    // ---- epilogue ----
    const int tq = lane >> 2, tr2 = (lane & 3) * 2;
    const int lvlB = ((m0 >> 10) & 1) * 256;
    #pragma unroll
    for (int mf = 0; mf < 2; ++mf) {
        #pragma unroll
        for (int nj = 0; nj < 8; ++nj) {
            int mrow = m0 + wm * 32 + mf * 16 + tq;
            int col  = n0 + wn * 64 + nj * 8 + tr2;
            float* a0 = acc[mf][nj];
            if (mode == 1) {
                float* C = (float*)Cv;
                float bm0 = bias[mrow], bm1 = bias[mrow + 8];
                size_t base = ((size_t)((col >> 10) * ldC)) * 1024 + (col & 1023);
                *(float2*)(C + base + (size_t)mrow       * 1024) = make_float2(a0[0] + bm0, a0[1] + bm0);
                *(float2*)(C + base + (size_t)(mrow + 8) * 1024) = make_float2(a0[2] + bm1, a0[3] + bm1);
            } else if (mode == 3) {
                int rp0 = mrow, rp1 = mrow + 8;
                if (col < 512) {
                    __half* C = (__half*)Cv;
                    float b0 = bias[col], b1 = bias[col + 1];
                    *(__half2*)(C + (size_t)rp0 * 512 + col) =
                        __floats2half2_rn(a0[0] + b0, a0[1] + b1);
                    *(__half2*)(C + (size_t)rp1 * 512 + col) =
                        __floats2half2_rn(a0[2] + b0, a0[3] + b1);
                } else {
                    float* C = (float*)Cv2;
                    int cc = col - 512;
                    float b0 = bias2[lvlB + cc], b1 = bias2[lvlB + cc + 1];
                    *(float2*)(C + (size_t)rp0 * 256 + cc) = make_float2(a0[0] + b0, a0[1] + b1);
                    *(float2*)(C + (size_t)rp1 * 256 + cc) = make_float2(a0[2] + b0, a0[3] + b1);
                }
            } else {
                float b0 = bias[col], b1 = bias[col + 1];
                int rp0 = (mrow >> 10) * mMul + mOffE + (mrow & 1023);
                int m2 = mrow + 8;
                int rp1 = (m2 >> 10) * mMul + mOffE + (m2 & 1023);
                if (mode == 0) {
                    float* C = (float*)Cv;
                    *(float2*)(C + (size_t)rp0 * ldC + col) = make_float2(a0[0] + b0, a0[1] + b1);
                    *(float2*)(C + (size_t)rp1 * ldC + col) = make_float2(a0[2] + b0, a0[3] + b1);
                } else {
                    __half* C = (__half*)Cv;
                    *(__half2*)(C + (size_t)rp0 * ldC + col) =
                        __floats2half2_rn(a0[0] + b0, a0[1] + b1);
                    *(__half2*)(C + (size_t)rp1 * ldC + col) =
                        __floats2half2_rn(a0[2] + b0, a0[3] + b1);
                }
            }
        }
    }
}

// ---------------- prep: transpose (b,c,hw)->(b*hw,c), single fp16 plane ----------------
__global__ void prep_input(const float* __restrict__ in, __half* __restrict__ xh)
{
    __shared__ float tl[32][33];
    int b = blockIdx.z, c0 = blockIdx.y * 32, hw0 = blockIdx.x * 32;
    const float* ip = in + ((size_t)b * CC + c0) * HWW + hw0;
    #pragma unroll
    for (int j = 0; j < 4; ++j)
        tl[threadIdx.y + j*8][threadIdx.x] = ip[(size_t)(threadIdx.y + j*8) * HWW + threadIdx.x];
    __syncthreads();
    #pragma unroll
    for (int j = 0; j < 4; ++j) {
        int hw = hw0 + threadIdx.y + j*8;
        int cc = c0 + threadIdx.x;
        size_t o = ((size_t)b * HWW + hw) * CC + cc;
        xh[o] = __float2half_rn(tl[threadIdx.x][threadIdx.y + j*8]);
    }
}

// ---------------- one-shot weight prep ----------------
__global__ void prep_weights(
    const float* __restrict__ wv,    const float* __restrict__ wi,
    const float* __restrict__ w_val, const float* __restrict__ w_out,
    const float* __restrict__ w_off, const float* __restrict__ w_attn,
    const float* __restrict__ wc,
    const float* __restrict__ bv,    const float* __restrict__ bi,
    __half* __restrict__ w1h,  __half* __restrict__ wvoa,
    __half* __restrict__ wouth,
    __half* __restrict__ wch,
    float* __restrict__ b1)
{
    int i = blockIdx.x * 256 + threadIdx.x;
    if (i < 786432) {
        w1h[i] = __float2half_rn(i < 393216 ? wv[i] : wi[i - 393216]);
    } else if (i < 1179648) {
        int j = i - 786432;                // 0..393215, combined [w_val ; w_oa]
        int r = j >> 9, c = j & 511;
        float v;
        if (r < 512) v = w_val[r * 512 + c];
        else {
            int rr = r - 512;
            v = (rr < 128) ? w_off[rr * 512 + c] : ((rr < 192) ? w_attn[(rr - 128) * 512 + c] : 0.f);
        }
        wvoa[j] = __float2half_rn(v);
    } else if (i < 1441792) {
        int j = i - 1179648;
        wouth[j] = __float2half_rn(w_out[j]);
    } else if (i < 2228224) {
        int j = i - 1441792;               // 0..786431
        wch[j] = __float2half_rn(wc[j]);
    } else if (i < 2229248) {
        int j = i - 2228224;
        b1[j] = (j < 512) ? bv[j] : bi[j - 512];
    }
}

// ---------------- lep[lvl][n] = le[lvl] . Woa[n] + boa[n]  (fp32, exact) -------
__global__ void leproj_k(const float* __restrict__ le,
                         const float* __restrict__ w_off, const float* __restrict__ w_attn,
                         const float* __restrict__ b_off, const float* __restrict__ b_attn,
                         float* __restrict__ lep)
{
    int lvl = blockIdx.x, n = threadIdx.x;   // 2 x 256
    const float* l = le + lvl * 512;
    float s = 0.f;
    if (n < 128) {
        s = b_off[n];
        const float* w = w_off + n * 512;
        for (int d = 0; d < 512; ++d) s = fmaf(l[d], w[d], s);
    } else if (n < 192) {
        s = b_attn[n - 128];
        const float* w = w_attn + (n - 128) * 512;
        for (int d = 0; d < 512; ++d) s = fmaf(l[d], w[d], s);
    }
    lep[lvl * 256 + n] = s;
}

// ---------------- GN stats over seq-major (rows=(be,hw), 512 ch); group=16 ch ----------------
__global__ void gn_stats_seq(const float* __restrict__ x, float* __restrict__ stats)
{
    int be = blockIdx.y, g = blockIdx.x;
    int t = threadIdx.x;
    const float* base = x + (size_t)be * 1024 * 512 + g * 16 + (t & 3) * 4;
    float s = 0.f, sq = 0.f;
    #pragma unroll
    for (int it = 0; it < 16; ++it) {
        float4 v = *(const float4*)(base + (size_t)((t >> 2) + it * 64) * 512);
        s  += v.x + v.y + v.z + v.w;
        sq += v.x*v.x + v.y*v.y + v.z*v.z + v.w*v.w;
    }
    __shared__ float red[16];
    for (int o = 16; o > 0; o >>= 1) {
        s  += __shfl_down_sync(0xffffffffu, s,  o);
        sq += __shfl_down_sync(0xffffffffu, sq, o);
    }
    if ((t & 31) == 0) { red[t >> 5] = s; red[8 + (t >> 5)] = sq; }
    __syncthreads();
    if (t < 32) {
        s  = (t < 8) ? red[t]     : 0.f;
        sq = (t < 8) ? red[8 + t] : 0.f;
        for (int o = 4; o > 0; o >>= 1) {
            s  += __shfl_down_sync(0xffffffffu, s,  o);
            sq += __shfl_down_sync(0xffffffffu, sq, o);
        }
        if (t == 0) {
            float mean = s * (1.f/16384.f);
            float var  = sq * (1.f/16384.f) - mean * mean;
            stats[(be*32+g)*2]   = mean;
            stats[(be*32+g)*2+1] = rsqrtf(var + 1e-5f);
        }
    }
}

// ---------------- GN1 finish: src fp16 hi/lo ----------------
__global__ void gn1_finish2(const float* __restrict__ pre, const float* __restrict__ stats,
    const float* __restrict__ gv, const float* __restrict__ bev,
    const float* __restrict__ gi, const float* __restrict__ bei,
    __half* __restrict__ sh, __half* __restrict__ sl)
{
    size_t e = ((size_t)blockIdx.x * 256 + threadIdx.x) * 4;
    int row = (int)(e >> 9), d = (int)(e & 511);
    int be = row >> 10, lvl = be & 1;
    float mean = stats[(be * 32 + (d >> 4)) * 2];
    float rstd = stats[(be * 32 + (d >> 4)) * 2 + 1];
    const float* gam = lvl ? gi : gv;
    const float* bet = lvl ? bei : bev;
    float4 v = *(const float4*)(pre + e);
    float vv[4] = {v.x, v.y, v.z, v.w};
    __half hh[4], ll[4];
    #pragma unroll
    for (int k = 0; k < 4; ++k) {
        float sv = (vv[k] - mean) * rstd * gam[d + k] + bet[d + k];
        splitH(sv, hh[k], ll[k]);
    }
    *(uint2*)(sh + e) = *(uint2*)hh;
    *(uint2*)(sl + e) = *(uint2*)ll;
}

// ---------------- deformable sampling (fused softmax), half2 loads ----------------
__global__ __launch_bounds__(256) void msda_sample(
    const __half* __restrict__ vproj, const float* __restrict__ oa,
    __half* __restrict__ msh)
{
    int bq = blockIdx.x;
    int b = bq >> 11;
    int hw = bq & 1023;
    float refx = ((hw & 31) + 0.5f) * (1.f/32.f);
    float refy = ((hw >> 5) + 0.5f) * (1.f/32.f);
    __shared__ float sx[64], sy[64], sw[64];
    int t = threadIdx.x;   // 256
    const float* row = oa + (size_t)bq * 256;
    if (t < 64) {
        sx[t] = (refx + row[t*2]   * (1.f/32.f)) * 32.f - 0.5f;
        sy[t] = (refy + row[t*2+1] * (1.f/32.f)) * 32.f - 0.5f;
        float lg = row[128 + t];
        float m = lg;
        #pragma unroll
        for (int o = 1; o < 8; o <<= 1) m = fmaxf(m, __shfl_xor_sync(0xffffffffu, m, o));
        float ex = expf(lg - m);
        float s = ex;
        #pragma unroll
        for (int o = 1; o < 8; o <<= 1) s += __shfl_xor_sync(0xffffffffu, s, o);
        sw[t] = ex / s;
    }
    __syncthreads();
    int head = t >> 5, c2 = t & 31;       // 8 heads x 32 half2-channels
    const __half2* vb = (const __half2*)(vproj + (size_t)b * LQQ * DD) + head * 32 + c2;
    float accx = 0.f, accy = 0.f;
    #pragma unroll
    for (int lp = 0; lp < 8; lp++) {
        int l = lp >> 2;
        float xs = sx[head*8+lp], ys = sy[head*8+lp], w = sw[head*8+lp];
        float x0f = floorf(xs), y0f = floorf(ys);
        float fx = xs - x0f, fy = ys - y0f;
        int x0 = (int)x0f, y0 = (int)y0f;
        const __half2* vl = vb + (size_t)l * HWW * 256;
        bool xa = (unsigned)x0 < 32u, xb = (unsigned)(x0+1) < 32u;
        bool ya = (unsigned)y0 < 32u, yb = (unsigned)(y0+1) < 32u;
        float2 z2 = make_float2(0.f, 0.f);
        float2 v00 = (ya && xa) ? __half22float2(vl[(size_t)(y0*32 + x0)      * 256]) : z2;
        float2 v01 = (ya && xb) ? __half22float2(vl[(size_t)(y0*32 + x0 + 1)  * 256]) : z2;
        float2 v10 = (yb && xa) ? __half22float2(vl[(size_t)(y0*32 + x0 + 32) * 256]) : z2;
        float2 v11 = (yb && xb) ? __half22float2(vl[(size_t)(y0*32 + x0 + 33) * 256]) : z2;
        float w00 = (1.f-fy)*(1.f-fx), w01 = (1.f-fy)*fx, w10 = fy*(1.f-fx), w11 = fy*fx;
        accx = fmaf(w, v00.x*w00 + v01.x*w01 + v10.x*w10 + v11.x*w11, accx);
        accy = fmaf(w, v00.y*w00 + v01.y*w01 + v10.y*w10 + v11.y*w11, accy);
    }
    ((__half2*)msh)[(size_t)bq * 256 + head * 32 + c2] = __floats2half2_rn(accx, accy);
}

// ---------------- residual + LayerNorm -> cat fp16 (conv2 B layout) ----------------
__global__ void ln_res(const __half* __restrict__ srch, const __half* __restrict__ srcl,
                       const __half* __restrict__ att,
                       const float* __restrict__ g, const float* __restrict__ be,
                       __half* __restrict__ cath)
{
    int grow = blockIdx.x;            // b*2048 + lvl*1024 + hw
    size_t base = (size_t)grow * DD;
    int t = threadIdx.x;              // 256
    float s0 = __half2float(srch[base + t])       + __half2float(srcl[base + t]);
    float s1 = __half2float(srch[base + t + 256]) + __half2float(srcl[base + t + 256]);
    float v0 = s0 + __half2float(att[base + t]);
    float v1 = s1 + __half2float(att[base + t + 256]);
    float s = v0 + v1, sq = v0*v0 + v1*v1;
    __shared__ float red[16];
    for (int o = 16; o > 0; o >>= 1) {
        s  += __shfl_down_sync(0xffffffffu, s,  o);
        sq += __shfl_down_sync(0xffffffffu, sq, o);
    }
    if ((t & 31) == 0) { red[t >> 5] = s; red[8 + (t >> 5)] = sq; }
    __syncthreads();
    if (t < 32) {
        s  = (t < 8) ? red[t]     : 0.f;
        sq = (t < 8) ? red[8 + t] : 0.f;
        for (int o = 4; o > 0; o >>= 1) {
            s  += __shfl_down_sync(0xffffffffu, s,  o);
            sq += __shfl_down_sync(0xffffffffu, sq, o);
        }
        if (t == 0) { red[0] = s; red[8] = sq; }
    }
    __syncthreads();
    float mu   = red[0] * (1.f/512.f);
    float var  = red[8] * (1.f/512.f) - mu * mu;
    float rstd = rsqrtf(var + 1e-5f);
    int b = grow >> 11, lvl = (grow >> 10) & 1, hw = grow & 1023;
    size_t obase = ((size_t)b * 1024 + hw) * 1024 + lvl * 512;
    cath[obase + t]       = __float2half_rn((v0 - mu) * rstd * g[t]       + be[t]);
    cath[obase + t + 256] = __float2half_rn((v1 - mu) * rstd * g[t + 256] + be[t + 256]);
}

// ---------------- GN stats: contiguous groups (conv2 output) ----------------
__global__ void gn_stats(const float* __restrict__ x, float* __restrict__ stats, int groupElems)
{
    int idx = blockIdx.y * gridDim.x + blockIdx.x;
    const float* p = x + (size_t)idx * groupElems;
    float s = 0.f, sq = 0.f;
    for (int i = threadIdx.x * 4; i < groupElems; i += blockDim.x * 4) {
        float4 v = *(const float4*)(p + i);
        s  += v.x + v.y + v.z + v.w;
        sq += v.x*v.x + v.y*v.y + v.z*v.z + v.w*v.w;
    }
    __shared__ float red[16];
    int t = threadIdx.x;
    for (int o = 16; o > 0; o >>= 1) {
        s  += __shfl_down_sync(0xffffffffu, s,  o);
        sq += __shfl_down_sync(0xffffffffu, sq, o);
    }
    if ((t & 31) == 0) { red[t >> 5] = s; red[8 + (t >> 5)] = sq; }
    __syncthreads();
    if (t < 32) {
        s  = (t < 8) ? red[t]     : 0.f;
        sq = (t < 8) ? red[8 + t] : 0.f;
        for (int o = 4; o > 0; o >>= 1) {
            s  += __shfl_down_sync(0xffffffffu, s,  o);
            sq += __shfl_down_sync(0xffffffffu, sq, o);
        }
        if (t == 0) {
            float inv = 1.f / (float)groupElems;
            float mean = s * inv;
            stats[idx*2]   = mean;
            stats[idx*2+1] = rsqrtf(sq * inv - mean * mean + 1e-5f);
        }
    }
}

__global__ void gn2_finish(const float* __restrict__ x, const float* __restrict__ stats,
    const float* __restrict__ gc, const float* __restrict__ bec, float* __restrict__ out)
{
    size_t i = (size_t)blockIdx.x * blockDim.x + threadIdx.x;
    int hwch = (int)(i >> 10);
    int ch = hwch % 768;
    int b  = hwch / 768;
    int g  = ch / 24;
    float mean = stats[(b*32 + g) * 2];
    float rstd = stats[(b*32 + g) * 2 + 1];
    out[i] = (x[i] - mean) * rstd * gc[ch] + bec[ch];
}

// ---------------- launcher ----------------
#define SYM(T, v, s) T v; cudaGetSymbolAddress((void**)&v, s)
extern "C" void kernel_launch(void* const* d_in, const int* in_sizes, int n_in,
                              void* d_out, int out_size)
{
    const float* input_v = (const float*)d_in[0];
    const float* input_i = (const float*)d_in[1];
    const float* wv      = (const float*)d_in[2];
    const float* bv      = (const float*)d_in[3];
    const float* gv      = (const float*)d_in[4];
    const float* bev     = (const float*)d_in[5];
    const float* wi      = (const float*)d_in[6];
    const float* bi      = (const float*)d_in[7];
    const float* gi      = (const float*)d_in[8];
    const float* bei     = (const float*)d_in[9];
    const float* le      = (const float*)d_in[10];
    const float* w_off   = (const float*)d_in[11];
    const float* b_off   = (const float*)d_in[12];
    const float* w_attn  = (const float*)d_in[13];
    const float* b_attn  = (const float*)d_in[14];
    const float* w_val   = (const float*)d_in[15];
    const float* b_val   = (const float*)d_in[16];
    const float* w_out   = (const float*)d_in[17];
    const float* b_out   = (const float*)d_in[18];
    const float* ln_g    = (const float*)d_in[19];
    const float* ln_b    = (const float*)d_in[20];
    const float* wc      = (const float*)d_in[21];
    const float* bc      = (const float*)d_in[22];
    const float* gc      = (const float*)d_in[23];
    const float* bec     = (const float*)d_in[24];

    SYM(__half*, xth,  g_xth);
    SYM(__half*, w1h,  g_w1h);  SYM(__half*, wvoa, g_wvoa);
    SYM(__half*, wouth,g_wouth);
    SYM(__half*, wch,  g_wch_);
    SYM(__half*, srch, g_srch); SYM(__half*, srcl, g_srcl);
    SYM(__half*, msh,  g_msh);
    SYM(__half*, cath, g_cath); SYM(__half*, vph,  g_vph);
    SYM(__half*, attno, g_attnoh);
    SYM(float*, pre,   g_pre4);
    SYM(float*, oa,    g_oa4);
    SYM(float*, conv2, g_conv24);
    SYM(float*, lep,   g_lep);    SYM(float*, b1,    g_b1);
    SYM(float*, st1,   g_stats1); SYM(float*, st2,   g_stats2);
    size_t XT = (size_t)8192*768;

    cudaFuncSetAttribute(gemm_tc<1>, cudaFuncAttributeMaxDynamicSharedMemorySize, GEMM_SMEM);
    cudaFuncSetAttribute(gemm_tc<2>, cudaFuncAttributeMaxDynamicSharedMemorySize, GEMM_SMEM);

    // prep
    prep_weights<<<8708, 256>>>(wv, wi, w_val, w_out, w_off, w_attn, wc,
                                bv, bi, w1h, wvoa, wouth, wch, b1);
    leproj_k<<<2, 256>>>(le, w_off, w_attn, b_off, b_attn, lep);
    prep_input<<<dim3(32, 24, BB), dim3(32, 8)>>>(input_v, xth);
    prep_input<<<dim3(32, 24, BB), dim3(32, 8)>>>(input_i, xth + XT);

    // conv1 (v+i, z planes): D[8192,512] -> rows (b, lvl, hw)  [1-split]
    gemm_tc<1><<<dim3(4, 64, 2), 256, GEMM_SMEM>>>(xth, xth, w1h, b1, pre,
        768, 0, 2048, 0, 512, (long)XT, 393216L, 512, 1024, 0, nullptr, nullptr);
    // GN1
    gn_stats_seq<<<dim3(32, 16), 256>>>(pre, st1);
    gn1_finish2<<<8192, 256>>>(pre, st1, gv, bev, gi, bei, srch, srcl);
    // fused vproj+oa projection [1-split, dual output]
    gemm_tc<1><<<dim3(6, 128), 256, GEMM_SMEM>>>(srch, srch, wvoa, b_val, vph,
        512, 3, 1024, 0, 512, 0L, 0L, 0, 0, 0, oa, lep);
    // sampling (softmax fused)
    msda_sample<<<MROWS, 256>>>(vph, oa, msh);
    // output projection [1-split, fp16 out]
    gemm_tc<1><<<dim3(4, 128), 256, GEMM_SMEM>>>(msh, msh, wouth, b_out, attno,
        512, 2, 1024, 0, 512, 0L, 0L, 0, 0, 0, nullptr, nullptr);
    // residual + LN -> cat fp16
    ln_res<<<MROWS, 256>>>(srch, srcl, attno, ln_g, ln_b, cath);
    // conv2: D[768, 8192] -> (b, o, hw)  [1-split]
    gemm_tc<1><<<dim3(64, 6), 256, GEMM_SMEM>>>(wch, wch, cath, bc, conv2,
        1024, 1, 0, 0, 768, 0L, 0L, 0, 0, 0, nullptr, nullptr);
    // final GN
    gn_stats<<<dim3(32, BB), 256>>>(conv2, st2, 24 * HWW);
    gn2_finish<<<24576, 256>>>(conv2, st2, gc, bec, (float*)d_out);
}

// round 12
// speedup vs baseline: 3.8305x; 1.0315x over previous
#include <cuda_runtime.h>
#include <cuda_fp16.h>
#include <cstdint>

#define BB   8
#define CC   768
#define DD   512
#define HWW  1024
#define LQQ  2048
#define MROWS (BB*LQQ)   // 16384

// ---------------- scratch (device globals) ----------------
__device__ uint4 g_xth [2][8192*768/8];
__device__ uint4 g_w1h [2*512*768/8];                 // conv1 weights v|i
__device__ uint4 g_wvoa[768*512/8];                   // [w_val(512) ; w_oa(256)]
__device__ uint4 g_wouth[512*512/8];
__device__ uint4 g_wch_[768*1024/8];
__device__ uint4 g_preh[MROWS*512/8];                 // conv1 out fp16
__device__ uint4 g_srch[MROWS*512/8];
__device__ uint4 g_msh[MROWS*512/8];
__device__ uint4 g_cath[8192*1024/8];
__device__ uint4 g_vph [MROWS*512/8];                 // vproj fp16
__device__ uint4 g_attnoh[MROWS*512/8];               // attn out fp16
__device__ uint4 g_conv2h[BB*CC*HWW/8];               // conv2 out fp16
__device__ float4 g_oa4   [MROWS*256/4];
__device__ float  g_lep  [512];                       // le@Woa^T + boa, [lvl][256]
__device__ float  g_b1   [1024];                      // conv1 bias v|i
__device__ float  g_stats1[BB*2*32*2];
__device__ float  g_stats2[BB*32*2];

// ---------------- PTX helpers (sm_80-compatible ISA only) ----------------
__device__ __forceinline__ uint32_t smem_u32(const void* p) {
    uint32_t a;
    asm("{ .reg .u64 t; cvta.to.shared.u64 t, %1; cvt.u32.u64 %0, t; }" : "=r"(a) : "l"(p));
    return a;
}
#define CP16(s, g) \
    asm volatile("cp.async.cg.shared.global [%0], [%1], 16;" :: "r"(s), "l"(g))
#define CP_COMMIT() asm volatile("cp.async.commit_group;" ::: "memory")
#define LDSM4(r, a) \
    asm volatile("ldmatrix.sync.aligned.m8n8.x4.shared.b16 {%0,%1,%2,%3}, [%4];" \
        : "=r"((r)[0]), "=r"((r)[1]), "=r"((r)[2]), "=r"((r)[3]) : "r"(a))
#define MMA16(c, a, b0, b1) \
    asm volatile("mma.sync.aligned.m16n8k16.row.col.f32.f16.f16.f32 " \
        "{%0,%1,%2,%3}, {%4,%5,%6,%7}, {%8,%9}, {%0,%1,%2,%3};" \
        : "+f"((c)[0]), "+f"((c)[1]), "+f"((c)[2]), "+f"((c)[3]) \
        : "r"((a)[0]), "r"((a)[1]), "r"((a)[2]), "r"((a)[3]), "r"(b0), "r"(b1))

__device__ __forceinline__ void splitH(float v, __half& h, __half& l) {
    h = __float2half_rn(v);
    l = __float2half_rn(v - __half2float(h));
}

// ============================================================================
// Split-fp16 HMMA GEMM (template NSPLIT = 1 or 2 A-planes).
// D[m,n] = sum_k A[m,k]*B[n,k]; 128x128 tiles, K chunk 32, 4-stage pipeline,
// one __syncthreads per chunk.
// mode 0: fp32 C[((m>>10)*mMul + mOff + m&1023)*ldC + n] + bias[n]
// mode 1: fp32 C[((n>>10)*ldC + m)*1024 + (n&1023)]      + bias[m]
// mode 2: fp16 C, row mapping of mode 0
// mode 3: dual: col<512 -> fp16 Cv (ld 512, bias[n]); col>=512 -> fp32 Cv2
//         (ld 256, bias2[lvl*256 + n-512]),  lvl = (m0>>10)&1
// mode 4: fp16 C, mapping of mode 1
// ============================================================================
#define GEMM_SMEM 98304
template<int NSPLIT>
__global__ __launch_bounds__(256) void gemm_tc(
    const __half* __restrict__ Ah, const __half* __restrict__ Al,
    const __half* __restrict__ B,
    const float* __restrict__ bias, void* __restrict__ Cv,
    int K, int mode, int mMul, int mOff, int ldC,
    long zA, long zB, int zBias, int zOffMul, int biasLvl,
    void* __restrict__ Cv2, const float* __restrict__ bias2)
{
    extern __shared__ __align__(16) char smem[];
    const uint32_t sb = smem_u32(smem);
    const int tid = threadIdx.x;
    const int z = blockIdx.z;
    Ah += (size_t)z * zA; Al += (size_t)z * zA; B += (size_t)z * zB;
    const int m0 = blockIdx.y * 128, n0 = blockIdx.x * 128;
    bias += z * zBias + ((m0 >> 10) & 1) * biasLvl;
    const int mOffE = mOff + z * zOffMul;
    const int warp = tid >> 5, lane = tid & 31;
    const int wm = warp >> 1, wn = warp & 1;

    const int kg = tid & 3, r0 = tid >> 2;
    const int arow_l = lane & 15, akg_l = lane >> 4;
    const int nr = (lane & 7) + ((lane & 16) >> 1);
    const int bkg_l = (lane >> 3) & 1;

    float acc[2][8][4];
    #pragma unroll
    for (int i = 0; i < 2; ++i)
        #pragma unroll
        for (int j = 0; j < 8; ++j)
            #pragma unroll
            for (int k = 0; k < 4; ++k) acc[i][j][k] = 0.f;

    const int nC = K >> 5;

    auto load_stage = [&](int c) {
        const uint32_t stb = sb + (uint32_t)(c & 3) * 24576u;
        const int k0 = c << 5;
        #pragma unroll
        for (int h = 0; h < 2; ++h) {
            int row = r0 + h * 64;
            uint32_t so = (uint32_t)(row * 64 + ((kg ^ (row & 3)) << 4));
            size_t ga = (size_t)(m0 + row) * K + k0 + kg * 8;
            size_t gb = (size_t)(n0 + row) * K + k0 + kg * 8;
            CP16(stb +         so, Ah + ga);
            if (NSPLIT == 2) CP16(stb + 8192 + so, Al + ga);
            CP16(stb + 16384 + so, B  + gb);
        }
        CP_COMMIT();
    };

    load_stage(0); load_stage(1); load_stage(2);
    for (int c = 0; c < nC; ++c) {
        int rem = nC - c;
        if (rem >= 3)      asm volatile("cp.async.wait_group 2;" ::: "memory");
        else if (rem == 2) asm volatile("cp.async.wait_group 1;" ::: "memory");
        else               asm volatile("cp.async.wait_group 0;" ::: "memory");
        __syncthreads();
        if (c + 3 < nC) load_stage(c + 3);
        const uint32_t stb = sb + (uint32_t)(c & 3) * 24576u;
        #pragma unroll
        for (int kk = 0; kk < 2; ++kk) {
            uint32_t ah[2][4], al[2][4];
            #pragma unroll
            for (int mf = 0; mf < 2; ++mf) {
                int arow = wm * 32 + mf * 16 + arow_l;
                uint32_t ad = stb + (uint32_t)(arow * 64 +
                              ((((kk << 1) + akg_l) ^ (arow_l & 3)) << 4));
                LDSM4(ah[mf], ad);
                if (NSPLIT == 2) LDSM4(al[mf], ad + 8192);
            }
            #pragma unroll
            for (int np = 0; np < 4; ++np) {
                int brow = wn * 64 + np * 16 + nr;
                uint32_t bd = stb + 16384u + (uint32_t)(brow * 64 +
                              ((((kk << 1) + bkg_l) ^ (nr & 3)) << 4));
                uint32_t bh[4];
                LDSM4(bh, bd);
                #pragma unroll
                for (int half = 0; half < 2; ++half) {
                    uint32_t b0 = bh[half*2], b1 = bh[half*2+1];
                    int nj = np * 2 + half;
                    #pragma unroll
                    for (int mf = 0; mf < 2; ++mf) {
                        MMA16(acc[mf][nj], ah[mf], b0, b1);
                        if (NSPLIT == 2) MMA16(acc[mf][nj], al[mf], b0, b1);
                    }
                }
            }
        }
    }

    // ---- epilogue ----
    const int tq = lane >> 2, tr2 = (lane & 3) * 2;
    const int lvlB = ((m0 >> 10) & 1) * 256;
    #pragma unroll
    for (int mf = 0; mf < 2; ++mf) {
        #pragma unroll
        for (int nj = 0; nj < 8; ++nj) {
            int mrow = m0 + wm * 32 + mf * 16 + tq;
            int col  = n0 + wn * 64 + nj * 8 + tr2;
            float* a0 = acc[mf][nj];
            if (mode == 1 || mode == 4) {
                float bm0 = bias[mrow], bm1 = bias[mrow + 8];
                size_t base = ((size_t)((col >> 10) * ldC)) * 1024 + (col & 1023);
                if (mode == 1) {
                    float* C = (float*)Cv;
                    *(float2*)(C + base + (size_t)mrow       * 1024) = make_float2(a0[0] + bm0, a0[1] + bm0);
                    *(float2*)(C + base + (size_t)(mrow + 8) * 1024) = make_float2(a0[2] + bm1, a0[3] + bm1);
                } else {
                    __half* C = (__half*)Cv;
                    *(__half2*)(C + base + (size_t)mrow       * 1024) = __floats2half2_rn(a0[0] + bm0, a0[1] + bm0);
                    *(__half2*)(C + base + (size_t)(mrow + 8) * 1024) = __floats2half2_rn(a0[2] + bm1, a0[3] + bm1);
                }
            } else if (mode == 3) {
                int rp0 = mrow, rp1 = mrow + 8;
                if (col < 512) {
                    __half* C = (__half*)Cv;
                    float b0 = bias[col], b1 = bias[col + 1];
                    *(__half2*)(C + (size_t)rp0 * 512 + col) =
                        __floats2half2_rn(a0[0] + b0, a0[1] + b1);
                    *(__half2*)(C + (size_t)rp1 * 512 + col) =
                        __floats2half2_rn(a0[2] + b0, a0[3] + b1);
                } else {
                    float* C = (float*)Cv2;
                    int cc = col - 512;
                    float b0 = bias2[lvlB + cc], b1 = bias2[lvlB + cc + 1];
                    *(float2*)(C + (size_t)rp0 * 256 + cc) = make_float2(a0[0] + b0, a0[1] + b1);
                    *(float2*)(C + (size_t)rp1 * 256 + cc) = make_float2(a0[2] + b0, a0[3] + b1);
                }
            } else {
                float b0 = bias[col], b1 = bias[col + 1];
                int rp0 = (mrow >> 10) * mMul + mOffE + (mrow & 1023);
                int m2 = mrow + 8;
                int rp1 = (m2 >> 10) * mMul + mOffE + (m2 & 1023);
                if (mode == 0) {
                    float* C = (float*)Cv;
                    *(float2*)(C + (size_t)rp0 * ldC + col) = make_float2(a0[0] + b0, a0[1] + b1);
                    *(float2*)(C + (size_t)rp1 * ldC + col) = make_float2(a0[2] + b0, a0[3] + b1);
                } else {
                    __half* C = (__half*)Cv;
                    *(__half2*)(C + (size_t)rp0 * ldC + col) =
                        __floats2half2_rn(a0[0] + b0, a0[1] + b1);
                    *(__half2*)(C + (size_t)rp1 * ldC + col) =
                        __floats2half2_rn(a0[2] + b0, a0[3] + b1);
                }
            }
        }
    }
}

// ---------------- prep: transpose both inputs (z=16) ----------------
__global__ void prep_input2(const float* __restrict__ iv, const float* __restrict__ ii,
                            __half* __restrict__ xh)
{
    __shared__ float tl[32][33];
    int zz = blockIdx.z;
    int b = zz & 7;
    const float* in = (zz < 8) ? iv : ii;
    __half* out = xh + (size_t)(zz >> 3) * 8192 * 768;
    int c0 = blockIdx.y * 32, hw0 = blockIdx.x * 32;
    const float* ip = in + ((size_t)b * CC + c0) * HWW + hw0;
    #pragma unroll
    for (int j = 0; j < 4; ++j)
        tl[threadIdx.y + j*8][threadIdx.x] = ip[(size_t)(threadIdx.y + j*8) * HWW + threadIdx.x];
    __syncthreads();
    #pragma unroll
    for (int j = 0; j < 4; ++j) {
        int hw = hw0 + threadIdx.y + j*8;
        int cc = c0 + threadIdx.x;
        size_t o = ((size_t)b * HWW + hw) * CC + cc;
        out[o] = __float2half_rn(tl[threadIdx.x][threadIdx.y + j*8]);
    }
}

// ---------------- one-shot weight prep ----------------
__global__ void prep_weights(
    const float* __restrict__ wv,    const float* __restrict__ wi,
    const float* __restrict__ w_val, const float* __restrict__ w_out,
    const float* __restrict__ w_off, const float* __restrict__ w_attn,
    const float* __restrict__ wc,
    const float* __restrict__ bv,    const float* __restrict__ bi,
    __half* __restrict__ w1h,  __half* __restrict__ wvoa,
    __half* __restrict__ wouth,
    __half* __restrict__ wch,
    float* __restrict__ b1)
{
    int i = blockIdx.x * 256 + threadIdx.x;
    if (i < 786432) {
        w1h[i] = __float2half_rn(i < 393216 ? wv[i] : wi[i - 393216]);
    } else if (i < 1179648) {
        int j = i - 786432;                // combined [w_val ; w_oa]
        int r = j >> 9, c = j & 511;
        float v;
        if (r < 512) v = w_val[r * 512 + c];
        else {
            int rr = r - 512;
            v = (rr < 128) ? w_off[rr * 512 + c] : ((rr < 192) ? w_attn[(rr - 128) * 512 + c] : 0.f);
        }
        wvoa[j] = __float2half_rn(v);
    } else if (i < 1441792) {
        int j = i - 1179648;
        wouth[j] = __float2half_rn(w_out[j]);
    } else if (i < 2228224) {
        int j = i - 1441792;
        wch[j] = __float2half_rn(wc[j]);
    } else if (i < 2229248) {
        int j = i - 2228224;
        b1[j] = (j < 512) ? bv[j] : bi[j - 512];
    }
}

// ---------------- lep[lvl][n] = le[lvl] . Woa[n] + boa[n]  (fp32, exact) -------
__global__ void leproj_k(const float* __restrict__ le,
                         const float* __restrict__ w_off, const float* __restrict__ w_attn,
                         const float* __restrict__ b_off, const float* __restrict__ b_attn,
                         float* __restrict__ lep)
{
    int lvl = blockIdx.x, n = threadIdx.x;   // 2 x 256
    const float* l = le + lvl * 512;
    float s = 0.f;
    if (n < 128) {
        s = b_off[n];
        const float* w = w_off + n * 512;
        for (int d = 0; d < 512; ++d) s = fmaf(l[d], w[d], s);
    } else if (n < 192) {
        s = b_attn[n - 128];
        const float* w = w_attn + (n - 128) * 512;
        for (int d = 0; d < 512; ++d) s = fmaf(l[d], w[d], s);
    }
    lep[lvl * 256 + n] = s;
}

// ---------------- GN stats over seq-major fp16 pre; group = (be, 16 ch) ----------------
__global__ void gn_stats_seq(const __half* __restrict__ x, float* __restrict__ stats)
{
    int be = blockIdx.y, g = blockIdx.x;
    int t = threadIdx.x;
    const __half* base = x + (size_t)be * 1024 * 512 + g * 16 + (t & 3) * 4;
    float s = 0.f, sq = 0.f;
    #pragma unroll
    for (int it = 0; it < 16; ++it) {
        uint2 raw = *(const uint2*)(base + (size_t)((t >> 2) + it * 64) * 512);
        float2 a = __half22float2(*(__half2*)&raw.x);
        float2 b = __half22float2(*(__half2*)&raw.y);
        s  += a.x + a.y + b.x + b.y;
        sq += a.x*a.x + a.y*a.y + b.x*b.x + b.y*b.y;
    }
    __shared__ float red[16];
    for (int o = 16; o > 0; o >>= 1) {
        s  += __shfl_down_sync(0xffffffffu, s,  o);
        sq += __shfl_down_sync(0xffffffffu, sq, o);
    }
    if ((t & 31) == 0) { red[t >> 5] = s; red[8 + (t >> 5)] = sq; }
    __syncthreads();
    if (t < 32) {
        s  = (t < 8) ? red[t]     : 0.f;
        sq = (t < 8) ? red[8 + t] : 0.f;
        for (int o = 4; o > 0; o >>= 1) {
            s  += __shfl_down_sync(0xffffffffu, s,  o);
            sq += __shfl_down_sync(0xffffffffu, sq, o);
        }
        if (t == 0) {
            float mean = s * (1.f/16384.f);
            float var  = sq * (1.f/16384.f) - mean * mean;
            stats[(be*32+g)*2]   = mean;
            stats[(be*32+g)*2+1] = rsqrtf(var + 1e-5f);
        }
    }
}

// ---------------- GN1 finish: fp16 pre -> src fp16 ----------------
__global__ void gn1_finish2(const __half* __restrict__ pre, const float* __restrict__ stats,
    const float* __restrict__ gv, const float* __restrict__ bev,
    const float* __restrict__ gi, const float* __restrict__ bei,
    __half* __restrict__ sh)
{
    size_t e = ((size_t)blockIdx.x * 256 + threadIdx.x) * 4;
    int row = (int)(e >> 9), d = (int)(e & 511);
    int be = row >> 10, lvl = be & 1;
    float mean = stats[(be * 32 + (d >> 4)) * 2];
    float rstd = stats[(be * 32 + (d >> 4)) * 2 + 1];
    const float* gam = lvl ? gi : gv;
    const float* bet = lvl ? bei : bev;
    uint2 raw = *(const uint2*)(pre + e);
    float2 a = __half22float2(*(__half2*)&raw.x);
    float2 b = __half22float2(*(__half2*)&raw.y);
    float vv[4] = {a.x, a.y, b.x, b.y};
    __half hh[4];
    #pragma unroll
    for (int k = 0; k < 4; ++k)
        hh[k] = __float2half_rn((vv[k] - mean) * rstd * gam[d + k] + bet[d + k]);
    *(uint2*)(sh + e) = *(uint2*)hh;
}

// ---------------- deformable sampling (fused softmax), half2 loads ----------------
__global__ __launch_bounds__(256) void msda_sample(
    const __half* __restrict__ vproj, const float* __restrict__ oa,
    __half* __restrict__ msh)
{
    int bq = blockIdx.x;
    int b = bq >> 11;
    int hw = bq & 1023;
    float refx = ((hw & 31) + 0.5f) * (1.f/32.f);
    float refy = ((hw >> 5) + 0.5f) * (1.f/32.f);
    __shared__ float sx[64], sy[64], sw[64];
    int t = threadIdx.x;   // 256
    const float* row = oa + (size_t)bq * 256;
    if (t < 64) {
        sx[t] = (refx + row[t*2]   * (1.f/32.f)) * 32.f - 0.5f;
        sy[t] = (refy + row[t*2+1] * (1.f/32.f)) * 32.f - 0.5f;
        float lg = row[128 + t];
        float m = lg;
        #pragma unroll
        for (int o = 1; o < 8; o <<= 1) m = fmaxf(m, __shfl_xor_sync(0xffffffffu, m, o));
        float ex = expf(lg - m);
        float s = ex;
        #pragma unroll
        for (int o = 1; o < 8; o <<= 1) s += __shfl_xor_sync(0xffffffffu, s, o);
        sw[t] = ex / s;
    }
    __syncthreads();
    int head = t >> 5, c2 = t & 31;       // 8 heads x 32 half2-channels
    const __half2* vb = (const __half2*)(vproj + (size_t)b * LQQ * DD) + head * 32 + c2;
    float accx = 0.f, accy = 0.f;
    #pragma unroll
    for (int lp = 0; lp < 8; lp++) {
        int l = lp >> 2;
        float xs = sx[head*8+lp], ys = sy[head*8+lp], w = sw[head*8+lp];
        float x0f = floorf(xs), y0f = floorf(ys);
        float fx = xs - x0f, fy = ys - y0f;
        int x0 = (int)x0f, y0 = (int)y0f;
        const __half2* vl = vb + (size_t)l * HWW * 256;
        bool xa = (unsigned)x0 < 32u, xb = (unsigned)(x0+1) < 32u;
        bool ya = (unsigned)y0 < 32u, yb = (unsigned)(y0+1) < 32u;
        float2 z2 = make_float2(0.f, 0.f);
        float2 v00 = (ya && xa) ? __half22float2(vl[(size_t)(y0*32 + x0)      * 256]) : z2;
        float2 v01 = (ya && xb) ? __half22float2(vl[(size_t)(y0*32 + x0 + 1)  * 256]) : z2;
        float2 v10 = (yb && xa) ? __half22float2(vl[(size_t)(y0*32 + x0 + 32) * 256]) : z2;
        float2 v11 = (yb && xb) ? __half22float2(vl[(size_t)(y0*32 + x0 + 33) * 256]) : z2;
        float w00 = (1.f-fy)*(1.f-fx), w01 = (1.f-fy)*fx, w10 = fy*(1.f-fx), w11 = fy*fx;
        accx = fmaf(w, v00.x*w00 + v01.x*w01 + v10.x*w10 + v11.x*w11, accx);
        accy = fmaf(w, v00.y*w00 + v01.y*w01 + v10.y*w10 + v11.y*w11, accy);
    }
    ((__half2*)msh)[(size_t)bq * 256 + head * 32 + c2] = __floats2half2_rn(accx, accy);
}

// ---------------- residual + LN: src recomputed from fp16 pre + stats ----------------
__global__ void ln_res(const __half* __restrict__ pre, const float* __restrict__ stats,
                       const float* __restrict__ gv, const float* __restrict__ bev,
                       const float* __restrict__ gi, const float* __restrict__ bei,
                       const __half* __restrict__ att,
                       const float* __restrict__ g, const float* __restrict__ be,
                       __half* __restrict__ cath)
{
    int grow = blockIdx.x;            // b*2048 + lvl*1024 + hw
    size_t base = (size_t)grow * DD;
    int t = threadIdx.x;              // 256
    int bee = grow >> 10, lvl = bee & 1;
    const float* gam = lvl ? gi : gv;
    const float* bet = lvl ? bei : bev;
    float mean0 = stats[(bee * 32 + (t >> 4)) * 2];
    float rstd0 = stats[(bee * 32 + (t >> 4)) * 2 + 1];
    int t2 = t + 256;
    float mean1 = stats[(bee * 32 + (t2 >> 4)) * 2];
    float rstd1 = stats[(bee * 32 + (t2 >> 4)) * 2 + 1];
    float s0 = (__half2float(pre[base + t])  - mean0) * rstd0 * gam[t]  + bet[t];
    float s1 = (__half2float(pre[base + t2]) - mean1) * rstd1 * gam[t2] + bet[t2];
    float v0 = s0 + __half2float(att[base + t]);
    float v1 = s1 + __half2float(att[base + t2]);
    float s = v0 + v1, sq = v0*v0 + v1*v1;
    __shared__ float red[16];
    for (int o = 16; o > 0; o >>= 1) {
        s  += __shfl_down_sync(0xffffffffu, s,  o);
        sq += __shfl_down_sync(0xffffffffu, sq, o);
    }
    if ((t & 31) == 0) { red[t >> 5] = s; red[8 + (t >> 5)] = sq; }
    __syncthreads();
    if (t < 32) {
        s  = (t < 8) ? red[t]     : 0.f;
        sq = (t < 8) ? red[8 + t] : 0.f;
        for (int o = 4; o > 0; o >>= 1) {
            s  += __shfl_down_sync(0xffffffffu, s,  o);
            sq += __shfl_down_sync(0xffffffffu, sq, o);
        }
        if (t == 0) { red[0] = s; red[8] = sq; }
    }
    __syncthreads();
    float mu   = red[0] * (1.f/512.f);
    float var  = red[8] * (1.f/512.f) - mu * mu;
    float rstd = rsqrtf(var + 1e-5f);
    int b = grow >> 11, hw = grow & 1023;
    size_t obase = ((size_t)b * 1024 + hw) * 1024 + lvl * 512;
    cath[obase + t]       = __float2half_rn((v0 - mu) * rstd * g[t]  + be[t]);
    cath[obase + t + 256] = __float2half_rn((v1 - mu) * rstd * g[t2] + be[t2]);
}

// ---------------- GN stats: contiguous fp16 groups (conv2 output) ----------------
__global__ void gn_stats_h(const __half* __restrict__ x, float* __restrict__ stats, int groupElems)
{
    int idx = blockIdx.y * gridDim.x + blockIdx.x;
    const __half* p = x + (size_t)idx * groupElems;
    float s = 0.f, sq = 0.f;
    for (int i = threadIdx.x * 8; i < groupElems; i += blockDim.x * 8) {
        uint4 raw = *(const uint4*)(p + i);
        float2 a = __half22float2(*(__half2*)&raw.x);
        float2 b = __half22float2(*(__half2*)&raw.y);
        float2 c = __half22float2(*(__half2*)&raw.z);
        float2 d = __half22float2(*(__half2*)&raw.w);
        s  += a.x + a.y + b.x + b.y + c.x + c.y + d.x + d.y;
        sq += a.x*a.x + a.y*a.y + b.x*b.x + b.y*b.y + c.x*c.x + c.y*c.y + d.x*d.x + d.y*d.y;
    }
    __shared__ float red[16];
    int t = threadIdx.x;
    for (int o = 16; o > 0; o >>= 1) {
        s  += __shfl_down_sync(0xffffffffu, s,  o);
        sq += __shfl_down_sync(0xffffffffu, sq, o);
    }
    if ((t & 31) == 0) { red[t >> 5] = s; red[8 + (t >> 5)] = sq; }
    __syncthreads();
    if (t < 32) {
        s  = (t < 8) ? red[t]     : 0.f;
        sq = (t < 8) ? red[8 + t] : 0.f;
        for (int o = 4; o > 0; o >>= 1) {
            s  += __shfl_down_sync(0xffffffffu, s,  o);
            sq += __shfl_down_sync(0xffffffffu, sq, o);
        }
        if (t == 0) {
            float inv = 1.f / (float)groupElems;
            float mean = s * inv;
            stats[idx*2]   = mean;
            stats[idx*2+1] = rsqrtf(sq * inv - mean * mean + 1e-5f);
        }
    }
}

__global__ void gn2_finish(const __half* __restrict__ x, const float* __restrict__ stats,
    const float* __restrict__ gc, const float* __restrict__ bec, float* __restrict__ out)
{
    size_t i2 = ((size_t)blockIdx.x * blockDim.x + threadIdx.x) * 2;
    int hwch = (int)(i2 >> 10);
    int ch = hwch % 768;
    int b  = hwch / 768;
    int g  = ch / 24;
    float mean = stats[(b*32 + g) * 2];
    float rstd = stats[(b*32 + g) * 2 + 1];
    float2 v = __half22float2(*(const __half2*)(x + i2));
    float gg = gc[ch], bb = bec[ch];
    *(float2*)(out + i2) = make_float2((v.x - mean) * rstd * gg + bb,
                                       (v.y - mean) * rstd * gg + bb);
}

// ---------------- launcher ----------------
#define SYM(T, v, s) T v; cudaGetSymbolAddress((void**)&v, s)
extern "C" void kernel_launch(void* const* d_in, const int* in_sizes, int n_in,
                              void* d_out, int out_size)
{
    const float* input_v = (const float*)d_in[0];
    const float* input_i = (const float*)d_in[1];
    const float* wv      = (const float*)d_in[2];
    const float* bv      = (const float*)d_in[3];
    const float* gv      = (const float*)d_in[4];
    const float* bev     = (const float*)d_in[5];
    const float* wi      = (const float*)d_in[6];
    const float* bi      = (const float*)d_in[7];
    const float* gi      = (const float*)d_in[8];
    const float* bei     = (const float*)d_in[9];
    const float* le      = (const float*)d_in[10];
    const float* w_off   = (const float*)d_in[11];
    const float* b_off   = (const float*)d_in[12];
    const float* w_attn  = (const float*)d_in[13];
    const float* b_attn  = (const float*)d_in[14];
    const float* w_val   = (const float*)d_in[15];
    const float* b_val   = (const float*)d_in[16];
    const float* w_out   = (const float*)d_in[17];
    const float* b_out   = (const float*)d_in[18];
    const float* ln_g    = (const float*)d_in[19];
    const float* ln_b    = (const float*)d_in[20];
    const float* wc      = (const float*)d_in[21];
    const float* bc      = (const float*)d_in[22];
    const float* gc      = (const float*)d_in[23];
    const float* bec     = (const float*)d_in[24];

    SYM(__half*, xth,  g_xth);
    SYM(__half*, w1h,  g_w1h);  SYM(__half*, wvoa, g_wvoa);
    SYM(__half*, wouth,g_wouth);
    SYM(__half*, wch,  g_wch_);
    SYM(__half*, preh, g_preh);
    SYM(__half*, srch, g_srch);
    SYM(__half*, msh,  g_msh);
    SYM(__half*, cath, g_cath); SYM(__half*, vph,  g_vph);
    SYM(__half*, attno, g_attnoh);
    SYM(__half*, conv2h, g_conv2h);
    SYM(float*, oa,    g_oa4);
    SYM(float*, lep,   g_lep);    SYM(float*, b1,    g_b1);
    SYM(float*, st1,   g_stats1); SYM(float*, st2,   g_stats2);
    size_t XT = (size_t)8192*768;

    cudaFuncSetAttribute(gemm_tc<1>, cudaFuncAttributeMaxDynamicSharedMemorySize, GEMM_SMEM);
    cudaFuncSetAttribute(gemm_tc<2>, cudaFuncAttributeMaxDynamicSharedMemorySize, GEMM_SMEM);

    // prep
    prep_weights<<<8708, 256>>>(wv, wi, w_val, w_out, w_off, w_attn, wc,
                                bv, bi, w1h, wvoa, wouth, wch, b1);
    leproj_k<<<2, 256>>>(le, w_off, w_attn, b_off, b_attn, lep);
    prep_input2<<<dim3(32, 24, 16), dim3(32, 8)>>>(input_v, input_i, xth);

    // conv1 (v+i, z planes): fp16 D -> rows (b, lvl, hw)
    gemm_tc<1><<<dim3(4, 64, 2), 256, GEMM_SMEM>>>(xth, xth, w1h, b1, preh,
        768, 2, 2048, 0, 512, (long)XT, 393216L, 512, 1024, 0, nullptr, nullptr);
    // GN1
    gn_stats_seq<<<dim3(32, 16), 256>>>(preh, st1);
    gn1_finish2<<<8192, 256>>>(preh, st1, gv, bev, gi, bei, srch);
    // fused vproj+oa projection [dual output]
    gemm_tc<1><<<dim3(6, 128), 256, GEMM_SMEM>>>(srch, srch, wvoa, b_val, vph,
        512, 3, 1024, 0, 512, 0L, 0L, 0, 0, 0, oa, lep);
    // sampling (softmax fused)
    msda_sample<<<MROWS, 256>>>(vph, oa, msh);
    // output projection [fp16 out]
    gemm_tc<1><<<dim3(4, 128), 256, GEMM_SMEM>>>(msh, msh, wouth, b_out, attno,
        512, 2, 1024, 0, 512, 0L, 0L, 0, 0, 0, nullptr, nullptr);
    // residual + LN (src recomputed from preh) -> cat fp16
    ln_res<<<MROWS, 256>>>(preh, st1, gv, bev, gi, bei, attno, ln_g, ln_b, cath);
    // conv2: fp16 D -> (b, o, hw)
    gemm_tc<1><<<dim3(64, 6), 256, GEMM_SMEM>>>(wch, wch, cath, bc, conv2h,
        1024, 4, 0, 0, 768, 0L, 0L, 0, 0, 0, nullptr, nullptr);
    // final GN
    gn_stats_h<<<dim3(32, BB), 256>>>(conv2h, st2, 24 * HWW);
    gn2_finish<<<12288, 256>>>(conv2h, st2, gc, bec, (float*)d_out);
}

// round 13
// speedup vs baseline: 4.3907x; 1.1462x over previous
#include <cuda_runtime.h>
#include <cuda_fp16.h>
#include <cstdint>

#define BB   8
#define CC   768
#define DD   512
#define HWW  1024
#define LQQ  2048
#define MROWS (BB*LQQ)   // 16384

// ---------------- scratch (device globals) ----------------
__device__ uint4 g_xth [2][8192*768/8];
__device__ uint4 g_w1h [2*512*768/8];                 // conv1 weights v|i
__device__ uint4 g_wvoa[768*512/8];                   // [w_val(512) ; w_oa(256)]
__device__ uint4 g_wouth[512*512/8];
__device__ uint4 g_wch_[768*1024/8];
__device__ uint4 g_preh[MROWS*512/8];                 // conv1 out fp16
__device__ uint4 g_srch[MROWS*512/8];
__device__ uint4 g_msh[MROWS*512/8];
__device__ uint4 g_cath[8192*1024/8];
__device__ uint4 g_vph [MROWS*512/8];                 // vproj fp16
__device__ uint4 g_attnoh[MROWS*512/8];               // attn out fp16
__device__ uint4 g_conv2h[BB*CC*HWW/8];               // conv2 out fp16
__device__ float4 g_oa4   [MROWS*256/4];
__device__ float  g_lep  [512];                       // le@Woa^T + boa, [lvl][256]
__device__ float  g_b1   [1024];                      // conv1 bias v|i
__device__ float  g_stats1[BB*2*32*2];
__device__ float  g_stats2[BB*32*2];

// ---------------- PTX helpers (sm_80-compatible ISA only) ----------------
__device__ __forceinline__ uint32_t smem_u32(const void* p) {
    uint32_t a;
    asm("{ .reg .u64 t; cvta.to.shared.u64 t, %1; cvt.u32.u64 %0, t; }" : "=r"(a) : "l"(p));
    return a;
}
#define CP16(s, g) \
    asm volatile("cp.async.cg.shared.global [%0], [%1], 16;" :: "r"(s), "l"(g))
#define CP_COMMIT() asm volatile("cp.async.commit_group;" ::: "memory")
#define LDSM4(r, a) \
    asm volatile("ldmatrix.sync.aligned.m8n8.x4.shared.b16 {%0,%1,%2,%3}, [%4];" \
        : "=r"((r)[0]), "=r"((r)[1]), "=r"((r)[2]), "=r"((r)[3]) : "r"(a))
#define MMA16(c, a, b0, b1) \
    asm volatile("mma.sync.aligned.m16n8k16.row.col.f32.f16.f16.f32 " \
        "{%0,%1,%2,%3}, {%4,%5,%6,%7}, {%8,%9}, {%0,%1,%2,%3};" \
        : "+f"((c)[0]), "+f"((c)[1]), "+f"((c)[2]), "+f"((c)[3]) \
        : "r"((a)[0]), "r"((a)[1]), "r"((a)[2]), "r"((a)[3]), "r"(b0), "r"(b1))

// ============================================================================
// fp16 HMMA GEMM: D[m,n] = sum_k A[m,k]*B[n,k]; 128x128 tiles, K chunk 64,
// 3-stage cp.async pipeline (32KB/stage), one __syncthreads per chunk.
// mode 0: fp32 C[((m>>10)*mMul + mOff + m&1023)*ldC + n] + bias[n]
// mode 1: fp32 C[((n>>10)*ldC + m)*1024 + (n&1023)]      + bias[m]
// mode 2: fp16 C, row mapping of mode 0
// mode 3: dual: col<512 -> fp16 Cv (ld 512, bias[n]); col>=512 -> fp32 Cv2
//         (ld 256, bias2[lvl*256 + n-512]),  lvl = (m0>>10)&1
// mode 4: fp16 C, mapping of mode 1
// ============================================================================
#define GEMM_SMEM 98304
__global__ __launch_bounds__(256) void gemm_tc(
    const __half* __restrict__ Ah,
    const __half* __restrict__ B,
    const float* __restrict__ bias, void* __restrict__ Cv,
    int K, int mode, int mMul, int mOff, int ldC,
    long zA, long zB, int zBias, int zOffMul, int biasLvl,
    void* __restrict__ Cv2, const float* __restrict__ bias2)
{
    extern __shared__ __align__(16) char smem[];
    const uint32_t sb = smem_u32(smem);
    const int tid = threadIdx.x;
    const int z = blockIdx.z;
    Ah += (size_t)z * zA; B += (size_t)z * zB;
    const int m0 = blockIdx.y * 128, n0 = blockIdx.x * 128;
    bias += z * zBias + ((m0 >> 10) & 1) * biasLvl;
    const int mOffE = mOff + z * zOffMul;
    const int warp = tid >> 5, lane = tid & 31;
    const int wm = warp >> 1, wn = warp & 1;

    const int arow_l = lane & 15, akg_l = lane >> 4;
    const int nr = (lane & 7) + ((lane & 16) >> 1);
    const int bkg_l = (lane >> 3) & 1;

    float acc[2][8][4];
    #pragma unroll
    for (int i = 0; i < 2; ++i)
        #pragma unroll
        for (int j = 0; j < 8; ++j)
            #pragma unroll
            for (int k = 0; k < 4; ++k) acc[i][j][k] = 0.f;

    const int nC = K >> 6;     // K chunks of 64

    auto load_stage = [&](int c) {
        const uint32_t stb = sb + (uint32_t)(c % 3) * 32768u;
        const int k0 = c << 6;
        #pragma unroll
        for (int gi = 0; gi < 4; ++gi) {
            int g = tid + gi * 256;             // 1024 16B-chunks per tile
            int row = g >> 3, c8 = g & 7;       // 8 chunks per 128B row
            uint32_t so = (uint32_t)(row * 128 + ((c8 ^ (row & 7)) << 4));
            CP16(stb +         so, Ah + (size_t)(m0 + row) * K + k0 + c8 * 8);
            CP16(stb + 16384 + so, B  + (size_t)(n0 + row) * K + k0 + c8 * 8);
        }
        CP_COMMIT();
    };

    load_stage(0);
    if (nC > 1) load_stage(1);
    for (int c = 0; c < nC; ++c) {
        if (c + 1 < nC) asm volatile("cp.async.wait_group 1;" ::: "memory");
        else            asm volatile("cp.async.wait_group 0;" ::: "memory");
        __syncthreads();
        if (c + 2 < nC) load_stage(c + 2);
        const uint32_t stb = sb + (uint32_t)(c % 3) * 32768u;
        #pragma unroll
        for (int kk = 0; kk < 4; ++kk) {
            uint32_t ah[2][4];
            #pragma unroll
            for (int mf = 0; mf < 2; ++mf) {
                int arow = wm * 32 + mf * 16 + arow_l;
                uint32_t ad = stb + (uint32_t)(arow * 128 +
                              ((((kk << 1) + akg_l) ^ (arow_l & 7)) << 4));
                LDSM4(ah[mf], ad);
            }
            #pragma unroll
            for (int np = 0; np < 4; ++np) {
                int brow = wn * 64 + np * 16 + nr;
                uint32_t bd = stb + 16384u + (uint32_t)(brow * 128 +
                              ((((kk << 1) + bkg_l) ^ (nr & 7)) << 4));
                uint32_t bh[4];
                LDSM4(bh, bd);
                #pragma unroll
                for (int half = 0; half < 2; ++half) {
                    uint32_t b0 = bh[half*2], b1 = bh[half*2+1];
                    int nj = np * 2 + half;
                    #pragma unroll
                    for (int mf = 0; mf < 2; ++mf)
                        MMA16(acc[mf][nj], ah[mf], b0, b1);
                }
            }
        }
    }

    // ---- epilogue ----
    const int tq = lane >> 2, tr2 = (lane & 3) * 2;
    const int lvlB = ((m0 >> 10) & 1) * 256;
    #pragma unroll
    for (int mf = 0; mf < 2; ++mf) {
        #pragma unroll
        for (int nj = 0; nj < 8; ++nj) {
            int mrow = m0 + wm * 32 + mf * 16 + tq;
            int col  = n0 + wn * 64 + nj * 8 + tr2;
            float* a0 = acc[mf][nj];
            if (mode == 1 || mode == 4) {
                float bm0 = bias[mrow], bm1 = bias[mrow + 8];
                size_t base = ((size_t)((col >> 10) * ldC)) * 1024 + (col & 1023);
                if (mode == 1) {
                    float* C = (float*)Cv;
                    *(float2*)(C + base + (size_t)mrow       * 1024) = make_float2(a0[0] + bm0, a0[1] + bm0);
                    *(float2*)(C + base + (size_t)(mrow + 8) * 1024) = make_float2(a0[2] + bm1, a0[3] + bm1);
                } else {
                    __half* C = (__half*)Cv;
                    *(__half2*)(C + base + (size_t)mrow       * 1024) = __floats2half2_rn(a0[0] + bm0, a0[1] + bm0);
                    *(__half2*)(C + base + (size_t)(mrow + 8) * 1024) = __floats2half2_rn(a0[2] + bm1, a0[3] + bm1);
                }
            } else if (mode == 3) {
                int rp0 = mrow, rp1 = mrow + 8;
                if (col < 512) {
                    __half* C = (__half*)Cv;
                    float b0 = bias[col], b1 = bias[col + 1];
                    *(__half2*)(C + (size_t)rp0 * 512 + col) =
                        __floats2half2_rn(a0[0] + b0, a0[1] + b1);
                    *(__half2*)(C + (size_t)rp1 * 512 + col) =
                        __floats2half2_rn(a0[2] + b0, a0[3] + b1);
                } else {
                    float* C = (float*)Cv2;
                    int cc = col - 512;
                    float b0 = bias2[lvlB + cc], b1 = bias2[lvlB + cc + 1];
                    *(float2*)(C + (size_t)rp0 * 256 + cc) = make_float2(a0[0] + b0, a0[1] + b1);
                    *(float2*)(C + (size_t)rp1 * 256 + cc) = make_float2(a0[2] + b0, a0[3] + b1);
                }
            } else {
                float b0 = bias[col], b1 = bias[col + 1];
                int rp0 = (mrow >> 10) * mMul + mOffE + (mrow & 1023);
                int m2 = mrow + 8;
                int rp1 = (m2 >> 10) * mMul + mOffE + (m2 & 1023);
                if (mode == 0) {
                    float* C = (float*)Cv;
                    *(float2*)(C + (size_t)rp0 * ldC + col) = make_float2(a0[0] + b0, a0[1] + b1);
                    *(float2*)(C + (size_t)rp1 * ldC + col) = make_float2(a0[2] + b0, a0[3] + b1);
                } else {
                    __half* C = (__half*)Cv;
                    *(__half2*)(C + (size_t)rp0 * ldC + col) =
                        __floats2half2_rn(a0[0] + b0, a0[1] + b1);
                    *(__half2*)(C + (size_t)rp1 * ldC + col) =
                        __floats2half2_rn(a0[2] + b0, a0[3] + b1);
                }
            }
        }
    }
}

// ---------------- prep: transpose both inputs (z=16) ----------------
__global__ void prep_input2(const float* __restrict__ iv, const float* __restrict__ ii,
                            __half* __restrict__ xh)
{
    __shared__ float tl[32][33];
    int zz = blockIdx.z;
    int b = zz & 7;
    const float* in = (zz < 8) ? iv : ii;
    __half* out = xh + (size_t)(zz >> 3) * 8192 * 768;
    int c0 = blockIdx.y * 32, hw0 = blockIdx.x * 32;
    const float* ip = in + ((size_t)b * CC + c0) * HWW + hw0;
    #pragma unroll
    for (int j = 0; j < 4; ++j)
        tl[threadIdx.y + j*8][threadIdx.x] = ip[(size_t)(threadIdx.y + j*8) * HWW + threadIdx.x];
    __syncthreads();
    #pragma unroll
    for (int j = 0; j < 4; ++j) {
        int hw = hw0 + threadIdx.y + j*8;
        int cc = c0 + threadIdx.x;
        size_t o = ((size_t)b * HWW + hw) * CC + cc;
        out[o] = __float2half_rn(tl[threadIdx.x][threadIdx.y + j*8]);
    }
}

// ---------------- one-shot weight prep ----------------
__global__ void prep_weights(
    const float* __restrict__ wv,    const float* __restrict__ wi,
    const float* __restrict__ w_val, const float* __restrict__ w_out,
    const float* __restrict__ w_off, const float* __restrict__ w_attn,
    const float* __restrict__ wc,
    const float* __restrict__ bv,    const float* __restrict__ bi,
    __half* __restrict__ w1h,  __half* __restrict__ wvoa,
    __half* __restrict__ wouth,
    __half* __restrict__ wch,
    float* __restrict__ b1)
{
    int i = blockIdx.x * 256 + threadIdx.x;
    if (i < 786432) {
        w1h[i] = __float2half_rn(i < 393216 ? wv[i] : wi[i - 393216]);
    } else if (i < 1179648) {
        int j = i - 786432;                // combined [w_val ; w_oa]
        int r = j >> 9, c = j & 511;
        float v;
        if (r < 512) v = w_val[r * 512 + c];
        else {
            int rr = r - 512;
            v = (rr < 128) ? w_off[rr * 512 + c] : ((rr < 192) ? w_attn[(rr - 128) * 512 + c] : 0.f);
        }
        wvoa[j] = __float2half_rn(v);
    } else if (i < 1441792) {
        int j = i - 1179648;
        wouth[j] = __float2half_rn(w_out[j]);
    } else if (i < 2228224) {
        int j = i - 1441792;
        wch[j] = __float2half_rn(wc[j]);
    } else if (i < 2229248) {
        int j = i - 2228224;
        b1[j] = (j < 512) ? bv[j] : bi[j - 512];
    }
}

// ---------------- lep[lvl][n] = le[lvl] . Woa[n] + boa[n]  (fp32, exact) -------
__global__ void leproj_k(const float* __restrict__ le,
                         const float* __restrict__ w_off, const float* __restrict__ w_attn,
                         const float* __restrict__ b_off, const float* __restrict__ b_attn,
                         float* __restrict__ lep)
{
    int lvl = blockIdx.x, n = threadIdx.x;   // 2 x 256
    const float* l = le + lvl * 512;
    float s = 0.f;
    if (n < 128) {
        s = b_off[n];
        const float* w = w_off + n * 512;
        for (int d = 0; d < 512; ++d) s = fmaf(l[d], w[d], s);
    } else if (n < 192) {
        s = b_attn[n - 128];
        const float* w = w_attn + (n - 128) * 512;
        for (int d = 0; d < 512; ++d) s = fmaf(l[d], w[d], s);
    }
    lep[lvl * 256 + n] = s;
}

// ---------------- GN stats over seq-major fp16 pre; group = (be, 16 ch) ----------------
__global__ void gn_stats_seq(const __half* __restrict__ x, float* __restrict__ stats)
{
    int be = blockIdx.y, g = blockIdx.x;
    int t = threadIdx.x;
    const __half* base = x + (size_t)be * 1024 * 512 + g * 16 + (t & 1) * 8;
    float s = 0.f, sq = 0.f;
    #pragma unroll
    for (int it = 0; it < 8; ++it) {
        uint4 raw = *(const uint4*)(base + (size_t)((t >> 1) + it * 128) * 512);
        float2 a = __half22float2(*(__half2*)&raw.x);
        float2 b = __half22float2(*(__half2*)&raw.y);
        float2 cc = __half22float2(*(__half2*)&raw.z);
        float2 d = __half22float2(*(__half2*)&raw.w);
        s  += a.x + a.y + b.x + b.y + cc.x + cc.y + d.x + d.y;
        sq += a.x*a.x + a.y*a.y + b.x*b.x + b.y*b.y + cc.x*cc.x + cc.y*cc.y + d.x*d.x + d.y*d.y;
    }
    __shared__ float red[16];
    for (int o = 16; o > 0; o >>= 1) {
        s  += __shfl_down_sync(0xffffffffu, s,  o);
        sq += __shfl_down_sync(0xffffffffu, sq, o);
    }
    if ((t & 31) == 0) { red[t >> 5] = s; red[8 + (t >> 5)] = sq; }
    __syncthreads();
    if (t < 32) {
        s  = (t < 8) ? red[t]     : 0.f;
        sq = (t < 8) ? red[8 + t] : 0.f;
        for (int o = 4; o > 0; o >>= 1) {
            s  += __shfl_down_sync(0xffffffffu, s,  o);
            sq += __shfl_down_sync(0xffffffffu, sq, o);
        }
        if (t == 0) {
            float mean = s * (1.f/16384.f);
            float var  = sq * (1.f/16384.f) - mean * mean;
            stats[(be*32+g)*2]   = mean;
            stats[(be*32+g)*2+1] = rsqrtf(var + 1e-5f);
        }
    }
}

// ---------------- GN1 finish: fp16 pre -> src fp16 (8 elem/thread) ----------------
__global__ void gn1_finish2(const __half* __restrict__ pre, const float* __restrict__ stats,
    const float* __restrict__ gv, const float* __restrict__ bev,
    const float* __restrict__ gi, const float* __restrict__ bei,
    __half* __restrict__ sh)
{
    size_t e = ((size_t)blockIdx.x * 256 + threadIdx.x) * 8;
    int row = (int)(e >> 9), d = (int)(e & 511);
    int be = row >> 10, lvl = be & 1;
    float mean = stats[(be * 32 + (d >> 4)) * 2];
    float rstd = stats[(be * 32 + (d >> 4)) * 2 + 1];
    const float* gam = lvl ? gi : gv;
    const float* bet = lvl ? bei : bev;
    uint4 raw = *(const uint4*)(pre + e);
    __half* rp = (__half*)&raw;
    __half hh[8];
    #pragma unroll
    for (int k = 0; k < 8; ++k)
        hh[k] = __float2half_rn((__half2float(rp[k]) - mean) * rstd * gam[d + k] + bet[d + k]);
    *(uint4*)(sh + e) = *(uint4*)hh;
}

// ---------------- deformable sampling (fused softmax), half2 loads ----------------
__global__ __launch_bounds__(256) void msda_sample(
    const __half* __restrict__ vproj, const float* __restrict__ oa,
    __half* __restrict__ msh)
{
    int bq = blockIdx.x;
    int b = bq >> 11;
    int hw = bq & 1023;
    float refx = ((hw & 31) + 0.5f) * (1.f/32.f);
    float refy = ((hw >> 5) + 0.5f) * (1.f/32.f);
    __shared__ float sx[64], sy[64], sw[64];
    int t = threadIdx.x;   // 256
    const float* row = oa + (size_t)bq * 256;
    if (t < 64) {
        sx[t] = (refx + row[t*2]   * (1.f/32.f)) * 32.f - 0.5f;
        sy[t] = (refy + row[t*2+1] * (1.f/32.f)) * 32.f - 0.5f;
        float lg = row[128 + t];
        float m = lg;
        #pragma unroll
        for (int o = 1; o < 8; o <<= 1) m = fmaxf(m, __shfl_xor_sync(0xffffffffu, m, o));
        float ex = expf(lg - m);
        float s = ex;
        #pragma unroll
        for (int o = 1; o < 8; o <<= 1) s += __shfl_xor_sync(0xffffffffu, s, o);
        sw[t] = ex / s;
    }
    __syncthreads();
    int head = t >> 5, c2 = t & 31;       // 8 heads x 32 half2-channels
    const __half2* vb = (const __half2*)(vproj + (size_t)b * LQQ * DD) + head * 32 + c2;
    float accx = 0.f, accy = 0.f;
    #pragma unroll
    for (int lp = 0; lp < 8; lp++) {
        int l = lp >> 2;
        float xs = sx[head*8+lp], ys = sy[head*8+lp], w = sw[head*8+lp];
        float x0f = floorf(xs), y0f = floorf(ys);
        float fx = xs - x0f, fy = ys - y0f;
        int x0 = (int)x0f, y0 = (int)y0f;
        const __half2* vl = vb + (size_t)l * HWW * 256;
        bool xa = (unsigned)x0 < 32u, xb = (unsigned)(x0+1) < 32u;
        bool ya = (unsigned)y0 < 32u, yb = (unsigned)(y0+1) < 32u;
        float2 z2 = make_float2(0.f, 0.f);
        float2 v00 = (ya && xa) ? __half22float2(vl[(size_t)(y0*32 + x0)      * 256]) : z2;
        float2 v01 = (ya && xb) ? __half22float2(vl[(size_t)(y0*32 + x0 + 1)  * 256]) : z2;
        float2 v10 = (yb && xa) ? __half22float2(vl[(size_t)(y0*32 + x0 + 32) * 256]) : z2;
        float2 v11 = (yb && xb) ? __half22float2(vl[(size_t)(y0*32 + x0 + 33) * 256]) : z2;
        float w00 = (1.f-fy)*(1.f-fx), w01 = (1.f-fy)*fx, w10 = fy*(1.f-fx), w11 = fy*fx;
        accx = fmaf(w, v00.x*w00 + v01.x*w01 + v10.x*w10 + v11.x*w11, accx);
        accy = fmaf(w, v00.y*w00 + v01.y*w01 + v10.y*w10 + v11.y*w11, accy);
    }
    ((__half2*)msh)[(size_t)bq * 256 + head * 32 + c2] = __floats2half2_rn(accx, accy);
}

// ---------------- residual + LN: src recomputed from fp16 pre + stats ----------------
__global__ void ln_res(const __half* __restrict__ pre, const float* __restrict__ stats,
                       const float* __restrict__ gv, const float* __restrict__ bev,
                       const float* __restrict__ gi, const float* __restrict__ bei,
                       const __half* __restrict__ att,
                       const float* __restrict__ g, const float* __restrict__ be,
                       __half* __restrict__ cath)
{
    int grow = blockIdx.x;            // b*2048 + lvl*1024 + hw
    size_t base = (size_t)grow * DD;
    int t = threadIdx.x;              // 256
    int bee = grow >> 10, lvl = bee & 1;
    const float* gam = lvl ? gi : gv;
    const float* bet = lvl ? bei : bev;
    float mean0 = stats[(bee * 32 + (t >> 4)) * 2];
    float rstd0 = stats[(bee * 32 + (t >> 4)) * 2 + 1];
    int t2 = t + 256;
    float mean1 = stats[(bee * 32 + (t2 >> 4)) * 2];
    float rstd1 = stats[(bee * 32 + (t2 >> 4)) * 2 + 1];
    float s0 = (__half2float(pre[base + t])  - mean0) * rstd0 * gam[t]  + bet[t];
    float s1 = (__half2float(pre[base + t2]) - mean1) * rstd1 * gam[t2] + bet[t2];
    float v0 = s0 + __half2float(att[base + t]);
    float v1 = s1 + __half2float(att[base + t2]);
    float s = v0 + v1, sq = v0*v0 + v1*v1;
    __shared__ float red[16];
    for (int o = 16; o > 0; o >>= 1) {
        s  += __shfl_down_sync(0xffffffffu, s,  o);
        sq += __shfl_down_sync(0xffffffffu, sq, o);
    }
    if ((t & 31) == 0) { red[t >> 5] = s; red[8 + (t >> 5)] = sq; }
    __syncthreads();
    if (t < 32) {
        s  = (t < 8) ? red[t]     : 0.f;
        sq = (t < 8) ? red[8 + t] : 0.f;
        for (int o = 4; o > 0; o >>= 1) {
            s  += __shfl_down_sync(0xffffffffu, s,  o);
            sq += __shfl_down_sync(0xffffffffu, sq, o);
        }
        if (t == 0) { red[0] = s; red[8] = sq; }
    }
    __syncthreads();
    float mu   = red[0] * (1.f/512.f);
    float var  = red[8] * (1.f/512.f) - mu * mu;
    float rstd = rsqrtf(var + 1e-5f);
    int b = grow >> 11, hw = grow & 1023;
    size_t obase = ((size_t)b * 1024 + hw) * 1024 + lvl * 512;
    cath[obase + t]       = __float2half_rn((v0 - mu) * rstd * g[t]  + be[t]);
    cath[obase + t + 256] = __float2half_rn((v1 - mu) * rstd * g[t2] + be[t2]);
}

// ---------------- GN stats: contiguous fp16 groups (conv2 output) ----------------
__global__ void gn_stats_h(const __half* __restrict__ x, float* __restrict__ stats, int groupElems)
{
    int idx = blockIdx.y * gridDim.x + blockIdx.x;
    const __half* p = x + (size_t)idx * groupElems;
    float s = 0.f, sq = 0.f;
    for (int i = threadIdx.x * 8; i < groupElems; i += blockDim.x * 8) {
        uint4 raw = *(const uint4*)(p + i);
        float2 a = __half22float2(*(__half2*)&raw.x);
        float2 b = __half22float2(*(__half2*)&raw.y);
        float2 c = __half22float2(*(__half2*)&raw.z);
        float2 d = __half22float2(*(__half2*)&raw.w);
        s  += a.x + a.y + b.x + b.y + c.x + c.y + d.x + d.y;
        sq += a.x*a.x + a.y*a.y + b.x*b.x + b.y*b.y + c.x*c.x + c.y*c.y + d.x*d.x + d.y*d.y;
    }
    __shared__ float red[16];
    int t = threadIdx.x;
    for (int o = 16; o > 0; o >>= 1) {
        s  += __shfl_down_sync(0xffffffffu, s,  o);
        sq += __shfl_down_sync(0xffffffffu, sq, o);
    }
    if ((t & 31) == 0) { red[t >> 5] = s; red[8 + (t >> 5)] = sq; }
    __syncthreads();
    if (t < 32) {
        s  = (t < 8) ? red[t]     : 0.f;
        sq = (t < 8) ? red[8 + t] : 0.f;
        for (int o = 4; o > 0; o >>= 1) {
            s  += __shfl_down_sync(0xffffffffu, s,  o);
            sq += __shfl_down_sync(0xffffffffu, sq, o);
        }
        if (t == 0) {
            float inv = 1.f / (float)groupElems;
            float mean = s * inv;
            stats[idx*2]   = mean;
            stats[idx*2+1] = rsqrtf(sq * inv - mean * mean + 1e-5f);
        }
    }
}

__global__ void gn2_finish(const __half* __restrict__ x, const float* __restrict__ stats,
    const float* __restrict__ gc, const float* __restrict__ bec, float* __restrict__ out)
{
    size_t i2 = ((size_t)blockIdx.x * blockDim.x + threadIdx.x) * 2;
    int hwch = (int)(i2 >> 10);
    int ch = hwch % 768;
    int b  = hwch / 768;
    int g  = ch / 24;
    float mean = stats[(b*32 + g) * 2];
    float rstd = stats[(b*32 + g) * 2 + 1];
    float2 v = __half22float2(*(const __half2*)(x + i2));
    float gg = gc[ch], bb = bec[ch];
    *(float2*)(out + i2) = make_float2((v.x - mean) * rstd * gg + bb,
                                       (v.y - mean) * rstd * gg + bb);
}

// ---------------- launcher ----------------
#define SYM(T, v, s) T v; cudaGetSymbolAddress((void**)&v, s)
extern "C" void kernel_launch(void* const* d_in, const int* in_sizes, int n_in,
                              void* d_out, int out_size)
{
    const float* input_v = (const float*)d_in[0];
    const float* input_i = (const float*)d_in[1];
    const float* wv      = (const float*)d_in[2];
    const float* bv      = (const float*)d_in[3];
    const float* gv      = (const float*)d_in[4];
    const float* bev     = (const float*)d_in[5];
    const float* wi      = (const float*)d_in[6];
    const float* bi      = (const float*)d_in[7];
    const float* gi      = (const float*)d_in[8];
    const float* bei     = (const float*)d_in[9];
    const float* le      = (const float*)d_in[10];
    const float* w_off   = (const float*)d_in[11];
    const float* b_off   = (const float*)d_in[12];
    const float* w_attn  = (const float*)d_in[13];
    const float* b_attn  = (const float*)d_in[14];
    const float* w_val   = (const float*)d_in[15];
    const float* b_val   = (const float*)d_in[16];
    const float* w_out   = (const float*)d_in[17];
    const float* b_out   = (const float*)d_in[18];
    const float* ln_g    = (const float*)d_in[19];
    const float* ln_b    = (const float*)d_in[20];
    const float* wc      = (const float*)d_in[21];
    const float* bc      = (const float*)d_in[22];
    const float* gc      = (const float*)d_in[23];
    const float* bec     = (const float*)d_in[24];

    SYM(__half*, xth,  g_xth);
    SYM(__half*, w1h,  g_w1h);  SYM(__half*, wvoa, g_wvoa);
    SYM(__half*, wouth,g_wouth);
    SYM(__half*, wch,  g_wch_);
    SYM(__half*, preh, g_preh);
    SYM(__half*, srch, g_srch);
    SYM(__half*, msh,  g_msh);
    SYM(__half*, cath, g_cath); SYM(__half*, vph,  g_vph);
    SYM(__half*, attno, g_attnoh);
    SYM(__half*, conv2h, g_conv2h);
    SYM(float*, oa,    g_oa4);
    SYM(float*, lep,   g_lep);    SYM(float*, b1,    g_b1);
    SYM(float*, st1,   g_stats1); SYM(float*, st2,   g_stats2);
    size_t XT = (size_t)8192*768;

    cudaFuncSetAttribute(gemm_tc, cudaFuncAttributeMaxDynamicSharedMemorySize, GEMM_SMEM);

    // prep
    prep_weights<<<8708, 256>>>(wv, wi, w_val, w_out, w_off, w_attn, wc,
                                bv, bi, w1h, wvoa, wouth, wch, b1);
    leproj_k<<<2, 256>>>(le, w_off, w_attn, b_off, b_attn, lep);
    prep_input2<<<dim3(32, 24, 16), dim3(32, 8)>>>(input_v, input_i, xth);

    // conv1 (v+i, z planes): fp16 D -> rows (b, lvl, hw)
    gemm_tc<<<dim3(4, 64, 2), 256, GEMM_SMEM>>>(xth, w1h, b1, preh,
        768, 2, 2048, 0, 512, (long)XT, 393216L, 512, 1024, 0, nullptr, nullptr);
    // GN1
    gn_stats_seq<<<dim3(32, 16), 256>>>(preh, st1);
    gn1_finish2<<<4096, 256>>>(preh, st1, gv, bev, gi, bei, srch);
    // fused vproj+oa projection [dual output]
    gemm_tc<<<dim3(6, 128), 256, GEMM_SMEM>>>(srch, wvoa, b_val, vph,
        512, 3, 1024, 0, 512, 0L, 0L, 0, 0, 0, oa, lep);
    // sampling (softmax fused)
    msda_sample<<<MROWS, 256>>>(vph, oa, msh);
    // output projection [fp16 out]
    gemm_tc<<<dim3(4, 128), 256, GEMM_SMEM>>>(msh, wouth, b_out, attno,
        512, 2, 1024, 0, 512, 0L, 0L, 0, 0, 0, nullptr, nullptr);
    // residual + LN (src recomputed from preh) -> cat fp16
    ln_res<<<MROWS, 256>>>(preh, st1, gv, bev, gi, bei, attno, ln_g, ln_b, cath);
    // conv2: fp16 D -> (b, o, hw)
    gemm_tc<<<dim3(64, 6), 256, GEMM_SMEM>>>(wch, cath, bc, conv2h,
        1024, 4, 0, 0, 768, 0L, 0L, 0, 0, 0, nullptr, nullptr);
    // final GN
    gn_stats_h<<<dim3(32, BB), 256>>>(conv2h, st2, 24 * HWW);
    gn2_finish<<<12288, 256>>>(conv2h, st2, gc, bec, (float*)d_out);
}